// round 12
// baseline (speedup 1.0000x reference)
#include <cuda_runtime.h>
#include <cuda_fp16.h>
#include <math.h>
#include <stdint.h>

// Model constants
#define BH      8
#define HDIM    64
#define DMODEL  512
#define SENC    2048
#define SRTR    72
#define NTOK_ENC 4096
#define NTOK_RTR 4608
#define FFH     1024

// ---- fp32 scratch (float offsets) ----
#define OFF_QKV   0ull
#define OFF_H     14155776ull
#define OFF_X     23592960ull
#define OFF_XR    25952256ull
#define OFF_OUT   28311552ull
#define OFF_KNR   28442624ull
#define OFF_KNG   28443136ull
#define OFF_RL    28443648ull
#define OFF_GL    28476416ull
#define SCRATCH_FLOATS 28509184ull
__device__ float g_s[SCRATCH_FLOATS];

// ---- fp16 scratch (half offsets) ----
#define HO_XNH   0ull
#define HO_XNL   2359296ull
#define HO_ATTH  4718592ull
#define HO_ATTL  7077888ull
#define HO_ACTH  9437184ull
#define HO_ACTL  14155776ull
#define HO_ROWSH 18874368ull
#define HO_ROWSL 19136512ull
#define HO_WH    19398656ull
#define HO_WL    35258368ull
#define HO_QH    51118080ull
#define HO_QL    53477376ull
#define HO_KH    55836672ull
#define HO_KL    58195968ull
#define HO_VH    60555264ull
#define HO_VL    62914560ull
#define HO_VTH   65273856ull
#define HO_VTL   67633152ull
#define SCRATCH_HALVES 69992448ull
__device__ __half g_h[SCRATCH_HALVES];

// weight-plane sub-offsets (halves)
#define WO_EQ   0ull
#define WO_EO   3145728ull
#define WO_EU   4194304ull
#define WO_ED   8388608ull
#define WO_RQ   10485760ull
#define WO_RO   12058624ull
#define WO_RU   12582912ull
#define WO_RD   14680064ull
#define WO_OUT  15728640ull

#define NSM_SLOTS 148

// ---------------- helpers ----------------
__device__ __forceinline__ float bsum128(float v, volatile float* red) {
    int tid = threadIdx.x;
    red[tid] = v;
    for (int off = 64; off >= 1; off >>= 1) {
        __syncthreads();
        if (tid < off) red[tid] += red[tid + off];
    }
    __syncthreads();
    float r = red[0];
    __syncthreads();
    return r;
}

__device__ __forceinline__ float bmax128(float v, volatile float* red) {
    int tid = threadIdx.x;
    red[tid] = v;
    for (int off = 64; off >= 1; off >>= 1) {
        __syncthreads();
        if (tid < off) red[tid] = fmaxf(red[tid], red[tid + off]);
    }
    __syncthreads();
    float r = red[0];
    __syncthreads();
    return r;
}

__device__ __forceinline__ void split_h(float v, __half& hi, __half& lo) {
    hi = __float2half_rn(v);
    lo = __float2half_rn(v - __half2float(hi));
}

__device__ __forceinline__ void mma16816(float* c, const uint32_t* a, const uint32_t* b) {
    asm volatile(
        "mma.sync.aligned.m16n8k16.row.col.f32.f16.f16.f32 "
        "{%0,%1,%2,%3}, {%4,%5,%6,%7}, {%8,%9}, {%0,%1,%2,%3};"
        : "+f"(c[0]), "+f"(c[1]), "+f"(c[2]), "+f"(c[3])
        : "r"(a[0]), "r"(a[1]), "r"(a[2]), "r"(a[3]), "r"(b[0]), "r"(b[1]));
}

// f16-accumulator variant (cross terms; values ~2^-11 of main term)
__device__ __forceinline__ void mma16816h(uint32_t* c, const uint32_t* a, const uint32_t* b) {
    asm volatile(
        "mma.sync.aligned.m16n8k16.row.col.f16.f16.f16.f16 "
        "{%0,%1}, {%2,%3,%4,%5}, {%6,%7}, {%0,%1};"
        : "+r"(c[0]), "+r"(c[1])
        : "r"(a[0]), "r"(a[1]), "r"(a[2]), "r"(a[3]), "r"(b[0]), "r"(b[1]));
}

__device__ __forceinline__ uint32_t sptr(const void* p) {
    return (uint32_t)__cvta_generic_to_shared(p);
}

__device__ __forceinline__ void ldsm4(uint32_t& r0, uint32_t& r1, uint32_t& r2,
                                      uint32_t& r3, uint32_t addr) {
    asm volatile("ldmatrix.sync.aligned.m8n8.x4.shared.b16 {%0,%1,%2,%3}, [%4];"
                 : "=r"(r0), "=r"(r1), "=r"(r2), "=r"(r3) : "r"(addr));
}

__device__ __forceinline__ void cpa16(uint32_t dst, const void* src) {
    asm volatile("cp.async.cg.shared.global [%0], [%1], 16;" :: "r"(dst), "l"(src));
}
__device__ __forceinline__ void cpa_commit() { asm volatile("cp.async.commit_group;"); }
__device__ __forceinline__ void cpa_wait0() { asm volatile("cp.async.wait_group 0;"); }

__device__ __forceinline__ uint32_t h2u(__half2 h) { return *(uint32_t*)&h; }

// ---------------- kernels ----------------
__global__ void copy_k(const float* __restrict__ src, float* __restrict__ dst, int n) {
    int i = blockIdx.x * blockDim.x + threadIdx.x;
    if (i < n) dst[i] = src[i];
}

// transpose + split weights; gridDim.z = layer index
__global__ void wsplitT_k(const float* __restrict__ w, __half* __restrict__ hT,
                          __half* __restrict__ lT, int K, int N, int ilv) {
    __shared__ float t[32][33];
    size_t loff = (size_t)blockIdx.z * K * N;
    w += loff; hT += loff; lT += loff;
    int n0 = blockIdx.x * 32, k0 = blockIdx.y * 32;
    int tx = threadIdx.x, ty = threadIdx.y;
    for (int i = ty; i < 32; i += 8) {
        int n = n0 + tx;
        int srcn = ilv ? ((n & 1) ? (N >> 1) + (n >> 1) : (n >> 1)) : n;
        t[i][tx] = w[(size_t)(k0 + i) * N + srcn];
    }
    __syncthreads();
    for (int i = ty; i < 32; i += 8) {
        float v = t[tx][i];
        __half h, l;
        split_h(v, h, l);
        hT[(size_t)(n0 + i) * K + k0 + tx] = h;
        lT[(size_t)(n0 + i) * K + k0 + tx] = l;
    }
}

__global__ void rmsnorm_k(const float* __restrict__ x, const float* __restrict__ w,
                          __half* __restrict__ yh, __half* __restrict__ yl) {
    __shared__ float red[128];
    size_t row = (size_t)blockIdx.x * DMODEL;
    int tid = threadIdx.x;
    float ss = 0.f;
    for (int i = tid; i < DMODEL; i += 128) {
        float v = x[row + i];
        ss += v * v;
    }
    float tot = bsum128(ss, red);
    float scale = rsqrtf(tot / (float)DMODEL + 1e-6f);
    for (int i = tid; i < DMODEL; i += 128) {
        __half h, l;
        split_h(x[row + i] * scale * w[i], h, l);
        yh[row + i] = h;
        yl[row + i] = l;
    }
}

// ---- 3xFP16 split GEMM: main term f32-accum, cross terms f16-accum ----
// mode 0: C = A@B ; mode 1: C += A@B ; mode 2: silu-gate epilogue to Dh/Dl.
__global__ __launch_bounds__(256) void sgemm_h3(const __half* __restrict__ Ah,
                                                const __half* __restrict__ Al,
                                                const __half* __restrict__ BTh,
                                                const __half* __restrict__ BTl,
                                                float* __restrict__ C,
                                                __half* __restrict__ Dh,
                                                __half* __restrict__ Dl,
                                                int M, int N, int K, int mode) {
    __shared__ __align__(16) __half As[2][2][128][24];
    __shared__ __align__(16) __half Bs[2][2][128][24];
    int tid = threadIdx.x;
    int lane = tid & 31, warp = tid >> 5;
    int wm = warp >> 2, wn = warp & 3;
    int grp = lane >> 2, qid = lane & 3;
    int lrow = tid >> 1, lseg = (tid & 1) * 8;
    int arow = lane & 15, acg = (lane >> 4) * 8;
    int nk = K >> 4;
    int ntN = N >> 7;
    int ntiles = (M >> 7) * ntN;

#define LOADA(buf, k0)                                                              \
    {                                                                               \
        cpa16(sptr(&As[buf][0][lrow][lseg]), Ah + (size_t)(bm + lrow) * K + (k0) + lseg); \
        cpa16(sptr(&As[buf][1][lrow][lseg]), Al + (size_t)(bm + lrow) * K + (k0) + lseg); \
        cpa16(sptr(&Bs[buf][0][lrow][lseg]), BTh + (size_t)(bn + lrow) * K + (k0) + lseg); \
        cpa16(sptr(&Bs[buf][1][lrow][lseg]), BTl + (size_t)(bn + lrow) * K + (k0) + lseg); \
        cpa_commit();                                                               \
    }

    for (int t = blockIdx.x; t < ntiles; t += gridDim.x) {
        int bm = (t / ntN) << 7;
        int bn = (t % ntN) << 7;

        float acc[4][4][4];
        uint32_t hacc[4][4][2];
#pragma unroll
        for (int i = 0; i < 4; i++)
#pragma unroll
            for (int j = 0; j < 4; j++) {
#pragma unroll
                for (int u = 0; u < 4; u++) acc[i][j][u] = 0.f;
                hacc[i][j][0] = 0u;
                hacc[i][j][1] = 0u;
            }

        LOADA(0, 0);

        for (int kt = 0; kt < nk; kt++) {
            int buf = kt & 1;
            cpa_wait0();
            __syncthreads();
            if (kt + 1 < nk) LOADA(buf ^ 1, (kt + 1) << 4);

            uint32_t ah[4][4], al[4][4], bh[4][2], bl[4][2];
#pragma unroll
            for (int mt = 0; mt < 4; mt++) {
                int r = wm * 64 + mt * 16 + arow;
                ldsm4(ah[mt][0], ah[mt][1], ah[mt][2], ah[mt][3], sptr(&As[buf][0][r][acg]));
                ldsm4(al[mt][0], al[mt][1], al[mt][2], al[mt][3], sptr(&As[buf][1][r][acg]));
            }
#pragma unroll
            for (int ntp = 0; ntp < 2; ntp++) {
                int r = wn * 32 + ntp * 16 + arow;
                uint32_t m0, m1, m2, m3;
                ldsm4(m0, m1, m2, m3, sptr(&Bs[buf][0][r][acg]));
                bh[2 * ntp][0] = m0; bh[2 * ntp][1] = m2;
                bh[2 * ntp + 1][0] = m1; bh[2 * ntp + 1][1] = m3;
                ldsm4(m0, m1, m2, m3, sptr(&Bs[buf][1][r][acg]));
                bl[2 * ntp][0] = m0; bl[2 * ntp][1] = m2;
                bl[2 * ntp + 1][0] = m1; bl[2 * ntp + 1][1] = m3;
            }
#pragma unroll
            for (int mt = 0; mt < 4; mt++)
#pragma unroll
                for (int nt = 0; nt < 4; nt++) {
                    mma16816h(hacc[mt][nt], al[mt], bh[nt]);
                    mma16816h(hacc[mt][nt], ah[mt], bl[nt]);
                    mma16816(acc[mt][nt], ah[mt], bh[nt]);
                }
            __syncthreads();
        }

        // fold f16 cross accumulators into fp32
#pragma unroll
        for (int mt = 0; mt < 4; mt++)
#pragma unroll
            for (int nt = 0; nt < 4; nt++) {
                __half2 h0 = *(__half2*)&hacc[mt][nt][0];
                __half2 h1 = *(__half2*)&hacc[mt][nt][1];
                acc[mt][nt][0] += __low2float(h0);
                acc[mt][nt][1] += __high2float(h0);
                acc[mt][nt][2] += __low2float(h1);
                acc[mt][nt][3] += __high2float(h1);
            }

        if (mode == 2) {
            int half_n = N >> 1;
#pragma unroll
            for (int mt = 0; mt < 4; mt++)
#pragma unroll
                for (int nt = 0; nt < 4; nt++) {
                    int r0 = bm + wm * 64 + mt * 16 + grp;
                    int j = (bn + wn * 32 + nt * 8 + 2 * qid) >> 1;
                    float a0 = acc[mt][nt][0], b0 = acc[mt][nt][1];
                    float a1 = acc[mt][nt][2], b1 = acc[mt][nt][3];
                    float g0 = (a0 / (1.0f + __expf(-a0))) * b0;
                    float g1 = (a1 / (1.0f + __expf(-a1))) * b1;
                    __half h, l;
                    split_h(g0, h, l);
                    Dh[(size_t)r0 * half_n + j] = h;
                    Dl[(size_t)r0 * half_n + j] = l;
                    split_h(g1, h, l);
                    Dh[(size_t)(r0 + 8) * half_n + j] = h;
                    Dl[(size_t)(r0 + 8) * half_n + j] = l;
                }
        } else {
#pragma unroll
            for (int mt = 0; mt < 4; mt++)
#pragma unroll
                for (int nt = 0; nt < 4; nt++) {
                    int r0 = bm + wm * 64 + mt * 16 + grp;
                    int c0 = bn + wn * 32 + nt * 8 + 2 * qid;
                    size_t i00 = (size_t)r0 * N + c0;
                    size_t i10 = (size_t)(r0 + 8) * N + c0;
                    if (mode == 1) {
                        C[i00]     += acc[mt][nt][0];
                        C[i00 + 1] += acc[mt][nt][1];
                        C[i10]     += acc[mt][nt][2];
                        C[i10 + 1] += acc[mt][nt][3];
                    } else {
                        C[i00]     = acc[mt][nt][0];
                        C[i00 + 1] = acc[mt][nt][1];
                        C[i10]     = acc[mt][nt][2];
                        C[i10 + 1] = acc[mt][nt][3];
                    }
                }
        }
    }
#undef LOADA
}

// qkv row -> q/k (RoPE) and v, hi/lo half planes [bh][SEQ][64]
__global__ void split_rope_k(const float* __restrict__ qkv,
                             __half* __restrict__ Qh, __half* __restrict__ Ql,
                             __half* __restrict__ Kh, __half* __restrict__ Kl,
                             __half* __restrict__ Vh, __half* __restrict__ Vl,
                             int SEQ) {
    int tok = blockIdx.x;
    int b = tok / SEQ, s = tok % SEQ;
    const float* row = qkv + (size_t)tok * 1536;
    int tid = threadIdx.x;
    int h = tid >> 5, i = tid & 31;
    float q1 = row[h * 64 + i], q2 = row[h * 64 + i + 32];
    float k1 = row[512 + h * 64 + i], k2 = row[512 + h * 64 + i + 32];
    float inv = powf(1e-4f, (float)i * (1.0f / 32.0f));
    float ang = (float)s * inv;
    float c = cosf(ang), sn = sinf(ang);
    size_t base = ((size_t)(b * BH + h) * SEQ + s) * 64;
    __half hh, ll;
    split_h(q1 * c + q2 * sn, hh, ll);      Qh[base + i] = hh;      Ql[base + i] = ll;
    split_h(-q1 * sn + q2 * c, hh, ll);     Qh[base + i + 32] = hh; Ql[base + i + 32] = ll;
    split_h(k1 * c + k2 * sn, hh, ll);      Kh[base + i] = hh;      Kl[base + i] = ll;
    split_h(-k1 * sn + k2 * c, hh, ll);     Kh[base + i + 32] = hh; Kl[base + i + 32] = ll;
    for (int j = tid; j < 512; j += 256) {
        int hd = j >> 6, dd = j & 63;
        split_h(row[1024 + j], hh, ll);
        size_t vi = ((size_t)(b * BH + hd) * SEQ + s) * 64 + dd;
        Vh[vi] = hh;
        Vl[vi] = ll;
    }
}

// V [bh][s][64] -> Vt [bh][64][s]
__global__ void vtrans_k(const __half* __restrict__ Vh, const __half* __restrict__ Vl,
                         __half* __restrict__ Vth, __half* __restrict__ Vtl, int SEQ) {
    __shared__ __half t[2][64][72];
    int sc = blockIdx.x * 64;
    int bh = blockIdx.y;
    int tid = threadIdx.x;
    for (int i = tid; i < 512; i += 256) {
        int r = i >> 3, c = (i & 7) * 8;
        *(uint4*)&t[0][r][c] = *(const uint4*)(Vh + ((size_t)bh * SEQ + sc + r) * 64 + c);
        *(uint4*)&t[1][r][c] = *(const uint4*)(Vl + ((size_t)bh * SEQ + sc + r) * 64 + c);
    }
    __syncthreads();
    for (int i = tid; i < 4096; i += 256) {
        int d = i >> 6, s = i & 63;
        Vth[((size_t)bh * 64 + d) * SEQ + sc + s] = t[0][s][d];
        Vtl[((size_t)bh * 64 + d) * SEQ + sc + s] = t[1][s][d];
    }
}

// ---- tensor-core flash attention, 3xFP16 split (encoder path) ----
#define ATS 72
#define AMMA_SMEM (6 * 64 * ATS * 2 + 256)
__global__ __launch_bounds__(128) void attn_mma_k(
        const __half* __restrict__ Qh, const __half* __restrict__ Ql,
        const __half* __restrict__ Kh, const __half* __restrict__ Kl,
        const __half* __restrict__ Vth, const __half* __restrict__ Vtl,
        __half* __restrict__ Oh, __half* __restrict__ Ol,
        const int* __restrict__ doc, int SEQ) {
    extern __shared__ __half hsm[];
    __half* Qsh = hsm;
    __half* Qsl = hsm + 64 * ATS;
    __half* Ksh = hsm + 2 * 64 * ATS;
    __half* Ksl = hsm + 3 * 64 * ATS;
    __half* Vsh = hsm + 4 * 64 * ATS;
    __half* Vsl = hsm + 5 * 64 * ATS;
    int* sdoc = (int*)(hsm + 6 * 64 * ATS);

    int qb = blockIdx.x, bh = blockIdx.y;
    int b = bh >> 3, h = bh & 7;
    int tid = threadIdx.x, lane = tid & 31, warp = tid >> 5;
    int grp = lane >> 2, qid = lane & 3;
    int arow = lane & 15, acg = (lane >> 4) * 8;

    const __half* Qbh = Qh + ((size_t)bh * SEQ + qb * 64) * 64;
    const __half* Qbl = Ql + ((size_t)bh * SEQ + qb * 64) * 64;
    for (int i = tid; i < 512; i += 128) {
        int r = i >> 3, c = (i & 7) * 8;
        *(uint4*)(Qsh + r * ATS + c) = *(const uint4*)(Qbh + r * 64 + c);
        *(uint4*)(Qsl + r * ATS + c) = *(const uint4*)(Qbl + r * 64 + c);
    }
    __syncthreads();

    uint32_t qfh[4][4], qfl[4][4];
#pragma unroll
    for (int ds = 0; ds < 4; ds++) {
        ldsm4(qfh[ds][0], qfh[ds][1], qfh[ds][2], qfh[ds][3],
              sptr(Qsh + (warp * 16 + arow) * ATS + ds * 16 + acg));
        ldsm4(qfl[ds][0], qfl[ds][1], qfl[ds][2], qfl[ds][3],
              sptr(Qsl + (warp * 16 + arow) * ATS + ds * 16 + acg));
    }
    int dq0 = doc[b * SEQ + qb * 64 + warp * 16 + grp];
    int dq1 = doc[b * SEQ + qb * 64 + warp * 16 + grp + 8];

    float o[8][4];
#pragma unroll
    for (int j = 0; j < 8; j++)
#pragma unroll
        for (int t = 0; t < 4; t++) o[j][t] = 0.f;
    float m0r = -1e30f, m1r = -1e30f, l0 = 0.f, l1 = 0.f;

    const __half* Kbh = Kh + (size_t)bh * SEQ * 64;
    const __half* Kbl = Kl + (size_t)bh * SEQ * 64;
    const __half* Vbh = Vth + (size_t)bh * 64 * SEQ;
    const __half* Vbl = Vtl + (size_t)bh * 64 * SEQ;

    for (int kt = 0; kt <= qb; kt++) {
        int kbase = kt * 64;
        __syncthreads();
        for (int i = tid; i < 512; i += 128) {
            int r = i >> 3, c = (i & 7) * 8;
            *(uint4*)(Ksh + r * ATS + c) = *(const uint4*)(Kbh + (size_t)(kbase + r) * 64 + c);
            *(uint4*)(Ksl + r * ATS + c) = *(const uint4*)(Kbl + (size_t)(kbase + r) * 64 + c);
            *(uint4*)(Vsh + r * ATS + c) = *(const uint4*)(Vbh + (size_t)r * SEQ + kbase + c);
            *(uint4*)(Vsl + r * ATS + c) = *(const uint4*)(Vbl + (size_t)r * SEQ + kbase + c);
        }
        if (tid < 64) sdoc[tid] = doc[b * SEQ + kbase + tid];
        __syncthreads();

        float sc[8][4];
#pragma unroll
        for (int j = 0; j < 8; j++)
#pragma unroll
            for (int t = 0; t < 4; t++) sc[j][t] = 0.f;
#pragma unroll
        for (int ds = 0; ds < 4; ds++) {
            uint32_t kfh[8][2], kfl[8][2];
#pragma unroll
            for (int np = 0; np < 4; np++) {
                uint32_t m0, m1, m2, m3;
                ldsm4(m0, m1, m2, m3, sptr(Ksh + (np * 16 + arow) * ATS + ds * 16 + acg));
                kfh[2 * np][0] = m0; kfh[2 * np][1] = m2;
                kfh[2 * np + 1][0] = m1; kfh[2 * np + 1][1] = m3;
                ldsm4(m0, m1, m2, m3, sptr(Ksl + (np * 16 + arow) * ATS + ds * 16 + acg));
                kfl[2 * np][0] = m0; kfl[2 * np][1] = m2;
                kfl[2 * np + 1][0] = m1; kfl[2 * np + 1][1] = m3;
            }
#pragma unroll
            for (int j = 0; j < 8; j++) {
                mma16816(sc[j], qfl[ds], kfh[j]);
                mma16816(sc[j], qfh[ds], kfl[j]);
                mma16816(sc[j], qfh[ds], kfh[j]);
            }
        }

#pragma unroll
        for (int j = 0; j < 8; j++) {
            int dk0 = sdoc[8 * j + 2 * qid], dk1 = sdoc[8 * j + 2 * qid + 1];
            sc[j][0] = (dk0 == dq0) ? sc[j][0] * 0.125f : -6e30f;
            sc[j][1] = (dk1 == dq0) ? sc[j][1] * 0.125f : -6e30f;
            sc[j][2] = (dk0 == dq1) ? sc[j][2] * 0.125f : -6e30f;
            sc[j][3] = (dk1 == dq1) ? sc[j][3] * 0.125f : -6e30f;
        }

        float tm0 = -1e30f, tm1 = -1e30f;
#pragma unroll
        for (int j = 0; j < 8; j++) {
            tm0 = fmaxf(tm0, fmaxf(sc[j][0], sc[j][1]));
            tm1 = fmaxf(tm1, fmaxf(sc[j][2], sc[j][3]));
        }
#pragma unroll
        for (int off = 1; off < 4; off <<= 1) {
            tm0 = fmaxf(tm0, __shfl_xor_sync(0xffffffffu, tm0, off));
            tm1 = fmaxf(tm1, __shfl_xor_sync(0xffffffffu, tm1, off));
        }
        float mn0 = fmaxf(m0r, tm0), mn1 = fmaxf(m1r, tm1);
        float r0 = __expf(m0r - mn0), r1 = __expf(m1r - mn1);

        uint32_t pfh[8][2], pfl[8][2];
        float ps0 = 0.f, ps1 = 0.f;
#pragma unroll
        for (int j = 0; j < 8; j++) {
            float p0 = __expf(sc[j][0] - mn0), p1 = __expf(sc[j][1] - mn0);
            float p2 = __expf(sc[j][2] - mn1), p3 = __expf(sc[j][3] - mn1);
            ps0 += p0 + p1; ps1 += p2 + p3;
            __half2 hA = __floats2half2_rn(p0, p1);
            __half2 hB = __floats2half2_rn(p2, p3);
            pfh[j][0] = h2u(hA);
            pfh[j][1] = h2u(hB);
            __half2 lA = __floats2half2_rn(p0 - __half2float(__low2half(hA)),
                                           p1 - __half2float(__high2half(hA)));
            __half2 lB = __floats2half2_rn(p2 - __half2float(__low2half(hB)),
                                           p3 - __half2float(__high2half(hB)));
            pfl[j][0] = h2u(lA);
            pfl[j][1] = h2u(lB);
        }
#pragma unroll
        for (int off = 1; off < 4; off <<= 1) {
            ps0 += __shfl_xor_sync(0xffffffffu, ps0, off);
            ps1 += __shfl_xor_sync(0xffffffffu, ps1, off);
        }
        l0 = l0 * r0 + ps0;
        l1 = l1 * r1 + ps1;
        m0r = mn0; m1r = mn1;
#pragma unroll
        for (int j = 0; j < 8; j++) {
            o[j][0] *= r0; o[j][1] *= r0; o[j][2] *= r1; o[j][3] *= r1;
        }

#pragma unroll
        for (int ks = 0; ks < 4; ks++) {
            uint32_t pah[4] = {pfh[2 * ks][0], pfh[2 * ks][1], pfh[2 * ks + 1][0], pfh[2 * ks + 1][1]};
            uint32_t pal[4] = {pfl[2 * ks][0], pfl[2 * ks][1], pfl[2 * ks + 1][0], pfl[2 * ks + 1][1]};
            uint32_t vfh[8][2], vfl[8][2];
#pragma unroll
            for (int np = 0; np < 4; np++) {
                uint32_t m0, m1, m2, m3;
                ldsm4(m0, m1, m2, m3, sptr(Vsh + (np * 16 + arow) * ATS + ks * 16 + acg));
                vfh[2 * np][0] = m0; vfh[2 * np][1] = m2;
                vfh[2 * np + 1][0] = m1; vfh[2 * np + 1][1] = m3;
                ldsm4(m0, m1, m2, m3, sptr(Vsl + (np * 16 + arow) * ATS + ks * 16 + acg));
                vfl[2 * np][0] = m0; vfl[2 * np][1] = m2;
                vfl[2 * np + 1][0] = m1; vfl[2 * np + 1][1] = m3;
            }
#pragma unroll
            for (int j = 0; j < 8; j++) {
                mma16816(o[j], pal, vfh[j]);
                mma16816(o[j], pah, vfl[j]);
                mma16816(o[j], pah, vfh[j]);
            }
        }
    }

    float inv0 = 1.0f / l0, inv1 = 1.0f / l1;
    int row0 = qb * 64 + warp * 16 + grp;
#pragma unroll
    for (int j = 0; j < 8; j++) {
        int col = h * 64 + 8 * j + 2 * qid;
        float v0 = o[j][0] * inv0, v1 = o[j][1] * inv0;
        __half2 hh = __floats2half2_rn(v0, v1);
        __half2 ll = __floats2half2_rn(v0 - __half2float(__low2half(hh)),
                                       v1 - __half2float(__high2half(hh)));
        size_t i0 = (size_t)(b * SEQ + row0) * DMODEL + col;
        *(__half2*)(Oh + i0) = hh;
        *(__half2*)(Ol + i0) = ll;
        float v2 = o[j][2] * inv1, v3 = o[j][3] * inv1;
        hh = __floats2half2_rn(v2, v3);
        ll = __floats2half2_rn(v2 - __half2float(__low2half(hh)),
                               v3 - __half2float(__high2half(hh)));
        size_t i1 = (size_t)(b * SEQ + row0 + 8) * DMODEL + col;
        *(__half2*)(Oh + i1) = hh;
        *(__half2*)(Ol + i1) = ll;
    }
}

// router attention (full attention within 72 tokens)
__global__ __launch_bounds__(128) void attn_k(
        const __half* __restrict__ Qh, const __half* __restrict__ Ql,
        const __half* __restrict__ Kh, const __half* __restrict__ Kl,
        const __half* __restrict__ Vh, const __half* __restrict__ Vl,
        __half* __restrict__ Oh, __half* __restrict__ Ol, int SEQ) {
    __shared__ float sq[64];
    __shared__ float sp[128];
    __shared__ float red[128];
    int q = blockIdx.x;
    int bh = blockIdx.y;
    int b = bh / BH, h = bh % BH;
    int tid = threadIdx.x;
    size_t qoff = ((size_t)bh * SEQ + q) * 64;
    if (tid < 64)
        sq[tid] = __half2float(Qh[qoff + tid]) + __half2float(Ql[qoff + tid]);
    __syncthreads();

    float m = -1e30f;
    for (int k = tid; k < SEQ; k += 128) {
        const __half2* krh = (const __half2*)(Kh + ((size_t)bh * SEQ + k) * 64);
        const __half2* krl = (const __half2*)(Kl + ((size_t)bh * SEQ + k) * 64);
        float a = 0.f;
#pragma unroll
        for (int i = 0; i < 32; i++) {
            float2 kh2 = __half22float2(krh[i]);
            float2 kl2 = __half22float2(krl[i]);
            a += (kh2.x + kl2.x) * sq[2 * i] + (kh2.y + kl2.y) * sq[2 * i + 1];
        }
        sp[k] = a * 0.125f;
        m = fmaxf(m, a * 0.125f);
    }
    m = bmax128(m, red);

    float l = 0.f;
    for (int k = tid; k < SEQ; k += 128) {
        float e = __expf(sp[k] - m);
        sp[k] = e;
        l += e;
    }
    l = bsum128(l, red);

    int d = tid & 63, half = tid >> 6;
    float acc = 0.f;
    for (int k = half; k < SEQ; k += 2) {
        size_t vi = ((size_t)bh * SEQ + k) * 64 + d;
        acc += sp[k] * (__half2float(Vh[vi]) + __half2float(Vl[vi]));
    }
    red[tid] = acc;
    __syncthreads();
    if (tid < 64) {
        float o = (red[tid] + red[tid + 64]) / l;
        size_t idx = (size_t)(b * SEQ + q) * DMODEL + h * 64 + tid;
        __half hh, ll;
        split_h(o, hh, ll);
        Oh[idx] = hh;
        Ol[idx] = ll;
    }
}

__global__ void build_xr_k(const float* __restrict__ x, const float* __restrict__ rt,
                           float* __restrict__ xr) {
    int i = blockIdx.x * blockDim.x + threadIdx.x;
    if (i >= NTOK_RTR * DMODEL) return;
    int blk = i / (SRTR * DMODEL);
    int rem = i % (SRTR * DMODEL);
    int t = rem / DMODEL, dd = rem % DMODEL;
    xr[i] = (t < 64) ? x[(size_t)(blk * 64 + t) * DMODEL + dd]
                     : rt[(size_t)(t - 64) * DMODEL + dd];
}

__global__ void gather_rows_k(const float* __restrict__ xr, __half* __restrict__ rh,
                              __half* __restrict__ rl) {
    int i = blockIdx.x * blockDim.x + threadIdx.x;
    if (i >= 512 * DMODEL) return;
    int row = i / DMODEL, dd = i % DMODEL;
    int blk = row >> 3, r = row & 7;
    __half h, l;
    split_h(xr[((size_t)blk * SRTR + 64 + r) * DMODEL + dd], h, l);
    rh[i] = h;
    rl[i] = l;
}

__global__ void knorm_k(const float* __restrict__ kr, const float* __restrict__ kg,
                        float* __restrict__ knr, float* __restrict__ kng) {
    int tid = threadIdx.x;
    int which = tid >> 9;
    int idx = tid & 511;
    int g = idx >> 4, e = idx & 15;
    const float* src = which ? kg : kr;
    const float* col = src + (size_t)g * 128 * 16 + e;
    float s = 0.f;
    for (int d = 0; d < 128; d++) { float v = col[d * 16]; s += v * v; }
    float n = fmaxf(sqrtf(s), 1e-12f);
    if (which) kng[idx] = n; else knr[idx] = n;
}

__global__ void logits_k(const float* __restrict__ outp,
                         const float* __restrict__ keys_r, const float* __restrict__ keys_g,
                         const float* __restrict__ knr, const float* __restrict__ kng,
                         float* __restrict__ rl, float* __restrict__ gl) {
    __shared__ float vr[128], vg[128], red[128];
    int g = blockIdx.x >> 6, bb = blockIdx.x & 63;
    int b = bb >> 5, l = bb & 31;
    int srcl = (l + 31) & 31;
    int r = g >> 2;
    const float* row = outp + (size_t)((b * 32 + srcl) * 8 + r) * 256;
    int tid = threadIdx.x;
    vr[tid] = row[tid];
    vg[tid] = row[128 + tid];
    float nr2 = bsum128(vr[tid] * vr[tid], red);
    float ng2 = bsum128(vg[tid] * vg[tid], red);
    float inr = 1.0f / fmaxf(sqrtf(nr2), 1e-12f);
    float ing = 1.0f / fmaxf(sqrtf(ng2), 1e-12f);
    if (tid < 16) {
        int e = tid;
        const float* kr = keys_r + (size_t)g * 128 * 16 + e;
        const float* kg = keys_g + (size_t)g * 128 * 16 + e;
        float dr = 0.f, dg = 0.f;
        for (int dd = 0; dd < 128; dd++) {
            dr += vr[dd] * kr[dd * 16];
            dg += vg[dd] * kg[dd * 16];
        }
        rl[(size_t)(g * 64 + bb) * 16 + e] = dr * inr / knr[g * 16 + e];
        gl[(size_t)(g * 64 + bb) * 16 + e] = dg * ing / kng[g * 16 + e];
    }
}

__global__ void topk_k(const float* __restrict__ rl, const float* __restrict__ gl,
                       float* __restrict__ out) {
    int t = blockIdx.x * blockDim.x + threadIdx.x;
    if (t >= 2048) return;
    const float* r = rl + (size_t)t * 16;
    const float* g = gl + (size_t)t * 16;
    int i1 = 0; float v1 = r[0];
    for (int e = 1; e < 16; e++) if (r[e] > v1) { v1 = r[e]; i1 = e; }
    int i2 = -1; float v2 = -1e30f;
    for (int e = 0; e < 16; e++) {
        if (e == i1) continue;
        if (r[e] > v2) { v2 = r[e]; i2 = e; }
    }
    out[(size_t)t * 2 + 0] = v1;
    out[(size_t)t * 2 + 1] = v2;
    out[4096 + (size_t)t * 2 + 0] = g[i1];
    out[4096 + (size_t)t * 2 + 1] = g[i2];
}

// ---------------- host orchestration ----------------
static inline int pgrid(int tiles) { return tiles < NSM_SLOTS ? tiles : NSM_SLOTS; }

static void run_layer_tail(float* cur, size_t oo, size_t upo, size_t dno,
                           const float* n2, int ntok, int SEQ, int enc, const int* doc,
                           float* sb, __half* hb_) {
    float*  qkv  = sb + OFF_QKV;
    float*  hbuf = sb + OFF_H;
    __half* xnh = hb_ + HO_XNH; __half* xnl = hb_ + HO_XNL;
    __half* ath = hb_ + HO_ATTH; __half* atl = hb_ + HO_ATTL;
    __half* ach = hb_ + HO_ACTH; __half* acl = hb_ + HO_ACTL;
    __half* wh = hb_ + HO_WH;  __half* wl = hb_ + HO_WL;
    __half* qh_ = hb_ + HO_QH; __half* ql_ = hb_ + HO_QL;
    __half* kh_ = hb_ + HO_KH; __half* kl_ = hb_ + HO_KL;
    __half* vh_ = hb_ + HO_VH; __half* vl_ = hb_ + HO_VL;
    __half* vth_ = hb_ + HO_VTH; __half* vtl_ = hb_ + HO_VTL;
    int bh_total = (ntok / SEQ) * BH;
    int mt = ntok / 128;

    split_rope_k<<<ntok, 256>>>(qkv, qh_, ql_, kh_, kl_, vh_, vl_, SEQ);
    if (enc) {
        vtrans_k<<<dim3(SEQ / 64, bh_total), 256>>>(vh_, vl_, vth_, vtl_, SEQ);
        attn_mma_k<<<dim3(SEQ / 64, bh_total), 128, AMMA_SMEM>>>(
            qh_, ql_, kh_, kl_, vth_, vtl_, ath, atl, doc, SEQ);
    } else {
        attn_k<<<dim3(SEQ, bh_total), 128>>>(qh_, ql_, kh_, kl_, vh_, vl_, ath, atl, SEQ);
    }
    sgemm_h3<<<pgrid(4 * mt), 256>>>(ath, atl, wh + oo, wl + oo, cur,
                                     nullptr, nullptr, ntok, 512, 512, 1);
    rmsnorm_k<<<ntok, 128>>>(cur, n2, xnh, xnl);
    sgemm_h3<<<pgrid(16 * mt), 256>>>(xnh, xnl, wh + upo, wl + upo, hbuf,
                                      ach, acl, ntok, 2048, 512, 2);
    sgemm_h3<<<pgrid(4 * mt), 256>>>(ach, acl, wh + dno, wl + dno, cur,
                                     nullptr, nullptr, ntok, 512, 1024, 1);
}

extern "C" void kernel_launch(void* const* d_in, const int* in_sizes, int n_in,
                              void* d_out, int out_size) {
    const float* x_in   = (const float*)d_in[0];
    const int*   doc    = (const int*)d_in[1];
    const float* rt     = (const float*)d_in[2];
    const float* out_w  = (const float*)d_in[3];
    const float* keys_r = (const float*)d_in[4];
    const float* keys_g = (const float*)d_in[5];
    const float* e_qkv  = (const float*)d_in[6];
    const float* e_o    = (const float*)d_in[7];
    const float* e_up   = (const float*)d_in[8];
    const float* e_dn   = (const float*)d_in[9];
    const float* e_n1   = (const float*)d_in[10];
    const float* e_n2   = (const float*)d_in[11];
    const float* r_qkv  = (const float*)d_in[12];
    const float* r_o    = (const float*)d_in[13];
    const float* r_up   = (const float*)d_in[14];
    const float* r_dn   = (const float*)d_in[15];
    const float* r_n1   = (const float*)d_in[16];
    const float* r_n2   = (const float*)d_in[17];
    float* out = (float*)d_out;

    static int attr_set = 0;
    if (!attr_set) {
        cudaFuncSetAttribute(attn_mma_k, cudaFuncAttributeMaxDynamicSharedMemorySize, AMMA_SMEM);
        attr_set = 1;
    }

    float* sb;
    cudaGetSymbolAddress((void**)&sb, g_s);
    __half* hb_;
    cudaGetSymbolAddress((void**)&hb_, g_h);

    float* xbuf = sb + OFF_X;
    float* xr   = sb + OFF_XR;
    float* outp = sb + OFF_OUT;
    float* knr  = sb + OFF_KNR;
    float* kng  = sb + OFF_KNG;
    float* rl   = sb + OFF_RL;
    float* gl   = sb + OFF_GL;
    __half* wh = hb_ + HO_WH;
    __half* wl = hb_ + HO_WL;
    __half* rowsh = hb_ + HO_ROWSH;
    __half* rowsl = hb_ + HO_ROWSL;
    __half* xnh = hb_ + HO_XNH; __half* xnl = hb_ + HO_XNL;
    float*  qkv = sb + OFF_QKV;

    // Launch order chosen so the ncu capture (-s 5 -c 1) profiles the big GEMM.
    // [0] wEQ  [1] copy  [2] rmsnorm  [3] wEO  [4] wEU  [5] sgemm_qkv(layer0)
    wsplitT_k<<<dim3(1536 / 32, 512 / 32, 4), dim3(32, 8)>>>(e_qkv, wh + WO_EQ, wl + WO_EQ, 512, 1536, 0);
    copy_k<<<(NTOK_ENC * DMODEL + 255) / 256, 256>>>(x_in, xbuf, NTOK_ENC * DMODEL);
    rmsnorm_k<<<NTOK_ENC, 128>>>(xbuf, e_n1, xnh, xnl);
    wsplitT_k<<<dim3(512 / 32, 512 / 32, 4), dim3(32, 8)>>>(e_o, wh + WO_EO, wl + WO_EO, 512, 512, 0);
    wsplitT_k<<<dim3(2048 / 32, 512 / 32, 4), dim3(32, 8)>>>(e_up, wh + WO_EU, wl + WO_EU, 512, 2048, 1);
    sgemm_h3<<<pgrid(12 * (NTOK_ENC / 128)), 256>>>(xnh, xnl, wh + WO_EQ, wl + WO_EQ, qkv,
                                                    nullptr, nullptr, NTOK_ENC, 1536, 512, 0);
    // remaining weight prep
    wsplitT_k<<<dim3(512 / 32, 1024 / 32, 4), dim3(32, 8)>>>(e_dn, wh + WO_ED, wl + WO_ED, 1024, 512, 0);
    wsplitT_k<<<dim3(1536 / 32, 512 / 32, 2), dim3(32, 8)>>>(r_qkv, wh + WO_RQ, wl + WO_RQ, 512, 1536, 0);
    wsplitT_k<<<dim3(512 / 32, 512 / 32, 2), dim3(32, 8)>>>(r_o, wh + WO_RO, wl + WO_RO, 512, 512, 0);
    wsplitT_k<<<dim3(2048 / 32, 512 / 32, 2), dim3(32, 8)>>>(r_up, wh + WO_RU, wl + WO_RU, 512, 2048, 1);
    wsplitT_k<<<dim3(512 / 32, 1024 / 32, 2), dim3(32, 8)>>>(r_dn, wh + WO_RD, wl + WO_RD, 1024, 512, 0);
    wsplitT_k<<<dim3(256 / 32, 512 / 32, 1), dim3(32, 8)>>>(out_w, wh + WO_OUT, wl + WO_OUT, 512, 256, 0);

    // layer 0 tail (qkv GEMM already issued above)
    run_layer_tail(xbuf, WO_EO, WO_EU, WO_ED,
                   e_n2, NTOK_ENC, SENC, 1, doc, sb, hb_);

    for (int i = 1; i < 4; i++) {
        rmsnorm_k<<<NTOK_ENC, 128>>>(xbuf, e_n1 + (size_t)i * 512, xnh, xnl);
        sgemm_h3<<<pgrid(12 * (NTOK_ENC / 128)), 256>>>(
            xnh, xnl, wh + WO_EQ + (size_t)i * 786432, wl + WO_EQ + (size_t)i * 786432,
            qkv, nullptr, nullptr, NTOK_ENC, 1536, 512, 0);
        run_layer_tail(xbuf,
                       WO_EO + (size_t)i * 262144,
                       WO_EU + (size_t)i * 1048576,
                       WO_ED + (size_t)i * 524288,
                       e_n2 + (size_t)i * 512, NTOK_ENC, SENC, 1, doc, sb, hb_);
    }

    build_xr_k<<<(NTOK_RTR * DMODEL + 255) / 256, 256>>>(xbuf, rt, xr);

    for (int i = 0; i < 2; i++) {
        rmsnorm_k<<<NTOK_RTR, 128>>>(xr, r_n1 + (size_t)i * 512, xnh, xnl);
        sgemm_h3<<<pgrid(12 * (NTOK_RTR / 128)), 256>>>(
            xnh, xnl, wh + WO_RQ + (size_t)i * 786432, wl + WO_RQ + (size_t)i * 786432,
            qkv, nullptr, nullptr, NTOK_RTR, 1536, 512, 0);
        run_layer_tail(xr,
                       WO_RO + (size_t)i * 262144,
                       WO_RU + (size_t)i * 1048576,
                       WO_RD + (size_t)i * 524288,
                       r_n2 + (size_t)i * 512, NTOK_RTR, SRTR, 0, nullptr, sb, hb_);
    }

    gather_rows_k<<<(512 * DMODEL + 255) / 256, 256>>>(xr, rowsh, rowsl);
    sgemm_h3<<<pgrid(8), 256>>>(rowsh, rowsl, wh + WO_OUT, wl + WO_OUT, outp,
                                nullptr, nullptr, 512, 256, 512, 0);

    knorm_k<<<1, 1024>>>(keys_r, keys_g, knr, kng);
    logits_k<<<32 * 64, 128>>>(outp, keys_r, keys_g, knr, kng, rl, gl);
    topk_k<<<16, 128>>>(rl, gl, out);
}

// round 13
// speedup vs baseline: 1.4259x; 1.4259x over previous
#include <cuda_runtime.h>
#include <cuda_fp16.h>
#include <math.h>
#include <stdint.h>

// Model constants
#define BH      8
#define HDIM    64
#define DMODEL  512
#define SENC    2048
#define SRTR    72
#define NTOK_ENC 4096
#define NTOK_RTR 4608
#define FFH     1024

// ---- fp32 scratch (float offsets) ----
#define OFF_QKV   0ull
#define OFF_H     14155776ull
#define OFF_X     23592960ull
#define OFF_XR    25952256ull
#define OFF_OUT   28311552ull
#define OFF_KNR   28442624ull
#define OFF_KNG   28443136ull
#define OFF_RL    28443648ull
#define OFF_GL    28476416ull
#define SCRATCH_FLOATS 28509184ull
__device__ float g_s[SCRATCH_FLOATS];

// ---- fp16 scratch (half offsets) ----
#define HO_XNH   0ull
#define HO_XNL   2359296ull
#define HO_ATTH  4718592ull
#define HO_ATTL  7077888ull
#define HO_ACTH  9437184ull
#define HO_ACTL  14155776ull
#define HO_ROWSH 18874368ull
#define HO_ROWSL 19136512ull
#define HO_WH    19398656ull
#define HO_WL    35258368ull
#define HO_QH    51118080ull
#define HO_QL    53477376ull
#define HO_KH    55836672ull
#define HO_KL    58195968ull
#define HO_VH    60555264ull
#define HO_VL    62914560ull
#define HO_VTH   65273856ull
#define HO_VTL   67633152ull
#define SCRATCH_HALVES 69992448ull
__device__ __half g_h[SCRATCH_HALVES];

// weight-plane sub-offsets (halves)
#define WO_EQ   0ull
#define WO_EO   3145728ull
#define WO_EU   4194304ull
#define WO_ED   8388608ull
#define WO_RQ   10485760ull
#define WO_RO   12058624ull
#define WO_RU   12582912ull
#define WO_RD   14680064ull
#define WO_OUT  15728640ull

#define NSM_SLOTS 296

// ---------------- helpers ----------------
__device__ __forceinline__ float bsum128(float v, volatile float* red) {
    int tid = threadIdx.x;
    red[tid] = v;
    for (int off = 64; off >= 1; off >>= 1) {
        __syncthreads();
        if (tid < off) red[tid] += red[tid + off];
    }
    __syncthreads();
    float r = red[0];
    __syncthreads();
    return r;
}

__device__ __forceinline__ void split_h(float v, __half& hi, __half& lo) {
    hi = __float2half_rn(v);
    lo = __float2half_rn(v - __half2float(hi));
}

__device__ __forceinline__ void mma16816(float* c, const uint32_t* a, const uint32_t* b) {
    asm volatile(
        "mma.sync.aligned.m16n8k16.row.col.f32.f16.f16.f32 "
        "{%0,%1,%2,%3}, {%4,%5,%6,%7}, {%8,%9}, {%0,%1,%2,%3};"
        : "+f"(c[0]), "+f"(c[1]), "+f"(c[2]), "+f"(c[3])
        : "r"(a[0]), "r"(a[1]), "r"(a[2]), "r"(a[3]), "r"(b[0]), "r"(b[1]));
}

__device__ __forceinline__ uint32_t sptr(const void* p) {
    return (uint32_t)__cvta_generic_to_shared(p);
}

__device__ __forceinline__ void ldsm4(uint32_t& r0, uint32_t& r1, uint32_t& r2,
                                      uint32_t& r3, uint32_t addr) {
    asm volatile("ldmatrix.sync.aligned.m8n8.x4.shared.b16 {%0,%1,%2,%3}, [%4];"
                 : "=r"(r0), "=r"(r1), "=r"(r2), "=r"(r3) : "r"(addr));
}

__device__ __forceinline__ void cpa16(uint32_t dst, const void* src) {
    asm volatile("cp.async.cg.shared.global [%0], [%1], 16;" :: "r"(dst), "l"(src));
}
__device__ __forceinline__ void cpa_commit() { asm volatile("cp.async.commit_group;"); }
__device__ __forceinline__ void cpa_wait0() { asm volatile("cp.async.wait_group 0;"); }
__device__ __forceinline__ void cpa_wait1() { asm volatile("cp.async.wait_group 1;"); }

__device__ __forceinline__ uint32_t h2u(__half2 h) { return *(uint32_t*)&h; }

// ---------------- kernels ----------------
__global__ void copy_k(const float* __restrict__ src, float* __restrict__ dst, int n) {
    int i = blockIdx.x * blockDim.x + threadIdx.x;
    if (i < n) dst[i] = src[i];
}

// transpose + split weights; gridDim.z = layer index
__global__ void wsplitT_k(const float* __restrict__ w, __half* __restrict__ hT,
                          __half* __restrict__ lT, int K, int N, int ilv) {
    __shared__ float t[32][33];
    size_t loff = (size_t)blockIdx.z * K * N;
    w += loff; hT += loff; lT += loff;
    int n0 = blockIdx.x * 32, k0 = blockIdx.y * 32;
    int tx = threadIdx.x, ty = threadIdx.y;
    for (int i = ty; i < 32; i += 8) {
        int n = n0 + tx;
        int srcn = ilv ? ((n & 1) ? (N >> 1) + (n >> 1) : (n >> 1)) : n;
        t[i][tx] = w[(size_t)(k0 + i) * N + srcn];
    }
    __syncthreads();
    for (int i = ty; i < 32; i += 8) {
        float v = t[tx][i];
        __half h, l;
        split_h(v, h, l);
        hT[(size_t)(n0 + i) * K + k0 + tx] = h;
        lT[(size_t)(n0 + i) * K + k0 + tx] = l;
    }
}

__global__ void rmsnorm_k(const float* __restrict__ x, const float* __restrict__ w,
                          __half* __restrict__ yh, __half* __restrict__ yl) {
    __shared__ float red[128];
    size_t row = (size_t)blockIdx.x * DMODEL;
    int tid = threadIdx.x;
    float ss = 0.f;
    for (int i = tid; i < DMODEL; i += 128) {
        float v = x[row + i];
        ss += v * v;
    }
    float tot = bsum128(ss, red);
    float scale = rsqrtf(tot / (float)DMODEL + 1e-6f);
    for (int i = tid; i < DMODEL; i += 128) {
        __half h, l;
        split_h(x[row + i] * scale * w[i], h, l);
        yh[row + i] = h;
        yl[row + i] = l;
    }
}

// ---- 3xFP16 split GEMM, 3-stage cp.async pipeline, persistent over tiles ----
// mode 0: C = A@B ; mode 1: C += A@B ; mode 2: silu-gate epilogue to Dh/Dl.
// Dynamic smem: 3 stages x 12288 halves (A hi/lo + B hi/lo, rows of 24).
#define STG_H 12288
#define GEMM_SMEM (3 * STG_H * 2)
__global__ __launch_bounds__(256) void sgemm_h3(const __half* __restrict__ Ah,
                                                const __half* __restrict__ Al,
                                                const __half* __restrict__ BTh,
                                                const __half* __restrict__ BTl,
                                                float* __restrict__ C,
                                                __half* __restrict__ Dh,
                                                __half* __restrict__ Dl,
                                                int M, int N, int K, int mode) {
    extern __shared__ __align__(16) __half gsm[];
    int tid = threadIdx.x;
    int lane = tid & 31, warp = tid >> 5;
    int wm = warp >> 2, wn = warp & 3;
    int grp = lane >> 2, qid = lane & 3;
    int lrow = tid >> 1, lseg = (tid & 1) * 8;
    int arow = lane & 15, acg = (lane >> 4) * 8;
    int nk = K >> 4;
    int ntN = N >> 7;
    int ntiles = (M >> 7) * ntN;

#define SA0(s) (gsm + (s) * STG_H)
#define SA1(s) (gsm + (s) * STG_H + 3072)
#define SB0(s) (gsm + (s) * STG_H + 6144)
#define SB1(s) (gsm + (s) * STG_H + 9216)
#define LOADS(s, k0)                                                                 \
    {                                                                                \
        cpa16(sptr(SA0(s) + lrow * 24 + lseg), Ah + (size_t)(bm + lrow) * K + (k0) + lseg); \
        cpa16(sptr(SA1(s) + lrow * 24 + lseg), Al + (size_t)(bm + lrow) * K + (k0) + lseg); \
        cpa16(sptr(SB0(s) + lrow * 24 + lseg), BTh + (size_t)(bn + lrow) * K + (k0) + lseg); \
        cpa16(sptr(SB1(s) + lrow * 24 + lseg), BTl + (size_t)(bn + lrow) * K + (k0) + lseg); \
        cpa_commit();                                                                \
    }

    for (int t = blockIdx.x; t < ntiles; t += gridDim.x) {
        int bm = (t / ntN) << 7;
        int bn = (t % ntN) << 7;

        float acc[4][4][4];
#pragma unroll
        for (int i = 0; i < 4; i++)
#pragma unroll
            for (int j = 0; j < 4; j++)
#pragma unroll
                for (int u = 0; u < 4; u++) acc[i][j][u] = 0.f;

        __syncthreads();        // all warps done with previous tile's smem
        LOADS(0, 0);
        LOADS(1, 16);           // nk >= 32 for all shapes here

        for (int kt = 0; kt < nk; kt++) {
            int slot = kt % 3;
            if (kt + 1 < nk) cpa_wait1(); else cpa_wait0();
            __syncthreads();
            if (kt + 2 < nk) {
                int s2 = (kt + 2) % 3;
                LOADS(s2, (kt + 2) << 4);
            }

            uint32_t ah[4][4], al[4][4], bh[4][2], bl[4][2];
#pragma unroll
            for (int mt = 0; mt < 4; mt++) {
                int r = wm * 64 + mt * 16 + arow;
                ldsm4(ah[mt][0], ah[mt][1], ah[mt][2], ah[mt][3], sptr(SA0(slot) + r * 24 + acg));
                ldsm4(al[mt][0], al[mt][1], al[mt][2], al[mt][3], sptr(SA1(slot) + r * 24 + acg));
            }
#pragma unroll
            for (int ntp = 0; ntp < 2; ntp++) {
                int r = wn * 32 + ntp * 16 + arow;
                uint32_t m0, m1, m2, m3;
                ldsm4(m0, m1, m2, m3, sptr(SB0(slot) + r * 24 + acg));
                bh[2 * ntp][0] = m0; bh[2 * ntp][1] = m2;
                bh[2 * ntp + 1][0] = m1; bh[2 * ntp + 1][1] = m3;
                ldsm4(m0, m1, m2, m3, sptr(SB1(slot) + r * 24 + acg));
                bl[2 * ntp][0] = m0; bl[2 * ntp][1] = m2;
                bl[2 * ntp + 1][0] = m1; bl[2 * ntp + 1][1] = m3;
            }
#pragma unroll
            for (int mt = 0; mt < 4; mt++)
#pragma unroll
                for (int nt = 0; nt < 4; nt++) {
                    mma16816(acc[mt][nt], al[mt], bh[nt]);
                    mma16816(acc[mt][nt], ah[mt], bl[nt]);
                    mma16816(acc[mt][nt], ah[mt], bh[nt]);
                }
        }

        if (mode == 2) {
            int half_n = N >> 1;
#pragma unroll
            for (int mt = 0; mt < 4; mt++)
#pragma unroll
                for (int nt = 0; nt < 4; nt++) {
                    int r0 = bm + wm * 64 + mt * 16 + grp;
                    int j = (bn + wn * 32 + nt * 8 + 2 * qid) >> 1;
                    float a0 = acc[mt][nt][0], b0 = acc[mt][nt][1];
                    float a1 = acc[mt][nt][2], b1 = acc[mt][nt][3];
                    float g0 = (a0 / (1.0f + __expf(-a0))) * b0;
                    float g1 = (a1 / (1.0f + __expf(-a1))) * b1;
                    __half h, l;
                    split_h(g0, h, l);
                    Dh[(size_t)r0 * half_n + j] = h;
                    Dl[(size_t)r0 * half_n + j] = l;
                    split_h(g1, h, l);
                    Dh[(size_t)(r0 + 8) * half_n + j] = h;
                    Dl[(size_t)(r0 + 8) * half_n + j] = l;
                }
        } else {
#pragma unroll
            for (int mt = 0; mt < 4; mt++)
#pragma unroll
                for (int nt = 0; nt < 4; nt++) {
                    int r0 = bm + wm * 64 + mt * 16 + grp;
                    int c0 = bn + wn * 32 + nt * 8 + 2 * qid;
                    size_t i00 = (size_t)r0 * N + c0;
                    size_t i10 = (size_t)(r0 + 8) * N + c0;
                    if (mode == 1) {
                        C[i00]     += acc[mt][nt][0];
                        C[i00 + 1] += acc[mt][nt][1];
                        C[i10]     += acc[mt][nt][2];
                        C[i10 + 1] += acc[mt][nt][3];
                    } else {
                        C[i00]     = acc[mt][nt][0];
                        C[i00 + 1] = acc[mt][nt][1];
                        C[i10]     = acc[mt][nt][2];
                        C[i10 + 1] = acc[mt][nt][3];
                    }
                }
        }
    }
#undef LOADS
}

// qkv row -> q/k (RoPE) and v, hi/lo half planes [bh][SEQ][64]
__global__ void split_rope_k(const float* __restrict__ qkv,
                             __half* __restrict__ Qh, __half* __restrict__ Ql,
                             __half* __restrict__ Kh, __half* __restrict__ Kl,
                             __half* __restrict__ Vh, __half* __restrict__ Vl,
                             int SEQ) {
    int tok = blockIdx.x;
    int b = tok / SEQ, s = tok % SEQ;
    const float* row = qkv + (size_t)tok * 1536;
    int tid = threadIdx.x;
    int h = tid >> 5, i = tid & 31;
    float q1 = row[h * 64 + i], q2 = row[h * 64 + i + 32];
    float k1 = row[512 + h * 64 + i], k2 = row[512 + h * 64 + i + 32];
    float inv = powf(1e-4f, (float)i * (1.0f / 32.0f));
    float ang = (float)s * inv;
    float c = cosf(ang), sn = sinf(ang);
    size_t base = ((size_t)(b * BH + h) * SEQ + s) * 64;
    __half hh, ll;
    split_h(q1 * c + q2 * sn, hh, ll);      Qh[base + i] = hh;      Ql[base + i] = ll;
    split_h(-q1 * sn + q2 * c, hh, ll);     Qh[base + i + 32] = hh; Ql[base + i + 32] = ll;
    split_h(k1 * c + k2 * sn, hh, ll);      Kh[base + i] = hh;      Kl[base + i] = ll;
    split_h(-k1 * sn + k2 * c, hh, ll);     Kh[base + i + 32] = hh; Kl[base + i + 32] = ll;
    for (int j = tid; j < 512; j += 256) {
        int hd = j >> 6, dd = j & 63;
        split_h(row[1024 + j], hh, ll);
        size_t vi = ((size_t)(b * BH + hd) * SEQ + s) * 64 + dd;
        Vh[vi] = hh;
        Vl[vi] = ll;
    }
}

// V [bh][s][64] -> Vt [bh][64][s]
__global__ void vtrans_k(const __half* __restrict__ Vh, const __half* __restrict__ Vl,
                         __half* __restrict__ Vth, __half* __restrict__ Vtl, int SEQ) {
    __shared__ __half t[2][64][72];
    int sc = blockIdx.x * 64;
    int bh = blockIdx.y;
    int tid = threadIdx.x;
    for (int i = tid; i < 512; i += 256) {
        int r = i >> 3, c = (i & 7) * 8;
        *(uint4*)&t[0][r][c] = *(const uint4*)(Vh + ((size_t)bh * SEQ + sc + r) * 64 + c);
        *(uint4*)&t[1][r][c] = *(const uint4*)(Vl + ((size_t)bh * SEQ + sc + r) * 64 + c);
    }
    __syncthreads();
    for (int i = tid; i < 4096; i += 256) {
        int d = i >> 6, s = i & 63;
        Vth[((size_t)bh * 64 + d) * SEQ + sc + s] = t[0][s][d];
        Vtl[((size_t)bh * 64 + d) * SEQ + sc + s] = t[1][s][d];
    }
}

// ---- tensor-core flash attention, 3xFP16 split (encoder path) ----
#define ATS 72
#define AMMA_SMEM (6 * 64 * ATS * 2 + 256)
__global__ __launch_bounds__(128) void attn_mma_k(
        const __half* __restrict__ Qh, const __half* __restrict__ Ql,
        const __half* __restrict__ Kh, const __half* __restrict__ Kl,
        const __half* __restrict__ Vth, const __half* __restrict__ Vtl,
        __half* __restrict__ Oh, __half* __restrict__ Ol,
        const int* __restrict__ doc, int SEQ) {
    extern __shared__ __half hsm[];
    __half* Qsh = hsm;
    __half* Qsl = hsm + 64 * ATS;
    __half* Ksh = hsm + 2 * 64 * ATS;
    __half* Ksl = hsm + 3 * 64 * ATS;
    __half* Vsh = hsm + 4 * 64 * ATS;
    __half* Vsl = hsm + 5 * 64 * ATS;
    int* sdoc = (int*)(hsm + 6 * 64 * ATS);

    int qb = blockIdx.x, bh = blockIdx.y;
    int b = bh >> 3, h = bh & 7;
    int tid = threadIdx.x, lane = tid & 31, warp = tid >> 5;
    int grp = lane >> 2, qid = lane & 3;
    int arow = lane & 15, acg = (lane >> 4) * 8;

    const __half* Qbh = Qh + ((size_t)bh * SEQ + qb * 64) * 64;
    const __half* Qbl = Ql + ((size_t)bh * SEQ + qb * 64) * 64;
    for (int i = tid; i < 512; i += 128) {
        int r = i >> 3, c = (i & 7) * 8;
        *(uint4*)(Qsh + r * ATS + c) = *(const uint4*)(Qbh + r * 64 + c);
        *(uint4*)(Qsl + r * ATS + c) = *(const uint4*)(Qbl + r * 64 + c);
    }
    __syncthreads();

    uint32_t qfh[4][4], qfl[4][4];
#pragma unroll
    for (int ds = 0; ds < 4; ds++) {
        ldsm4(qfh[ds][0], qfh[ds][1], qfh[ds][2], qfh[ds][3],
              sptr(Qsh + (warp * 16 + arow) * ATS + ds * 16 + acg));
        ldsm4(qfl[ds][0], qfl[ds][1], qfl[ds][2], qfl[ds][3],
              sptr(Qsl + (warp * 16 + arow) * ATS + ds * 16 + acg));
    }
    int dq0 = doc[b * SEQ + qb * 64 + warp * 16 + grp];
    int dq1 = doc[b * SEQ + qb * 64 + warp * 16 + grp + 8];

    float o[8][4];
#pragma unroll
    for (int j = 0; j < 8; j++)
#pragma unroll
        for (int t = 0; t < 4; t++) o[j][t] = 0.f;
    float m0r = -1e30f, m1r = -1e30f, l0 = 0.f, l1 = 0.f;

    const __half* Kbh = Kh + (size_t)bh * SEQ * 64;
    const __half* Kbl = Kl + (size_t)bh * SEQ * 64;
    const __half* Vbh = Vth + (size_t)bh * 64 * SEQ;
    const __half* Vbl = Vtl + (size_t)bh * 64 * SEQ;

    for (int kt = 0; kt <= qb; kt++) {
        int kbase = kt * 64;
        __syncthreads();
        for (int i = tid; i < 512; i += 128) {
            int r = i >> 3, c = (i & 7) * 8;
            *(uint4*)(Ksh + r * ATS + c) = *(const uint4*)(Kbh + (size_t)(kbase + r) * 64 + c);
            *(uint4*)(Ksl + r * ATS + c) = *(const uint4*)(Kbl + (size_t)(kbase + r) * 64 + c);
            *(uint4*)(Vsh + r * ATS + c) = *(const uint4*)(Vbh + (size_t)r * SEQ + kbase + c);
            *(uint4*)(Vsl + r * ATS + c) = *(const uint4*)(Vbl + (size_t)r * SEQ + kbase + c);
        }
        if (tid < 64) sdoc[tid] = doc[b * SEQ + kbase + tid];
        __syncthreads();

        float sc[8][4];
#pragma unroll
        for (int j = 0; j < 8; j++)
#pragma unroll
            for (int t = 0; t < 4; t++) sc[j][t] = 0.f;
#pragma unroll
        for (int ds = 0; ds < 4; ds++) {
            uint32_t kfh[8][2], kfl[8][2];
#pragma unroll
            for (int np = 0; np < 4; np++) {
                uint32_t m0, m1, m2, m3;
                ldsm4(m0, m1, m2, m3, sptr(Ksh + (np * 16 + arow) * ATS + ds * 16 + acg));
                kfh[2 * np][0] = m0; kfh[2 * np][1] = m2;
                kfh[2 * np + 1][0] = m1; kfh[2 * np + 1][1] = m3;
                ldsm4(m0, m1, m2, m3, sptr(Ksl + (np * 16 + arow) * ATS + ds * 16 + acg));
                kfl[2 * np][0] = m0; kfl[2 * np][1] = m2;
                kfl[2 * np + 1][0] = m1; kfl[2 * np + 1][1] = m3;
            }
#pragma unroll
            for (int j = 0; j < 8; j++) {
                mma16816(sc[j], qfl[ds], kfh[j]);
                mma16816(sc[j], qfh[ds], kfl[j]);
                mma16816(sc[j], qfh[ds], kfh[j]);
            }
        }

#pragma unroll
        for (int j = 0; j < 8; j++) {
            int dk0 = sdoc[8 * j + 2 * qid], dk1 = sdoc[8 * j + 2 * qid + 1];
            sc[j][0] = (dk0 == dq0) ? sc[j][0] * 0.125f : -6e30f;
            sc[j][1] = (dk1 == dq0) ? sc[j][1] * 0.125f : -6e30f;
            sc[j][2] = (dk0 == dq1) ? sc[j][2] * 0.125f : -6e30f;
            sc[j][3] = (dk1 == dq1) ? sc[j][3] * 0.125f : -6e30f;
        }

        float tm0 = -1e30f, tm1 = -1e30f;
#pragma unroll
        for (int j = 0; j < 8; j++) {
            tm0 = fmaxf(tm0, fmaxf(sc[j][0], sc[j][1]));
            tm1 = fmaxf(tm1, fmaxf(sc[j][2], sc[j][3]));
        }
#pragma unroll
        for (int off = 1; off < 4; off <<= 1) {
            tm0 = fmaxf(tm0, __shfl_xor_sync(0xffffffffu, tm0, off));
            tm1 = fmaxf(tm1, __shfl_xor_sync(0xffffffffu, tm1, off));
        }
        float mn0 = fmaxf(m0r, tm0), mn1 = fmaxf(m1r, tm1);
        float r0 = __expf(m0r - mn0), r1 = __expf(m1r - mn1);

        uint32_t pfh[8][2], pfl[8][2];
        float ps0 = 0.f, ps1 = 0.f;
#pragma unroll
        for (int j = 0; j < 8; j++) {
            float p0 = __expf(sc[j][0] - mn0), p1 = __expf(sc[j][1] - mn0);
            float p2 = __expf(sc[j][2] - mn1), p3 = __expf(sc[j][3] - mn1);
            ps0 += p0 + p1; ps1 += p2 + p3;
            __half2 hA = __floats2half2_rn(p0, p1);
            __half2 hB = __floats2half2_rn(p2, p3);
            pfh[j][0] = h2u(hA);
            pfh[j][1] = h2u(hB);
            __half2 lA = __floats2half2_rn(p0 - __half2float(__low2half(hA)),
                                           p1 - __half2float(__high2half(hA)));
            __half2 lB = __floats2half2_rn(p2 - __half2float(__low2half(hB)),
                                           p3 - __half2float(__high2half(hB)));
            pfl[j][0] = h2u(lA);
            pfl[j][1] = h2u(lB);
        }
#pragma unroll
        for (int off = 1; off < 4; off <<= 1) {
            ps0 += __shfl_xor_sync(0xffffffffu, ps0, off);
            ps1 += __shfl_xor_sync(0xffffffffu, ps1, off);
        }
        l0 = l0 * r0 + ps0;
        l1 = l1 * r1 + ps1;
        m0r = mn0; m1r = mn1;
#pragma unroll
        for (int j = 0; j < 8; j++) {
            o[j][0] *= r0; o[j][1] *= r0; o[j][2] *= r1; o[j][3] *= r1;
        }

#pragma unroll
        for (int ks = 0; ks < 4; ks++) {
            uint32_t pah[4] = {pfh[2 * ks][0], pfh[2 * ks][1], pfh[2 * ks + 1][0], pfh[2 * ks + 1][1]};
            uint32_t pal[4] = {pfl[2 * ks][0], pfl[2 * ks][1], pfl[2 * ks + 1][0], pfl[2 * ks + 1][1]};
            uint32_t vfh[8][2], vfl[8][2];
#pragma unroll
            for (int np = 0; np < 4; np++) {
                uint32_t m0, m1, m2, m3;
                ldsm4(m0, m1, m2, m3, sptr(Vsh + (np * 16 + arow) * ATS + ks * 16 + acg));
                vfh[2 * np][0] = m0; vfh[2 * np][1] = m2;
                vfh[2 * np + 1][0] = m1; vfh[2 * np + 1][1] = m3;
                ldsm4(m0, m1, m2, m3, sptr(Vsl + (np * 16 + arow) * ATS + ks * 16 + acg));
                vfl[2 * np][0] = m0; vfl[2 * np][1] = m2;
                vfl[2 * np + 1][0] = m1; vfl[2 * np + 1][1] = m3;
            }
#pragma unroll
            for (int j = 0; j < 8; j++) {
                mma16816(o[j], pal, vfh[j]);
                mma16816(o[j], pah, vfl[j]);
                mma16816(o[j], pah, vfh[j]);
            }
        }
    }

    float inv0 = 1.0f / l0, inv1 = 1.0f / l1;
    int row0 = qb * 64 + warp * 16 + grp;
#pragma unroll
    for (int j = 0; j < 8; j++) {
        int col = h * 64 + 8 * j + 2 * qid;
        float v0 = o[j][0] * inv0, v1 = o[j][1] * inv0;
        __half2 hh = __floats2half2_rn(v0, v1);
        __half2 ll = __floats2half2_rn(v0 - __half2float(__low2half(hh)),
                                       v1 - __half2float(__high2half(hh)));
        size_t i0 = (size_t)(b * SEQ + row0) * DMODEL + col;
        *(__half2*)(Oh + i0) = hh;
        *(__half2*)(Ol + i0) = ll;
        float v2 = o[j][2] * inv1, v3 = o[j][3] * inv1;
        hh = __floats2half2_rn(v2, v3);
        ll = __floats2half2_rn(v2 - __half2float(__low2half(hh)),
                               v3 - __half2float(__high2half(hh)));
        size_t i1 = (size_t)(b * SEQ + row0 + 8) * DMODEL + col;
        *(__half2*)(Oh + i1) = hh;
        *(__half2*)(Ol + i1) = ll;
    }
}

// ---- router attention: one block per (seq, head), full 72x72 in smem ----
// smem: Qs/Ks/Vs [72][65] fp32, Ps [72][73], den[72]  (~77.5 KB dynamic)
#define ATR_SMEM ((72 * 65 * 3 + 72 * 73 + 72) * 4)
__global__ __launch_bounds__(128) void attn_r2(
        const __half* __restrict__ Qh, const __half* __restrict__ Ql,
        const __half* __restrict__ Kh, const __half* __restrict__ Kl,
        const __half* __restrict__ Vh, const __half* __restrict__ Vl,
        __half* __restrict__ Oh, __half* __restrict__ Ol) {
    extern __shared__ float rs[];
    float* Qs = rs;
    float* Ks = rs + 72 * 65;
    float* Vs = rs + 2 * 72 * 65;
    float* Ps = rs + 3 * 72 * 65;
    float* den = rs + 3 * 72 * 65 + 72 * 73;

    int bh = blockIdx.x;
    int tid = threadIdx.x;

    for (int i = tid; i < 72 * 64; i += 128) {
        int r = i >> 6, d = i & 63;
        size_t base = ((size_t)bh * SRTR + r) * 64 + d;
        Qs[r * 65 + d] = __half2float(Qh[base]) + __half2float(Ql[base]);
        Ks[r * 65 + d] = __half2float(Kh[base]) + __half2float(Kl[base]);
        Vs[r * 65 + d] = __half2float(Vh[base]) + __half2float(Vl[base]);
    }
    __syncthreads();

    if (tid < 72) {
        int q = tid;
        float m = -1e30f;
        for (int k = 0; k < 72; k++) {
            float s = 0.f;
#pragma unroll 16
            for (int d = 0; d < 64; d++)
                s += Qs[q * 65 + d] * Ks[k * 65 + d];
            s *= 0.125f;
            Ps[q * 73 + k] = s;
            m = fmaxf(m, s);
        }
        float l = 0.f;
        for (int k = 0; k < 72; k++) {
            float e = __expf(Ps[q * 73 + k] - m);
            Ps[q * 73 + k] = e;
            l += e;
        }
        den[q] = 1.0f / l;
    }
    __syncthreads();

    int b = bh >> 3, h = bh & 7;
    for (int i = tid; i < 72 * 64; i += 128) {
        int q = i >> 6, d = i & 63;
        float acc = 0.f;
#pragma unroll 8
        for (int k = 0; k < 72; k++)
            acc += Ps[q * 73 + k] * Vs[k * 65 + d];
        float o = acc * den[q];
        size_t idx = (size_t)(b * SRTR + q) * DMODEL + h * 64 + d;
        __half hh, ll;
        split_h(o, hh, ll);
        Oh[idx] = hh;
        Ol[idx] = ll;
    }
}

__global__ void build_xr_k(const float* __restrict__ x, const float* __restrict__ rt,
                           float* __restrict__ xr) {
    int i = blockIdx.x * blockDim.x + threadIdx.x;
    if (i >= NTOK_RTR * DMODEL) return;
    int blk = i / (SRTR * DMODEL);
    int rem = i % (SRTR * DMODEL);
    int t = rem / DMODEL, dd = rem % DMODEL;
    xr[i] = (t < 64) ? x[(size_t)(blk * 64 + t) * DMODEL + dd]
                     : rt[(size_t)(t - 64) * DMODEL + dd];
}

__global__ void gather_rows_k(const float* __restrict__ xr, __half* __restrict__ rh,
                              __half* __restrict__ rl) {
    int i = blockIdx.x * blockDim.x + threadIdx.x;
    if (i >= 512 * DMODEL) return;
    int row = i / DMODEL, dd = i % DMODEL;
    int blk = row >> 3, r = row & 7;
    __half h, l;
    split_h(xr[((size_t)blk * SRTR + 64 + r) * DMODEL + dd], h, l);
    rh[i] = h;
    rl[i] = l;
}

__global__ void knorm_k(const float* __restrict__ kr, const float* __restrict__ kg,
                        float* __restrict__ knr, float* __restrict__ kng) {
    int tid = threadIdx.x;
    int which = tid >> 9;
    int idx = tid & 511;
    int g = idx >> 4, e = idx & 15;
    const float* src = which ? kg : kr;
    const float* col = src + (size_t)g * 128 * 16 + e;
    float s = 0.f;
    for (int d = 0; d < 128; d++) { float v = col[d * 16]; s += v * v; }
    float n = fmaxf(sqrtf(s), 1e-12f);
    if (which) kng[idx] = n; else knr[idx] = n;
}

__global__ void logits_k(const float* __restrict__ outp,
                         const float* __restrict__ keys_r, const float* __restrict__ keys_g,
                         const float* __restrict__ knr, const float* __restrict__ kng,
                         float* __restrict__ rl, float* __restrict__ gl) {
    __shared__ float vr[128], vg[128], red[128];
    int g = blockIdx.x >> 6, bb = blockIdx.x & 63;
    int b = bb >> 5, l = bb & 31;
    int srcl = (l + 31) & 31;
    int r = g >> 2;
    const float* row = outp + (size_t)((b * 32 + srcl) * 8 + r) * 256;
    int tid = threadIdx.x;
    vr[tid] = row[tid];
    vg[tid] = row[128 + tid];
    float nr2 = bsum128(vr[tid] * vr[tid], red);
    float ng2 = bsum128(vg[tid] * vg[tid], red);
    float inr = 1.0f / fmaxf(sqrtf(nr2), 1e-12f);
    float ing = 1.0f / fmaxf(sqrtf(ng2), 1e-12f);
    if (tid < 16) {
        int e = tid;
        const float* kr = keys_r + (size_t)g * 128 * 16 + e;
        const float* kg = keys_g + (size_t)g * 128 * 16 + e;
        float dr = 0.f, dg = 0.f;
        for (int dd = 0; dd < 128; dd++) {
            dr += vr[dd] * kr[dd * 16];
            dg += vg[dd] * kg[dd * 16];
        }
        rl[(size_t)(g * 64 + bb) * 16 + e] = dr * inr / knr[g * 16 + e];
        gl[(size_t)(g * 64 + bb) * 16 + e] = dg * ing / kng[g * 16 + e];
    }
}

__global__ void topk_k(const float* __restrict__ rl, const float* __restrict__ gl,
                       float* __restrict__ out) {
    int t = blockIdx.x * blockDim.x + threadIdx.x;
    if (t >= 2048) return;
    const float* r = rl + (size_t)t * 16;
    const float* g = gl + (size_t)t * 16;
    int i1 = 0; float v1 = r[0];
    for (int e = 1; e < 16; e++) if (r[e] > v1) { v1 = r[e]; i1 = e; }
    int i2 = -1; float v2 = -1e30f;
    for (int e = 0; e < 16; e++) {
        if (e == i1) continue;
        if (r[e] > v2) { v2 = r[e]; i2 = e; }
    }
    out[(size_t)t * 2 + 0] = v1;
    out[(size_t)t * 2 + 1] = v2;
    out[4096 + (size_t)t * 2 + 0] = g[i1];
    out[4096 + (size_t)t * 2 + 1] = g[i2];
}

// ---------------- host orchestration ----------------
static inline int pgrid(int tiles) { return tiles < NSM_SLOTS ? tiles : NSM_SLOTS; }

static void run_layer(float* cur, size_t qkvo, size_t oo, size_t upo, size_t dno,
                      const float* n1, const float* n2,
                      int ntok, int SEQ, int enc, const int* doc,
                      float* sb, __half* hb_) {
    float*  qkv  = sb + OFF_QKV;
    float*  hbuf = sb + OFF_H;
    __half* xnh = hb_ + HO_XNH; __half* xnl = hb_ + HO_XNL;
    __half* ath = hb_ + HO_ATTH; __half* atl = hb_ + HO_ATTL;
    __half* ach = hb_ + HO_ACTH; __half* acl = hb_ + HO_ACTL;
    __half* wh = hb_ + HO_WH;  __half* wl = hb_ + HO_WL;
    __half* qh_ = hb_ + HO_QH; __half* ql_ = hb_ + HO_QL;
    __half* kh_ = hb_ + HO_KH; __half* kl_ = hb_ + HO_KL;
    __half* vh_ = hb_ + HO_VH; __half* vl_ = hb_ + HO_VL;
    __half* vth_ = hb_ + HO_VTH; __half* vtl_ = hb_ + HO_VTL;
    int bh_total = (ntok / SEQ) * BH;
    int mt = ntok / 128;

    rmsnorm_k<<<ntok, 128>>>(cur, n1, xnh, xnl);
    sgemm_h3<<<pgrid(12 * mt), 256, GEMM_SMEM>>>(xnh, xnl, wh + qkvo, wl + qkvo, qkv,
                                                 nullptr, nullptr, ntok, 1536, 512, 0);
    split_rope_k<<<ntok, 256>>>(qkv, qh_, ql_, kh_, kl_, vh_, vl_, SEQ);
    if (enc) {
        vtrans_k<<<dim3(SEQ / 64, bh_total), 256>>>(vh_, vl_, vth_, vtl_, SEQ);
        attn_mma_k<<<dim3(SEQ / 64, bh_total), 128, AMMA_SMEM>>>(
            qh_, ql_, kh_, kl_, vth_, vtl_, ath, atl, doc, SEQ);
    } else {
        attn_r2<<<bh_total, 128, ATR_SMEM>>>(qh_, ql_, kh_, kl_, vh_, vl_, ath, atl);
    }
    sgemm_h3<<<pgrid(4 * mt), 256, GEMM_SMEM>>>(ath, atl, wh + oo, wl + oo, cur,
                                                nullptr, nullptr, ntok, 512, 512, 1);
    rmsnorm_k<<<ntok, 128>>>(cur, n2, xnh, xnl);
    sgemm_h3<<<pgrid(16 * mt), 256, GEMM_SMEM>>>(xnh, xnl, wh + upo, wl + upo, hbuf,
                                                 ach, acl, ntok, 2048, 512, 2);
    sgemm_h3<<<pgrid(4 * mt), 256, GEMM_SMEM>>>(ach, acl, wh + dno, wl + dno, cur,
                                                nullptr, nullptr, ntok, 512, 1024, 1);
}

extern "C" void kernel_launch(void* const* d_in, const int* in_sizes, int n_in,
                              void* d_out, int out_size) {
    const float* x_in   = (const float*)d_in[0];
    const int*   doc    = (const int*)d_in[1];
    const float* rt     = (const float*)d_in[2];
    const float* out_w  = (const float*)d_in[3];
    const float* keys_r = (const float*)d_in[4];
    const float* keys_g = (const float*)d_in[5];
    const float* e_qkv  = (const float*)d_in[6];
    const float* e_o    = (const float*)d_in[7];
    const float* e_up   = (const float*)d_in[8];
    const float* e_dn   = (const float*)d_in[9];
    const float* e_n1   = (const float*)d_in[10];
    const float* e_n2   = (const float*)d_in[11];
    const float* r_qkv  = (const float*)d_in[12];
    const float* r_o    = (const float*)d_in[13];
    const float* r_up   = (const float*)d_in[14];
    const float* r_dn   = (const float*)d_in[15];
    const float* r_n1   = (const float*)d_in[16];
    const float* r_n2   = (const float*)d_in[17];
    float* out = (float*)d_out;

    static int attr_set = 0;
    if (!attr_set) {
        cudaFuncSetAttribute(attn_mma_k, cudaFuncAttributeMaxDynamicSharedMemorySize, AMMA_SMEM);
        cudaFuncSetAttribute(sgemm_h3, cudaFuncAttributeMaxDynamicSharedMemorySize, GEMM_SMEM);
        cudaFuncSetAttribute(attn_r2, cudaFuncAttributeMaxDynamicSharedMemorySize, ATR_SMEM);
        attr_set = 1;
    }

    float* sb;
    cudaGetSymbolAddress((void**)&sb, g_s);
    __half* hb_;
    cudaGetSymbolAddress((void**)&hb_, g_h);

    float* xbuf = sb + OFF_X;
    float* xr   = sb + OFF_XR;
    float* outp = sb + OFF_OUT;
    float* knr  = sb + OFF_KNR;
    float* kng  = sb + OFF_KNG;
    float* rl   = sb + OFF_RL;
    float* gl   = sb + OFF_GL;
    __half* wh = hb_ + HO_WH;
    __half* wl = hb_ + HO_WL;
    __half* rowsh = hb_ + HO_ROWSH;
    __half* rowsl = hb_ + HO_ROWSL;

    // pre-split all weights (batched over layers via grid.z)
    wsplitT_k<<<dim3(1536 / 32, 512 / 32, 4), dim3(32, 8)>>>(e_qkv, wh + WO_EQ, wl + WO_EQ, 512, 1536, 0);
    wsplitT_k<<<dim3(512 / 32, 512 / 32, 4), dim3(32, 8)>>>(e_o, wh + WO_EO, wl + WO_EO, 512, 512, 0);
    wsplitT_k<<<dim3(2048 / 32, 512 / 32, 4), dim3(32, 8)>>>(e_up, wh + WO_EU, wl + WO_EU, 512, 2048, 1);
    wsplitT_k<<<dim3(512 / 32, 1024 / 32, 4), dim3(32, 8)>>>(e_dn, wh + WO_ED, wl + WO_ED, 1024, 512, 0);
    wsplitT_k<<<dim3(1536 / 32, 512 / 32, 2), dim3(32, 8)>>>(r_qkv, wh + WO_RQ, wl + WO_RQ, 512, 1536, 0);
    wsplitT_k<<<dim3(512 / 32, 512 / 32, 2), dim3(32, 8)>>>(r_o, wh + WO_RO, wl + WO_RO, 512, 512, 0);
    wsplitT_k<<<dim3(2048 / 32, 512 / 32, 2), dim3(32, 8)>>>(r_up, wh + WO_RU, wl + WO_RU, 512, 2048, 1);
    wsplitT_k<<<dim3(512 / 32, 1024 / 32, 2), dim3(32, 8)>>>(r_dn, wh + WO_RD, wl + WO_RD, 1024, 512, 0);
    wsplitT_k<<<dim3(256 / 32, 512 / 32, 1), dim3(32, 8)>>>(out_w, wh + WO_OUT, wl + WO_OUT, 512, 256, 0);

    copy_k<<<(NTOK_ENC * DMODEL + 255) / 256, 256>>>(x_in, xbuf, NTOK_ENC * DMODEL);

    for (int i = 0; i < 4; i++) {
        run_layer(xbuf,
                  WO_EQ + (size_t)i * 786432,
                  WO_EO + (size_t)i * 262144,
                  WO_EU + (size_t)i * 1048576,
                  WO_ED + (size_t)i * 524288,
                  e_n1 + (size_t)i * 512, e_n2 + (size_t)i * 512,
                  NTOK_ENC, SENC, 1, doc, sb, hb_);
    }

    build_xr_k<<<(NTOK_RTR * DMODEL + 255) / 256, 256>>>(xbuf, rt, xr);

    for (int i = 0; i < 2; i++) {
        run_layer(xr,
                  WO_RQ + (size_t)i * 786432,
                  WO_RO + (size_t)i * 262144,
                  WO_RU + (size_t)i * 1048576,
                  WO_RD + (size_t)i * 524288,
                  r_n1 + (size_t)i * 512, r_n2 + (size_t)i * 512,
                  NTOK_RTR, SRTR, 0, nullptr, sb, hb_);
    }

    gather_rows_k<<<(512 * DMODEL + 255) / 256, 256>>>(xr, rowsh, rowsl);
    sgemm_h3<<<pgrid(8), 256, GEMM_SMEM>>>(rowsh, rowsl, wh + WO_OUT, wl + WO_OUT, outp,
                                           nullptr, nullptr, 512, 256, 512, 0);

    knorm_k<<<1, 1024>>>(keys_r, keys_g, knr, kng);
    logits_k<<<32 * 64, 128>>>(outp, keys_r, keys_g, knr, kng, rl, gl);
    topk_k<<<16, 128>>>(rl, gl, out);
}

// round 14
// speedup vs baseline: 1.6018x; 1.1234x over previous
#include <cuda_runtime.h>
#include <cuda_fp16.h>
#include <math.h>
#include <stdint.h>

// Model constants
#define BH      8
#define HDIM    64
#define DMODEL  512
#define SENC    2048
#define SRTR    72
#define NTOK_ENC 4096
#define NTOK_RTR 4608
#define FFH     1024

// ---- fp32 scratch (float offsets) ----
#define OFF_QKV   0ull
#define OFF_H     14155776ull
#define OFF_X     23592960ull
#define OFF_XR    25952256ull
#define OFF_OUT   28311552ull
#define OFF_KNR   28442624ull
#define OFF_KNG   28443136ull
#define OFF_RL    28443648ull
#define OFF_GL    28476416ull
#define SCRATCH_FLOATS 28509184ull
__device__ float g_s[SCRATCH_FLOATS];

// ---- fp16 scratch (half offsets) ----
#define HO_XNH   0ull
#define HO_XNL   2359296ull
#define HO_ATTH  4718592ull
#define HO_ATTL  7077888ull
#define HO_ACTH  9437184ull
#define HO_ACTL  14155776ull
#define HO_ROWSH 18874368ull
#define HO_ROWSL 19136512ull
#define HO_WH    19398656ull
#define HO_WL    35258368ull
#define HO_QH    51118080ull
#define HO_QL    53477376ull
#define HO_KH    55836672ull
#define HO_KL    58195968ull
#define HO_VH    60555264ull
#define HO_VL    62914560ull
#define HO_VTH   65273856ull
#define HO_VTL   67633152ull
#define SCRATCH_HALVES 69992448ull
__device__ __half g_h[SCRATCH_HALVES];

// weight-plane sub-offsets (halves)
#define WO_EQ   0ull
#define WO_EO   3145728ull
#define WO_EU   4194304ull
#define WO_ED   8388608ull
#define WO_RQ   10485760ull
#define WO_RO   12058624ull
#define WO_RU   12582912ull
#define WO_RD   14680064ull
#define WO_OUT  15728640ull

#define NSM_SLOTS 296

// ---------------- helpers ----------------
__device__ __forceinline__ float bsum128(float v, volatile float* red) {
    int tid = threadIdx.x;
    red[tid] = v;
    for (int off = 64; off >= 1; off >>= 1) {
        __syncthreads();
        if (tid < off) red[tid] += red[tid + off];
    }
    __syncthreads();
    float r = red[0];
    __syncthreads();
    return r;
}

__device__ __forceinline__ void split_h(float v, __half& hi, __half& lo) {
    hi = __float2half_rn(v);
    lo = __float2half_rn(v - __half2float(hi));
}

__device__ __forceinline__ void mma16816(float* c, const uint32_t* a, const uint32_t* b) {
    asm volatile(
        "mma.sync.aligned.m16n8k16.row.col.f32.f16.f16.f32 "
        "{%0,%1,%2,%3}, {%4,%5,%6,%7}, {%8,%9}, {%0,%1,%2,%3};"
        : "+f"(c[0]), "+f"(c[1]), "+f"(c[2]), "+f"(c[3])
        : "r"(a[0]), "r"(a[1]), "r"(a[2]), "r"(a[3]), "r"(b[0]), "r"(b[1]));
}

__device__ __forceinline__ uint32_t sptr(const void* p) {
    return (uint32_t)__cvta_generic_to_shared(p);
}

__device__ __forceinline__ void ldsm4(uint32_t& r0, uint32_t& r1, uint32_t& r2,
                                      uint32_t& r3, uint32_t addr) {
    asm volatile("ldmatrix.sync.aligned.m8n8.x4.shared.b16 {%0,%1,%2,%3}, [%4];"
                 : "=r"(r0), "=r"(r1), "=r"(r2), "=r"(r3) : "r"(addr));
}

__device__ __forceinline__ void cpa16(uint32_t dst, const void* src) {
    asm volatile("cp.async.cg.shared.global [%0], [%1], 16;" :: "r"(dst), "l"(src));
}
__device__ __forceinline__ void cpa_commit() { asm volatile("cp.async.commit_group;"); }
__device__ __forceinline__ void cpa_wait0() { asm volatile("cp.async.wait_group 0;"); }
__device__ __forceinline__ void cpa_wait1() { asm volatile("cp.async.wait_group 1;"); }

__device__ __forceinline__ uint32_t h2u(__half2 h) { return *(uint32_t*)&h; }

// ---------------- kernels ----------------
__global__ void copy_k(const float* __restrict__ src, float* __restrict__ dst, int n) {
    int i = blockIdx.x * blockDim.x + threadIdx.x;
    if (i < n) dst[i] = src[i];
}

// transpose + split weights; gridDim.z = layer index
__global__ void wsplitT_k(const float* __restrict__ w, __half* __restrict__ hT,
                          __half* __restrict__ lT, int K, int N, int ilv) {
    __shared__ float t[32][33];
    size_t loff = (size_t)blockIdx.z * K * N;
    w += loff; hT += loff; lT += loff;
    int n0 = blockIdx.x * 32, k0 = blockIdx.y * 32;
    int tx = threadIdx.x, ty = threadIdx.y;
    for (int i = ty; i < 32; i += 8) {
        int n = n0 + tx;
        int srcn = ilv ? ((n & 1) ? (N >> 1) + (n >> 1) : (n >> 1)) : n;
        t[i][tx] = w[(size_t)(k0 + i) * N + srcn];
    }
    __syncthreads();
    for (int i = ty; i < 32; i += 8) {
        float v = t[tx][i];
        __half h, l;
        split_h(v, h, l);
        hT[(size_t)(n0 + i) * K + k0 + tx] = h;
        lT[(size_t)(n0 + i) * K + k0 + tx] = l;
    }
}

__global__ void rmsnorm_k(const float* __restrict__ x, const float* __restrict__ w,
                          __half* __restrict__ yh, __half* __restrict__ yl) {
    __shared__ float red[128];
    size_t row = (size_t)blockIdx.x * DMODEL;
    int tid = threadIdx.x;
    float ss = 0.f;
    for (int i = tid; i < DMODEL; i += 128) {
        float v = x[row + i];
        ss += v * v;
    }
    float tot = bsum128(ss, red);
    float scale = rsqrtf(tot / (float)DMODEL + 1e-6f);
    for (int i = tid; i < DMODEL; i += 128) {
        __half h, l;
        split_h(x[row + i] * scale * w[i], h, l);
        yh[row + i] = h;
        yl[row + i] = l;
    }
}

// ---- 3xFP16 split GEMM, 3-stage cp.async pipeline, persistent over tiles ----
#define STG_H 12288
#define GEMM_SMEM (3 * STG_H * 2)
__global__ __launch_bounds__(256) void sgemm_h3(const __half* __restrict__ Ah,
                                                const __half* __restrict__ Al,
                                                const __half* __restrict__ BTh,
                                                const __half* __restrict__ BTl,
                                                float* __restrict__ C,
                                                __half* __restrict__ Dh,
                                                __half* __restrict__ Dl,
                                                int M, int N, int K, int mode) {
    extern __shared__ __align__(16) __half gsm[];
    int tid = threadIdx.x;
    int lane = tid & 31, warp = tid >> 5;
    int wm = warp >> 2, wn = warp & 3;
    int grp = lane >> 2, qid = lane & 3;
    int lrow = tid >> 1, lseg = (tid & 1) * 8;
    int arow = lane & 15, acg = (lane >> 4) * 8;
    int nk = K >> 4;
    int ntN = N >> 7;
    int ntiles = (M >> 7) * ntN;

#define SA0(s) (gsm + (s) * STG_H)
#define SA1(s) (gsm + (s) * STG_H + 3072)
#define SB0(s) (gsm + (s) * STG_H + 6144)
#define SB1(s) (gsm + (s) * STG_H + 9216)
#define LOADS(s, k0)                                                                 \
    {                                                                                \
        cpa16(sptr(SA0(s) + lrow * 24 + lseg), Ah + (size_t)(bm + lrow) * K + (k0) + lseg); \
        cpa16(sptr(SA1(s) + lrow * 24 + lseg), Al + (size_t)(bm + lrow) * K + (k0) + lseg); \
        cpa16(sptr(SB0(s) + lrow * 24 + lseg), BTh + (size_t)(bn + lrow) * K + (k0) + lseg); \
        cpa16(sptr(SB1(s) + lrow * 24 + lseg), BTl + (size_t)(bn + lrow) * K + (k0) + lseg); \
        cpa_commit();                                                                \
    }

    for (int t = blockIdx.x; t < ntiles; t += gridDim.x) {
        int bm = (t / ntN) << 7;
        int bn = (t % ntN) << 7;

        float acc[4][4][4];
#pragma unroll
        for (int i = 0; i < 4; i++)
#pragma unroll
            for (int j = 0; j < 4; j++)
#pragma unroll
                for (int u = 0; u < 4; u++) acc[i][j][u] = 0.f;

        __syncthreads();
        LOADS(0, 0);
        LOADS(1, 16);

        for (int kt = 0; kt < nk; kt++) {
            int slot = kt % 3;
            if (kt + 1 < nk) cpa_wait1(); else cpa_wait0();
            __syncthreads();
            if (kt + 2 < nk) {
                int s2 = (kt + 2) % 3;
                LOADS(s2, (kt + 2) << 4);
            }

            uint32_t ah[4][4], al[4][4], bh[4][2], bl[4][2];
#pragma unroll
            for (int mt = 0; mt < 4; mt++) {
                int r = wm * 64 + mt * 16 + arow;
                ldsm4(ah[mt][0], ah[mt][1], ah[mt][2], ah[mt][3], sptr(SA0(slot) + r * 24 + acg));
                ldsm4(al[mt][0], al[mt][1], al[mt][2], al[mt][3], sptr(SA1(slot) + r * 24 + acg));
            }
#pragma unroll
            for (int ntp = 0; ntp < 2; ntp++) {
                int r = wn * 32 + ntp * 16 + arow;
                uint32_t m0, m1, m2, m3;
                ldsm4(m0, m1, m2, m3, sptr(SB0(slot) + r * 24 + acg));
                bh[2 * ntp][0] = m0; bh[2 * ntp][1] = m2;
                bh[2 * ntp + 1][0] = m1; bh[2 * ntp + 1][1] = m3;
                ldsm4(m0, m1, m2, m3, sptr(SB1(slot) + r * 24 + acg));
                bl[2 * ntp][0] = m0; bl[2 * ntp][1] = m2;
                bl[2 * ntp + 1][0] = m1; bl[2 * ntp + 1][1] = m3;
            }
#pragma unroll
            for (int mt = 0; mt < 4; mt++)
#pragma unroll
                for (int nt = 0; nt < 4; nt++) {
                    mma16816(acc[mt][nt], al[mt], bh[nt]);
                    mma16816(acc[mt][nt], ah[mt], bl[nt]);
                    mma16816(acc[mt][nt], ah[mt], bh[nt]);
                }
        }

        if (mode == 2) {
            int half_n = N >> 1;
#pragma unroll
            for (int mt = 0; mt < 4; mt++)
#pragma unroll
                for (int nt = 0; nt < 4; nt++) {
                    int r0 = bm + wm * 64 + mt * 16 + grp;
                    int j = (bn + wn * 32 + nt * 8 + 2 * qid) >> 1;
                    float a0 = acc[mt][nt][0], b0 = acc[mt][nt][1];
                    float a1 = acc[mt][nt][2], b1 = acc[mt][nt][3];
                    float g0 = (a0 / (1.0f + __expf(-a0))) * b0;
                    float g1 = (a1 / (1.0f + __expf(-a1))) * b1;
                    __half h, l;
                    split_h(g0, h, l);
                    Dh[(size_t)r0 * half_n + j] = h;
                    Dl[(size_t)r0 * half_n + j] = l;
                    split_h(g1, h, l);
                    Dh[(size_t)(r0 + 8) * half_n + j] = h;
                    Dl[(size_t)(r0 + 8) * half_n + j] = l;
                }
        } else {
#pragma unroll
            for (int mt = 0; mt < 4; mt++)
#pragma unroll
                for (int nt = 0; nt < 4; nt++) {
                    int r0 = bm + wm * 64 + mt * 16 + grp;
                    int c0 = bn + wn * 32 + nt * 8 + 2 * qid;
                    size_t i00 = (size_t)r0 * N + c0;
                    size_t i10 = (size_t)(r0 + 8) * N + c0;
                    if (mode == 1) {
                        C[i00]     += acc[mt][nt][0];
                        C[i00 + 1] += acc[mt][nt][1];
                        C[i10]     += acc[mt][nt][2];
                        C[i10 + 1] += acc[mt][nt][3];
                    } else {
                        C[i00]     = acc[mt][nt][0];
                        C[i00 + 1] = acc[mt][nt][1];
                        C[i10]     = acc[mt][nt][2];
                        C[i10 + 1] = acc[mt][nt][3];
                    }
                }
        }
    }
#undef LOADS
}

// qkv row -> q/k (RoPE) and v, hi/lo half planes [bh][SEQ][64]
__global__ void split_rope_k(const float* __restrict__ qkv,
                             __half* __restrict__ Qh, __half* __restrict__ Ql,
                             __half* __restrict__ Kh, __half* __restrict__ Kl,
                             __half* __restrict__ Vh, __half* __restrict__ Vl,
                             int SEQ) {
    int tok = blockIdx.x;
    int b = tok / SEQ, s = tok % SEQ;
    const float* row = qkv + (size_t)tok * 1536;
    int tid = threadIdx.x;
    int h = tid >> 5, i = tid & 31;
    float q1 = row[h * 64 + i], q2 = row[h * 64 + i + 32];
    float k1 = row[512 + h * 64 + i], k2 = row[512 + h * 64 + i + 32];
    float inv = powf(1e-4f, (float)i * (1.0f / 32.0f));
    float ang = (float)s * inv;
    float c = cosf(ang), sn = sinf(ang);
    size_t base = ((size_t)(b * BH + h) * SEQ + s) * 64;
    __half hh, ll;
    split_h(q1 * c + q2 * sn, hh, ll);      Qh[base + i] = hh;      Ql[base + i] = ll;
    split_h(-q1 * sn + q2 * c, hh, ll);     Qh[base + i + 32] = hh; Ql[base + i + 32] = ll;
    split_h(k1 * c + k2 * sn, hh, ll);      Kh[base + i] = hh;      Kl[base + i] = ll;
    split_h(-k1 * sn + k2 * c, hh, ll);     Kh[base + i + 32] = hh; Kl[base + i + 32] = ll;
    for (int j = tid; j < 512; j += 256) {
        int hd = j >> 6, dd = j & 63;
        split_h(row[1024 + j], hh, ll);
        size_t vi = ((size_t)(b * BH + hd) * SEQ + s) * 64 + dd;
        Vh[vi] = hh;
        Vl[vi] = ll;
    }
}

// V [bh][s][64] -> Vt [bh][64][s]
__global__ void vtrans_k(const __half* __restrict__ Vh, const __half* __restrict__ Vl,
                         __half* __restrict__ Vth, __half* __restrict__ Vtl, int SEQ) {
    __shared__ __half t[2][64][72];
    int sc = blockIdx.x * 64;
    int bh = blockIdx.y;
    int tid = threadIdx.x;
    for (int i = tid; i < 512; i += 256) {
        int r = i >> 3, c = (i & 7) * 8;
        *(uint4*)&t[0][r][c] = *(const uint4*)(Vh + ((size_t)bh * SEQ + sc + r) * 64 + c);
        *(uint4*)&t[1][r][c] = *(const uint4*)(Vl + ((size_t)bh * SEQ + sc + r) * 64 + c);
    }
    __syncthreads();
    for (int i = tid; i < 4096; i += 256) {
        int d = i >> 6, s = i & 63;
        Vth[((size_t)bh * 64 + d) * SEQ + sc + s] = t[0][s][d];
        Vtl[((size_t)bh * 64 + d) * SEQ + sc + s] = t[1][s][d];
    }
}

// ---- tensor-core flash attention, 3xFP16 split, doc-aware tile skipping ----
#define ATS 72
#define AMMA_SMEM (6 * 64 * ATS * 2 + 256)
__global__ __launch_bounds__(128) void attn_mma_k(
        const __half* __restrict__ Qh, const __half* __restrict__ Ql,
        const __half* __restrict__ Kh, const __half* __restrict__ Kl,
        const __half* __restrict__ Vth, const __half* __restrict__ Vtl,
        __half* __restrict__ Oh, __half* __restrict__ Ol,
        const int* __restrict__ doc, int SEQ) {
    extern __shared__ __half hsm[];
    __half* Qsh = hsm;
    __half* Qsl = hsm + 64 * ATS;
    __half* Ksh = hsm + 2 * 64 * ATS;
    __half* Ksl = hsm + 3 * 64 * ATS;
    __half* Vsh = hsm + 4 * 64 * ATS;
    __half* Vsl = hsm + 5 * 64 * ATS;
    int* sdoc = (int*)(hsm + 6 * 64 * ATS);

    int qb = blockIdx.x, bh = blockIdx.y;
    int b = bh >> 3, h = bh & 7;
    int tid = threadIdx.x, lane = tid & 31, warp = tid >> 5;
    int grp = lane >> 2, qid = lane & 3;
    int arow = lane & 15, acg = (lane >> 4) * 8;

    const __half* Qbh = Qh + ((size_t)bh * SEQ + qb * 64) * 64;
    const __half* Qbl = Ql + ((size_t)bh * SEQ + qb * 64) * 64;
    for (int i = tid; i < 512; i += 128) {
        int r = i >> 3, c = (i & 7) * 8;
        *(uint4*)(Qsh + r * ATS + c) = *(const uint4*)(Qbh + r * 64 + c);
        *(uint4*)(Qsl + r * ATS + c) = *(const uint4*)(Qbl + r * 64 + c);
    }
    __syncthreads();

    uint32_t qfh[4][4], qfl[4][4];
#pragma unroll
    for (int ds = 0; ds < 4; ds++) {
        ldsm4(qfh[ds][0], qfh[ds][1], qfh[ds][2], qfh[ds][3],
              sptr(Qsh + (warp * 16 + arow) * ATS + ds * 16 + acg));
        ldsm4(qfl[ds][0], qfl[ds][1], qfl[ds][2], qfl[ds][3],
              sptr(Qsl + (warp * 16 + arow) * ATS + ds * 16 + acg));
    }
    int dq0 = doc[b * SEQ + qb * 64 + warp * 16 + grp];
    int dq1 = doc[b * SEQ + qb * 64 + warp * 16 + grp + 8];

    // doc-aware skip: tile t is fully masked iff doc[t*64+63] < doc[qb*64]
    // (doc sorted ascending). First needed tile via warp ballot.
    int d0 = doc[b * SEQ + qb * 64];
    int pred = (lane <= qb) && (doc[b * SEQ + lane * 64 + 63] >= d0);
    uint32_t bm_ = __ballot_sync(0xffffffffu, pred);
    int kt_start = __ffs(bm_) - 1;   // always >=0: diagonal tile qualifies

    float o[8][4];
#pragma unroll
    for (int j = 0; j < 8; j++)
#pragma unroll
        for (int t = 0; t < 4; t++) o[j][t] = 0.f;
    float m0r = -1e30f, m1r = -1e30f, l0 = 0.f, l1 = 0.f;

    const __half* Kbh = Kh + (size_t)bh * SEQ * 64;
    const __half* Kbl = Kl + (size_t)bh * SEQ * 64;
    const __half* Vbh = Vth + (size_t)bh * 64 * SEQ;
    const __half* Vbl = Vtl + (size_t)bh * 64 * SEQ;

    for (int kt = kt_start; kt <= qb; kt++) {
        int kbase = kt * 64;
        __syncthreads();
        for (int i = tid; i < 512; i += 128) {
            int r = i >> 3, c = (i & 7) * 8;
            *(uint4*)(Ksh + r * ATS + c) = *(const uint4*)(Kbh + (size_t)(kbase + r) * 64 + c);
            *(uint4*)(Ksl + r * ATS + c) = *(const uint4*)(Kbl + (size_t)(kbase + r) * 64 + c);
            *(uint4*)(Vsh + r * ATS + c) = *(const uint4*)(Vbh + (size_t)r * SEQ + kbase + c);
            *(uint4*)(Vsl + r * ATS + c) = *(const uint4*)(Vbl + (size_t)r * SEQ + kbase + c);
        }
        if (tid < 64) sdoc[tid] = doc[b * SEQ + kbase + tid];
        __syncthreads();

        float sc[8][4];
#pragma unroll
        for (int j = 0; j < 8; j++)
#pragma unroll
            for (int t = 0; t < 4; t++) sc[j][t] = 0.f;
#pragma unroll
        for (int ds = 0; ds < 4; ds++) {
            uint32_t kfh[8][2], kfl[8][2];
#pragma unroll
            for (int np = 0; np < 4; np++) {
                uint32_t m0, m1, m2, m3;
                ldsm4(m0, m1, m2, m3, sptr(Ksh + (np * 16 + arow) * ATS + ds * 16 + acg));
                kfh[2 * np][0] = m0; kfh[2 * np][1] = m2;
                kfh[2 * np + 1][0] = m1; kfh[2 * np + 1][1] = m3;
                ldsm4(m0, m1, m2, m3, sptr(Ksl + (np * 16 + arow) * ATS + ds * 16 + acg));
                kfl[2 * np][0] = m0; kfl[2 * np][1] = m2;
                kfl[2 * np + 1][0] = m1; kfl[2 * np + 1][1] = m3;
            }
#pragma unroll
            for (int j = 0; j < 8; j++) {
                mma16816(sc[j], qfl[ds], kfh[j]);
                mma16816(sc[j], qfh[ds], kfl[j]);
                mma16816(sc[j], qfh[ds], kfh[j]);
            }
        }

#pragma unroll
        for (int j = 0; j < 8; j++) {
            int dk0 = sdoc[8 * j + 2 * qid], dk1 = sdoc[8 * j + 2 * qid + 1];
            sc[j][0] = (dk0 == dq0) ? sc[j][0] * 0.125f : -6e30f;
            sc[j][1] = (dk1 == dq0) ? sc[j][1] * 0.125f : -6e30f;
            sc[j][2] = (dk0 == dq1) ? sc[j][2] * 0.125f : -6e30f;
            sc[j][3] = (dk1 == dq1) ? sc[j][3] * 0.125f : -6e30f;
        }

        float tm0 = -1e30f, tm1 = -1e30f;
#pragma unroll
        for (int j = 0; j < 8; j++) {
            tm0 = fmaxf(tm0, fmaxf(sc[j][0], sc[j][1]));
            tm1 = fmaxf(tm1, fmaxf(sc[j][2], sc[j][3]));
        }
#pragma unroll
        for (int off = 1; off < 4; off <<= 1) {
            tm0 = fmaxf(tm0, __shfl_xor_sync(0xffffffffu, tm0, off));
            tm1 = fmaxf(tm1, __shfl_xor_sync(0xffffffffu, tm1, off));
        }
        float mn0 = fmaxf(m0r, tm0), mn1 = fmaxf(m1r, tm1);
        float r0 = __expf(m0r - mn0), r1 = __expf(m1r - mn1);

        uint32_t pfh[8][2], pfl[8][2];
        float ps0 = 0.f, ps1 = 0.f;
#pragma unroll
        for (int j = 0; j < 8; j++) {
            float p0 = __expf(sc[j][0] - mn0), p1 = __expf(sc[j][1] - mn0);
            float p2 = __expf(sc[j][2] - mn1), p3 = __expf(sc[j][3] - mn1);
            ps0 += p0 + p1; ps1 += p2 + p3;
            __half2 hA = __floats2half2_rn(p0, p1);
            __half2 hB = __floats2half2_rn(p2, p3);
            pfh[j][0] = h2u(hA);
            pfh[j][1] = h2u(hB);
            __half2 lA = __floats2half2_rn(p0 - __half2float(__low2half(hA)),
                                           p1 - __half2float(__high2half(hA)));
            __half2 lB = __floats2half2_rn(p2 - __half2float(__low2half(hB)),
                                           p3 - __half2float(__high2half(hB)));
            pfl[j][0] = h2u(lA);
            pfl[j][1] = h2u(lB);
        }
#pragma unroll
        for (int off = 1; off < 4; off <<= 1) {
            ps0 += __shfl_xor_sync(0xffffffffu, ps0, off);
            ps1 += __shfl_xor_sync(0xffffffffu, ps1, off);
        }
        l0 = l0 * r0 + ps0;
        l1 = l1 * r1 + ps1;
        m0r = mn0; m1r = mn1;
#pragma unroll
        for (int j = 0; j < 8; j++) {
            o[j][0] *= r0; o[j][1] *= r0; o[j][2] *= r1; o[j][3] *= r1;
        }

#pragma unroll
        for (int ks = 0; ks < 4; ks++) {
            uint32_t pah[4] = {pfh[2 * ks][0], pfh[2 * ks][1], pfh[2 * ks + 1][0], pfh[2 * ks + 1][1]};
            uint32_t pal[4] = {pfl[2 * ks][0], pfl[2 * ks][1], pfl[2 * ks + 1][0], pfl[2 * ks + 1][1]};
            uint32_t vfh[8][2], vfl[8][2];
#pragma unroll
            for (int np = 0; np < 4; np++) {
                uint32_t m0, m1, m2, m3;
                ldsm4(m0, m1, m2, m3, sptr(Vsh + (np * 16 + arow) * ATS + ks * 16 + acg));
                vfh[2 * np][0] = m0; vfh[2 * np][1] = m2;
                vfh[2 * np + 1][0] = m1; vfh[2 * np + 1][1] = m3;
                ldsm4(m0, m1, m2, m3, sptr(Vsl + (np * 16 + arow) * ATS + ks * 16 + acg));
                vfl[2 * np][0] = m0; vfl[2 * np][1] = m2;
                vfl[2 * np + 1][0] = m1; vfl[2 * np + 1][1] = m3;
            }
#pragma unroll
            for (int j = 0; j < 8; j++) {
                mma16816(o[j], pal, vfh[j]);
                mma16816(o[j], pah, vfl[j]);
                mma16816(o[j], pah, vfh[j]);
            }
        }
    }

    float inv0 = 1.0f / l0, inv1 = 1.0f / l1;
    int row0 = qb * 64 + warp * 16 + grp;
#pragma unroll
    for (int j = 0; j < 8; j++) {
        int col = h * 64 + 8 * j + 2 * qid;
        float v0 = o[j][0] * inv0, v1 = o[j][1] * inv0;
        __half2 hh = __floats2half2_rn(v0, v1);
        __half2 ll = __floats2half2_rn(v0 - __half2float(__low2half(hh)),
                                       v1 - __half2float(__high2half(hh)));
        size_t i0 = (size_t)(b * SEQ + row0) * DMODEL + col;
        *(__half2*)(Oh + i0) = hh;
        *(__half2*)(Ol + i0) = ll;
        float v2 = o[j][2] * inv1, v3 = o[j][3] * inv1;
        hh = __floats2half2_rn(v2, v3);
        ll = __floats2half2_rn(v2 - __half2float(__low2half(hh)),
                               v3 - __half2float(__high2half(hh)));
        size_t i1 = (size_t)(b * SEQ + row0 + 8) * DMODEL + col;
        *(__half2*)(Oh + i1) = hh;
        *(__half2*)(Ol + i1) = ll;
    }
}

// ---- router attention: one block per (seq, head), full 72x72 in smem ----
#define ATR_SMEM ((72 * 65 * 3 + 72 * 73 + 72) * 4)
__global__ __launch_bounds__(128) void attn_r2(
        const __half* __restrict__ Qh, const __half* __restrict__ Ql,
        const __half* __restrict__ Kh, const __half* __restrict__ Kl,
        const __half* __restrict__ Vh, const __half* __restrict__ Vl,
        __half* __restrict__ Oh, __half* __restrict__ Ol) {
    extern __shared__ float rs[];
    float* Qs = rs;
    float* Ks = rs + 72 * 65;
    float* Vs = rs + 2 * 72 * 65;
    float* Ps = rs + 3 * 72 * 65;
    float* den = rs + 3 * 72 * 65 + 72 * 73;

    int bh = blockIdx.x;
    int tid = threadIdx.x;

    for (int i = tid; i < 72 * 64; i += 128) {
        int r = i >> 6, d = i & 63;
        size_t base = ((size_t)bh * SRTR + r) * 64 + d;
        Qs[r * 65 + d] = __half2float(Qh[base]) + __half2float(Ql[base]);
        Ks[r * 65 + d] = __half2float(Kh[base]) + __half2float(Kl[base]);
        Vs[r * 65 + d] = __half2float(Vh[base]) + __half2float(Vl[base]);
    }
    __syncthreads();

    if (tid < 72) {
        int q = tid;
        float m = -1e30f;
        for (int k = 0; k < 72; k++) {
            float s = 0.f;
#pragma unroll 16
            for (int d = 0; d < 64; d++)
                s += Qs[q * 65 + d] * Ks[k * 65 + d];
            s *= 0.125f;
            Ps[q * 73 + k] = s;
            m = fmaxf(m, s);
        }
        float l = 0.f;
        for (int k = 0; k < 72; k++) {
            float e = __expf(Ps[q * 73 + k] - m);
            Ps[q * 73 + k] = e;
            l += e;
        }
        den[q] = 1.0f / l;
    }
    __syncthreads();

    int b = bh >> 3, h = bh & 7;
    for (int i = tid; i < 72 * 64; i += 128) {
        int q = i >> 6, d = i & 63;
        float acc = 0.f;
#pragma unroll 8
        for (int k = 0; k < 72; k++)
            acc += Ps[q * 73 + k] * Vs[k * 65 + d];
        float o = acc * den[q];
        size_t idx = (size_t)(b * SRTR + q) * DMODEL + h * 64 + d;
        __half hh, ll;
        split_h(o, hh, ll);
        Oh[idx] = hh;
        Ol[idx] = ll;
    }
}

__global__ void build_xr_k(const float* __restrict__ x, const float* __restrict__ rt,
                           float* __restrict__ xr) {
    int i = blockIdx.x * blockDim.x + threadIdx.x;
    if (i >= NTOK_RTR * DMODEL) return;
    int blk = i / (SRTR * DMODEL);
    int rem = i % (SRTR * DMODEL);
    int t = rem / DMODEL, dd = rem % DMODEL;
    xr[i] = (t < 64) ? x[(size_t)(blk * 64 + t) * DMODEL + dd]
                     : rt[(size_t)(t - 64) * DMODEL + dd];
}

__global__ void gather_rows_k(const float* __restrict__ xr, __half* __restrict__ rh,
                              __half* __restrict__ rl) {
    int i = blockIdx.x * blockDim.x + threadIdx.x;
    if (i >= 512 * DMODEL) return;
    int row = i / DMODEL, dd = i % DMODEL;
    int blk = row >> 3, r = row & 7;
    __half h, l;
    split_h(xr[((size_t)blk * SRTR + 64 + r) * DMODEL + dd], h, l);
    rh[i] = h;
    rl[i] = l;
}

__global__ void knorm_k(const float* __restrict__ kr, const float* __restrict__ kg,
                        float* __restrict__ knr, float* __restrict__ kng) {
    int tid = threadIdx.x;
    int which = tid >> 9;
    int idx = tid & 511;
    int g = idx >> 4, e = idx & 15;
    const float* src = which ? kg : kr;
    const float* col = src + (size_t)g * 128 * 16 + e;
    float s = 0.f;
    for (int d = 0; d < 128; d++) { float v = col[d * 16]; s += v * v; }
    float n = fmaxf(sqrtf(s), 1e-12f);
    if (which) kng[idx] = n; else knr[idx] = n;
}

__global__ void logits_k(const float* __restrict__ outp,
                         const float* __restrict__ keys_r, const float* __restrict__ keys_g,
                         const float* __restrict__ knr, const float* __restrict__ kng,
                         float* __restrict__ rl, float* __restrict__ gl) {
    __shared__ float vr[128], vg[128], red[128];
    int g = blockIdx.x >> 6, bb = blockIdx.x & 63;
    int b = bb >> 5, l = bb & 31;
    int srcl = (l + 31) & 31;
    int r = g >> 2;
    const float* row = outp + (size_t)((b * 32 + srcl) * 8 + r) * 256;
    int tid = threadIdx.x;
    vr[tid] = row[tid];
    vg[tid] = row[128 + tid];
    float nr2 = bsum128(vr[tid] * vr[tid], red);
    float ng2 = bsum128(vg[tid] * vg[tid], red);
    float inr = 1.0f / fmaxf(sqrtf(nr2), 1e-12f);
    float ing = 1.0f / fmaxf(sqrtf(ng2), 1e-12f);
    if (tid < 16) {
        int e = tid;
        const float* kr = keys_r + (size_t)g * 128 * 16 + e;
        const float* kg = keys_g + (size_t)g * 128 * 16 + e;
        float dr = 0.f, dg = 0.f;
        for (int dd = 0; dd < 128; dd++) {
            dr += vr[dd] * kr[dd * 16];
            dg += vg[dd] * kg[dd * 16];
        }
        rl[(size_t)(g * 64 + bb) * 16 + e] = dr * inr / knr[g * 16 + e];
        gl[(size_t)(g * 64 + bb) * 16 + e] = dg * ing / kng[g * 16 + e];
    }
}

__global__ void topk_k(const float* __restrict__ rl, const float* __restrict__ gl,
                       float* __restrict__ out) {
    int t = blockIdx.x * blockDim.x + threadIdx.x;
    if (t >= 2048) return;
    const float* r = rl + (size_t)t * 16;
    const float* g = gl + (size_t)t * 16;
    int i1 = 0; float v1 = r[0];
    for (int e = 1; e < 16; e++) if (r[e] > v1) { v1 = r[e]; i1 = e; }
    int i2 = -1; float v2 = -1e30f;
    for (int e = 0; e < 16; e++) {
        if (e == i1) continue;
        if (r[e] > v2) { v2 = r[e]; i2 = e; }
    }
    out[(size_t)t * 2 + 0] = v1;
    out[(size_t)t * 2 + 1] = v2;
    out[4096 + (size_t)t * 2 + 0] = g[i1];
    out[4096 + (size_t)t * 2 + 1] = g[i2];
}

// ---------------- host orchestration ----------------
static inline int pgrid(int tiles) { return tiles < NSM_SLOTS ? tiles : NSM_SLOTS; }

static void run_layer(float* cur, size_t qkvo, size_t oo, size_t upo, size_t dno,
                      const float* n1, const float* n2,
                      int ntok, int SEQ, int enc, const int* doc,
                      float* sb, __half* hb_) {
    float*  qkv  = sb + OFF_QKV;
    float*  hbuf = sb + OFF_H;
    __half* xnh = hb_ + HO_XNH; __half* xnl = hb_ + HO_XNL;
    __half* ath = hb_ + HO_ATTH; __half* atl = hb_ + HO_ATTL;
    __half* ach = hb_ + HO_ACTH; __half* acl = hb_ + HO_ACTL;
    __half* wh = hb_ + HO_WH;  __half* wl = hb_ + HO_WL;
    __half* qh_ = hb_ + HO_QH; __half* ql_ = hb_ + HO_QL;
    __half* kh_ = hb_ + HO_KH; __half* kl_ = hb_ + HO_KL;
    __half* vh_ = hb_ + HO_VH; __half* vl_ = hb_ + HO_VL;
    __half* vth_ = hb_ + HO_VTH; __half* vtl_ = hb_ + HO_VTL;
    int bh_total = (ntok / SEQ) * BH;
    int mt = ntok / 128;

    rmsnorm_k<<<ntok, 128>>>(cur, n1, xnh, xnl);
    sgemm_h3<<<pgrid(12 * mt), 256, GEMM_SMEM>>>(xnh, xnl, wh + qkvo, wl + qkvo, qkv,
                                                 nullptr, nullptr, ntok, 1536, 512, 0);
    split_rope_k<<<ntok, 256>>>(qkv, qh_, ql_, kh_, kl_, vh_, vl_, SEQ);
    if (enc) {
        vtrans_k<<<dim3(SEQ / 64, bh_total), 256>>>(vh_, vl_, vth_, vtl_, SEQ);
        attn_mma_k<<<dim3(SEQ / 64, bh_total), 128, AMMA_SMEM>>>(
            qh_, ql_, kh_, kl_, vth_, vtl_, ath, atl, doc, SEQ);
    } else {
        attn_r2<<<bh_total, 128, ATR_SMEM>>>(qh_, ql_, kh_, kl_, vh_, vl_, ath, atl);
    }
    sgemm_h3<<<pgrid(4 * mt), 256, GEMM_SMEM>>>(ath, atl, wh + oo, wl + oo, cur,
                                                nullptr, nullptr, ntok, 512, 512, 1);
    rmsnorm_k<<<ntok, 128>>>(cur, n2, xnh, xnl);
    sgemm_h3<<<pgrid(16 * mt), 256, GEMM_SMEM>>>(xnh, xnl, wh + upo, wl + upo, hbuf,
                                                 ach, acl, ntok, 2048, 512, 2);
    sgemm_h3<<<pgrid(4 * mt), 256, GEMM_SMEM>>>(ach, acl, wh + dno, wl + dno, cur,
                                                nullptr, nullptr, ntok, 512, 1024, 1);
}

extern "C" void kernel_launch(void* const* d_in, const int* in_sizes, int n_in,
                              void* d_out, int out_size) {
    const float* x_in   = (const float*)d_in[0];
    const int*   doc    = (const int*)d_in[1];
    const float* rt     = (const float*)d_in[2];
    const float* out_w  = (const float*)d_in[3];
    const float* keys_r = (const float*)d_in[4];
    const float* keys_g = (const float*)d_in[5];
    const float* e_qkv  = (const float*)d_in[6];
    const float* e_o    = (const float*)d_in[7];
    const float* e_up   = (const float*)d_in[8];
    const float* e_dn   = (const float*)d_in[9];
    const float* e_n1   = (const float*)d_in[10];
    const float* e_n2   = (const float*)d_in[11];
    const float* r_qkv  = (const float*)d_in[12];
    const float* r_o    = (const float*)d_in[13];
    const float* r_up   = (const float*)d_in[14];
    const float* r_dn   = (const float*)d_in[15];
    const float* r_n1   = (const float*)d_in[16];
    const float* r_n2   = (const float*)d_in[17];
    float* out = (float*)d_out;

    static int attr_set = 0;
    if (!attr_set) {
        cudaFuncSetAttribute(attn_mma_k, cudaFuncAttributeMaxDynamicSharedMemorySize, AMMA_SMEM);
        cudaFuncSetAttribute(sgemm_h3, cudaFuncAttributeMaxDynamicSharedMemorySize, GEMM_SMEM);
        cudaFuncSetAttribute(attn_r2, cudaFuncAttributeMaxDynamicSharedMemorySize, ATR_SMEM);
        attr_set = 1;
    }

    float* sb;
    cudaGetSymbolAddress((void**)&sb, g_s);
    __half* hb_;
    cudaGetSymbolAddress((void**)&hb_, g_h);

    float* xbuf = sb + OFF_X;
    float* xr   = sb + OFF_XR;
    float* outp = sb + OFF_OUT;
    float* knr  = sb + OFF_KNR;
    float* kng  = sb + OFF_KNG;
    float* rl   = sb + OFF_RL;
    float* gl   = sb + OFF_GL;
    __half* wh = hb_ + HO_WH;
    __half* wl = hb_ + HO_WL;
    __half* rowsh = hb_ + HO_ROWSH;
    __half* rowsl = hb_ + HO_ROWSL;

    // pre-split all weights (batched over layers via grid.z)
    wsplitT_k<<<dim3(1536 / 32, 512 / 32, 4), dim3(32, 8)>>>(e_qkv, wh + WO_EQ, wl + WO_EQ, 512, 1536, 0);
    wsplitT_k<<<dim3(512 / 32, 512 / 32, 4), dim3(32, 8)>>>(e_o, wh + WO_EO, wl + WO_EO, 512, 512, 0);
    wsplitT_k<<<dim3(2048 / 32, 512 / 32, 4), dim3(32, 8)>>>(e_up, wh + WO_EU, wl + WO_EU, 512, 2048, 1);
    wsplitT_k<<<dim3(512 / 32, 1024 / 32, 4), dim3(32, 8)>>>(e_dn, wh + WO_ED, wl + WO_ED, 1024, 512, 0);
    wsplitT_k<<<dim3(1536 / 32, 512 / 32, 2), dim3(32, 8)>>>(r_qkv, wh + WO_RQ, wl + WO_RQ, 512, 1536, 0);
    wsplitT_k<<<dim3(512 / 32, 512 / 32, 2), dim3(32, 8)>>>(r_o, wh + WO_RO, wl + WO_RO, 512, 512, 0);
    wsplitT_k<<<dim3(2048 / 32, 512 / 32, 2), dim3(32, 8)>>>(r_up, wh + WO_RU, wl + WO_RU, 512, 2048, 1);
    wsplitT_k<<<dim3(512 / 32, 1024 / 32, 2), dim3(32, 8)>>>(r_dn, wh + WO_RD, wl + WO_RD, 1024, 512, 0);
    wsplitT_k<<<dim3(256 / 32, 512 / 32, 1), dim3(32, 8)>>>(out_w, wh + WO_OUT, wl + WO_OUT, 512, 256, 0);

    copy_k<<<(NTOK_ENC * DMODEL + 255) / 256, 256>>>(x_in, xbuf, NTOK_ENC * DMODEL);

    for (int i = 0; i < 4; i++) {
        run_layer(xbuf,
                  WO_EQ + (size_t)i * 786432,
                  WO_EO + (size_t)i * 262144,
                  WO_EU + (size_t)i * 1048576,
                  WO_ED + (size_t)i * 524288,
                  e_n1 + (size_t)i * 512, e_n2 + (size_t)i * 512,
                  NTOK_ENC, SENC, 1, doc, sb, hb_);
    }

    build_xr_k<<<(NTOK_RTR * DMODEL + 255) / 256, 256>>>(xbuf, rt, xr);

    for (int i = 0; i < 2; i++) {
        run_layer(xr,
                  WO_RQ + (size_t)i * 786432,
                  WO_RO + (size_t)i * 262144,
                  WO_RU + (size_t)i * 1048576,
                  WO_RD + (size_t)i * 524288,
                  r_n1 + (size_t)i * 512, r_n2 + (size_t)i * 512,
                  NTOK_RTR, SRTR, 0, nullptr, sb, hb_);
    }

    gather_rows_k<<<(512 * DMODEL + 255) / 256, 256>>>(xr, rowsh, rowsl);
    sgemm_h3<<<pgrid(8), 256, GEMM_SMEM>>>(rowsh, rowsl, wh + WO_OUT, wl + WO_OUT, outp,
                                           nullptr, nullptr, 512, 256, 512, 0);

    knorm_k<<<1, 1024>>>(keys_r, keys_g, knr, kng);
    logits_k<<<32 * 64, 128>>>(outp, keys_r, keys_g, knr, kng, rl, gl);
    topk_k<<<16, 128>>>(rl, gl, out);
}

// round 15
// speedup vs baseline: 1.6282x; 1.0165x over previous
#include <cuda_runtime.h>
#include <cuda_fp16.h>
#include <math.h>
#include <stdint.h>

// Model constants
#define BH      8
#define HDIM    64
#define DMODEL  512
#define SENC    2048
#define SRTR    72
#define NTOK_ENC 4096
#define NTOK_RTR 4608
#define FFH     1024

// ---- fp32 scratch (float offsets) ----
#define OFF_QKV   0ull
#define OFF_H     14155776ull
#define OFF_X     23592960ull
#define OFF_XR    25952256ull
#define OFF_OUT   28311552ull
#define OFF_KNR   28442624ull
#define OFF_KNG   28443136ull
#define OFF_RL    28443648ull
#define OFF_GL    28476416ull
#define SCRATCH_FLOATS 28509184ull
__device__ float g_s[SCRATCH_FLOATS];

// ---- fp16 scratch (half offsets) ----
#define HO_XNH   0ull
#define HO_XNL   2359296ull
#define HO_ATTH  4718592ull
#define HO_ATTL  7077888ull
#define HO_ACTH  9437184ull
#define HO_ACTL  14155776ull
#define HO_ROWSH 18874368ull
#define HO_ROWSL 19136512ull
#define HO_WH    19398656ull
#define HO_WL    35258368ull
#define HO_QH    51118080ull
#define HO_QL    53477376ull
#define HO_KH    55836672ull
#define HO_KL    58195968ull
#define HO_VH    60555264ull
#define HO_VL    62914560ull
#define HO_VTH   65273856ull
#define HO_VTL   67633152ull
#define SCRATCH_HALVES 69992448ull
__device__ __half g_h[SCRATCH_HALVES];

// weight-plane sub-offsets (halves)
#define WO_EQ   0ull
#define WO_EO   3145728ull
#define WO_EU   4194304ull
#define WO_ED   8388608ull
#define WO_RQ   10485760ull
#define WO_RO   12058624ull
#define WO_RU   12582912ull
#define WO_RD   14680064ull
#define WO_OUT  15728640ull

#define NSM_SLOTS 296

// ---------------- helpers ----------------
__device__ __forceinline__ float bsum128(float v, volatile float* red) {
    int tid = threadIdx.x;
    red[tid] = v;
    for (int off = 64; off >= 1; off >>= 1) {
        __syncthreads();
        if (tid < off) red[tid] += red[tid + off];
    }
    __syncthreads();
    float r = red[0];
    __syncthreads();
    return r;
}

__device__ __forceinline__ void split_h(float v, __half& hi, __half& lo) {
    hi = __float2half_rn(v);
    lo = __float2half_rn(v - __half2float(hi));
}

// pack two values into hi-plane half2 + lo-plane half2
__device__ __forceinline__ void split_h2(float a, float b, __half2& hi2, __half2& lo2) {
    hi2 = __floats2half2_rn(a, b);
    lo2 = __floats2half2_rn(a - __half2float(__low2half(hi2)),
                            b - __half2float(__high2half(hi2)));
}

__device__ __forceinline__ void mma16816(float* c, const uint32_t* a, const uint32_t* b) {
    asm volatile(
        "mma.sync.aligned.m16n8k16.row.col.f32.f16.f16.f32 "
        "{%0,%1,%2,%3}, {%4,%5,%6,%7}, {%8,%9}, {%0,%1,%2,%3};"
        : "+f"(c[0]), "+f"(c[1]), "+f"(c[2]), "+f"(c[3])
        : "r"(a[0]), "r"(a[1]), "r"(a[2]), "r"(a[3]), "r"(b[0]), "r"(b[1]));
}

__device__ __forceinline__ uint32_t sptr(const void* p) {
    return (uint32_t)__cvta_generic_to_shared(p);
}

__device__ __forceinline__ void ldsm4(uint32_t& r0, uint32_t& r1, uint32_t& r2,
                                      uint32_t& r3, uint32_t addr) {
    asm volatile("ldmatrix.sync.aligned.m8n8.x4.shared.b16 {%0,%1,%2,%3}, [%4];"
                 : "=r"(r0), "=r"(r1), "=r"(r2), "=r"(r3) : "r"(addr));
}

__device__ __forceinline__ void cpa16(uint32_t dst, const void* src) {
    asm volatile("cp.async.cg.shared.global [%0], [%1], 16;" :: "r"(dst), "l"(src));
}
__device__ __forceinline__ void cpa_commit() { asm volatile("cp.async.commit_group;"); }
__device__ __forceinline__ void cpa_wait0() { asm volatile("cp.async.wait_group 0;"); }
__device__ __forceinline__ void cpa_wait1() { asm volatile("cp.async.wait_group 1;"); }
__device__ __forceinline__ void cpa_wait2() { asm volatile("cp.async.wait_group 2;"); }

__device__ __forceinline__ uint32_t h2u(__half2 h) { return *(uint32_t*)&h; }

// ---------------- kernels ----------------
__global__ void copy_k(const float* __restrict__ src, float* __restrict__ dst, int n) {
    int i = blockIdx.x * blockDim.x + threadIdx.x;
    if (i < n) dst[i] = src[i];
}

// transpose + split weights; gridDim.z = layer index
__global__ void wsplitT_k(const float* __restrict__ w, __half* __restrict__ hT,
                          __half* __restrict__ lT, int K, int N, int ilv) {
    __shared__ float t[32][33];
    size_t loff = (size_t)blockIdx.z * K * N;
    w += loff; hT += loff; lT += loff;
    int n0 = blockIdx.x * 32, k0 = blockIdx.y * 32;
    int tx = threadIdx.x, ty = threadIdx.y;
    for (int i = ty; i < 32; i += 8) {
        int n = n0 + tx;
        int srcn = ilv ? ((n & 1) ? (N >> 1) + (n >> 1) : (n >> 1)) : n;
        t[i][tx] = w[(size_t)(k0 + i) * N + srcn];
    }
    __syncthreads();
    for (int i = ty; i < 32; i += 8) {
        float v = t[tx][i];
        __half h, l;
        split_h(v, h, l);
        hT[(size_t)(n0 + i) * K + k0 + tx] = h;
        lT[(size_t)(n0 + i) * K + k0 + tx] = l;
    }
}

__global__ void rmsnorm_k(const float* __restrict__ x, const float* __restrict__ w,
                          __half* __restrict__ yh, __half* __restrict__ yl) {
    __shared__ float red[128];
    size_t row = (size_t)blockIdx.x * DMODEL;
    int tid = threadIdx.x;
    float ss = 0.f;
    for (int i = tid; i < DMODEL; i += 128) {
        float v = x[row + i];
        ss += v * v;
    }
    float tot = bsum128(ss, red);
    float scale = rsqrtf(tot / (float)DMODEL + 1e-6f);
    for (int i = tid; i < DMODEL; i += 128) {
        __half h, l;
        split_h(x[row + i] * scale * w[i], h, l);
        yh[row + i] = h;
        yl[row + i] = l;
    }
}

// ---- 3xFP16 split GEMM, 4-stage cp.async pipeline, persistent over tiles ----
#define STG_H 12288
#define GEMM_SMEM (4 * STG_H * 2)
__global__ __launch_bounds__(256) void sgemm_h3(const __half* __restrict__ Ah,
                                                const __half* __restrict__ Al,
                                                const __half* __restrict__ BTh,
                                                const __half* __restrict__ BTl,
                                                float* __restrict__ C,
                                                __half* __restrict__ Dh,
                                                __half* __restrict__ Dl,
                                                int M, int N, int K, int mode) {
    extern __shared__ __align__(16) __half gsm[];
    int tid = threadIdx.x;
    int lane = tid & 31, warp = tid >> 5;
    int wm = warp >> 2, wn = warp & 3;
    int grp = lane >> 2, qid = lane & 3;
    int lrow = tid >> 1, lseg = (tid & 1) * 8;
    int arow = lane & 15, acg = (lane >> 4) * 8;
    int nk = K >> 4;
    int ntN = N >> 7;
    int ntiles = (M >> 7) * ntN;

#define SA0(s) (gsm + (s) * STG_H)
#define SA1(s) (gsm + (s) * STG_H + 3072)
#define SB0(s) (gsm + (s) * STG_H + 6144)
#define SB1(s) (gsm + (s) * STG_H + 9216)
#define LOADS(s, k0)                                                                 \
    {                                                                                \
        cpa16(sptr(SA0(s) + lrow * 24 + lseg), Ah + (size_t)(bm + lrow) * K + (k0) + lseg); \
        cpa16(sptr(SA1(s) + lrow * 24 + lseg), Al + (size_t)(bm + lrow) * K + (k0) + lseg); \
        cpa16(sptr(SB0(s) + lrow * 24 + lseg), BTh + (size_t)(bn + lrow) * K + (k0) + lseg); \
        cpa16(sptr(SB1(s) + lrow * 24 + lseg), BTl + (size_t)(bn + lrow) * K + (k0) + lseg); \
        cpa_commit();                                                                \
    }

    for (int t = blockIdx.x; t < ntiles; t += gridDim.x) {
        int bm = (t / ntN) << 7;
        int bn = (t % ntN) << 7;

        float acc[4][4][4];
#pragma unroll
        for (int i = 0; i < 4; i++)
#pragma unroll
            for (int j = 0; j < 4; j++)
#pragma unroll
                for (int u = 0; u < 4; u++) acc[i][j][u] = 0.f;

        __syncthreads();        // all warps done with previous tile's smem
        LOADS(0, 0);
        LOADS(1, 16);
        LOADS(2, 32);           // nk >= 32 for all shapes here

        for (int kt = 0; kt < nk; kt++) {
            int slot = kt & 3;
            if (kt + 2 < nk) cpa_wait2();
            else if (kt + 1 < nk) cpa_wait1();
            else cpa_wait0();
            __syncthreads();
            if (kt + 3 < nk) {
                int s3 = (kt + 3) & 3;
                LOADS(s3, (kt + 3) << 4);
            }

            uint32_t ah[4][4], al[4][4], bh[4][2], bl[4][2];
#pragma unroll
            for (int mt = 0; mt < 4; mt++) {
                int r = wm * 64 + mt * 16 + arow;
                ldsm4(ah[mt][0], ah[mt][1], ah[mt][2], ah[mt][3], sptr(SA0(slot) + r * 24 + acg));
                ldsm4(al[mt][0], al[mt][1], al[mt][2], al[mt][3], sptr(SA1(slot) + r * 24 + acg));
            }
#pragma unroll
            for (int ntp = 0; ntp < 2; ntp++) {
                int r = wn * 32 + ntp * 16 + arow;
                uint32_t m0, m1, m2, m3;
                ldsm4(m0, m1, m2, m3, sptr(SB0(slot) + r * 24 + acg));
                bh[2 * ntp][0] = m0; bh[2 * ntp][1] = m2;
                bh[2 * ntp + 1][0] = m1; bh[2 * ntp + 1][1] = m3;
                ldsm4(m0, m1, m2, m3, sptr(SB1(slot) + r * 24 + acg));
                bl[2 * ntp][0] = m0; bl[2 * ntp][1] = m2;
                bl[2 * ntp + 1][0] = m1; bl[2 * ntp + 1][1] = m3;
            }
#pragma unroll
            for (int mt = 0; mt < 4; mt++)
#pragma unroll
                for (int nt = 0; nt < 4; nt++) {
                    mma16816(acc[mt][nt], al[mt], bh[nt]);
                    mma16816(acc[mt][nt], ah[mt], bl[nt]);
                    mma16816(acc[mt][nt], ah[mt], bh[nt]);
                }
        }

        if (mode == 2) {
            int half_n = N >> 1;
#pragma unroll
            for (int mt = 0; mt < 4; mt++)
#pragma unroll
                for (int nt = 0; nt < 4; nt++) {
                    int r0 = bm + wm * 64 + mt * 16 + grp;
                    int j = (bn + wn * 32 + nt * 8 + 2 * qid) >> 1;
                    float a0 = acc[mt][nt][0], b0 = acc[mt][nt][1];
                    float a1 = acc[mt][nt][2], b1 = acc[mt][nt][3];
                    float g0 = (a0 / (1.0f + __expf(-a0))) * b0;
                    float g1 = (a1 / (1.0f + __expf(-a1))) * b1;
                    __half h, l;
                    split_h(g0, h, l);
                    Dh[(size_t)r0 * half_n + j] = h;
                    Dl[(size_t)r0 * half_n + j] = l;
                    split_h(g1, h, l);
                    Dh[(size_t)(r0 + 8) * half_n + j] = h;
                    Dl[(size_t)(r0 + 8) * half_n + j] = l;
                }
        } else {
#pragma unroll
            for (int mt = 0; mt < 4; mt++)
#pragma unroll
                for (int nt = 0; nt < 4; nt++) {
                    int r0 = bm + wm * 64 + mt * 16 + grp;
                    int c0 = bn + wn * 32 + nt * 8 + 2 * qid;
                    size_t i00 = (size_t)r0 * N + c0;
                    size_t i10 = (size_t)(r0 + 8) * N + c0;
                    if (mode == 1) {
                        C[i00]     += acc[mt][nt][0];
                        C[i00 + 1] += acc[mt][nt][1];
                        C[i10]     += acc[mt][nt][2];
                        C[i10 + 1] += acc[mt][nt][3];
                    } else {
                        C[i00]     = acc[mt][nt][0];
                        C[i00 + 1] = acc[mt][nt][1];
                        C[i10]     = acc[mt][nt][2];
                        C[i10 + 1] = acc[mt][nt][3];
                    }
                }
        }
    }
#undef LOADS
}

// qkv row -> q/k (RoPE) and v, hi/lo half planes [bh][SEQ][64].
// 128 threads; each owns a PAIR of rotation indices -> all stores are half2.
__global__ void split_rope_k(const float* __restrict__ qkv,
                             __half* __restrict__ Qh, __half* __restrict__ Ql,
                             __half* __restrict__ Kh, __half* __restrict__ Kl,
                             __half* __restrict__ Vh, __half* __restrict__ Vl,
                             int SEQ) {
    int tok = blockIdx.x;
    int b = tok / SEQ, s = tok % SEQ;
    const float* row = qkv + (size_t)tok * 1536;
    int tid = threadIdx.x;                 // 0..127
    int h = tid >> 4, p = (tid & 15) * 2;  // head, even rotation index
    float q1a = row[h * 64 + p],      q1b = row[h * 64 + p + 1];
    float q2a = row[h * 64 + p + 32], q2b = row[h * 64 + p + 33];
    float k1a = row[512 + h * 64 + p],      k1b = row[512 + h * 64 + p + 1];
    float k2a = row[512 + h * 64 + p + 32], k2b = row[512 + h * 64 + p + 33];
    float inva = powf(1e-4f, (float)p * (1.0f / 32.0f));
    float invb = powf(1e-4f, (float)(p + 1) * (1.0f / 32.0f));
    float ca = cosf((float)s * inva), sa = sinf((float)s * inva);
    float cb = cosf((float)s * invb), sb2 = sinf((float)s * invb);
    size_t base = ((size_t)(b * BH + h) * SEQ + s) * 64;
    __half2 hi2, lo2;
    split_h2(q1a * ca + q2a * sa, q1b * cb + q2b * sb2, hi2, lo2);
    *(__half2*)(Qh + base + p) = hi2;       *(__half2*)(Ql + base + p) = lo2;
    split_h2(-q1a * sa + q2a * ca, -q1b * sb2 + q2b * cb, hi2, lo2);
    *(__half2*)(Qh + base + p + 32) = hi2;  *(__half2*)(Ql + base + p + 32) = lo2;
    split_h2(k1a * ca + k2a * sa, k1b * cb + k2b * sb2, hi2, lo2);
    *(__half2*)(Kh + base + p) = hi2;       *(__half2*)(Kl + base + p) = lo2;
    split_h2(-k1a * sa + k2a * ca, -k1b * sb2 + k2b * cb, hi2, lo2);
    *(__half2*)(Kh + base + p + 32) = hi2;  *(__half2*)(Kl + base + p + 32) = lo2;
    for (int j = tid; j < 256; j += 128) {
        int e = 2 * j;
        int hd = e >> 6, dd = e & 63;
        float va = row[1024 + e], vb = row[1024 + e + 1];
        split_h2(va, vb, hi2, lo2);
        size_t vi = ((size_t)(b * BH + hd) * SEQ + s) * 64 + dd;
        *(__half2*)(Vh + vi) = hi2;
        *(__half2*)(Vl + vi) = lo2;
    }
}

// V [bh][s][64] -> Vt [bh][64][s]
__global__ void vtrans_k(const __half* __restrict__ Vh, const __half* __restrict__ Vl,
                         __half* __restrict__ Vth, __half* __restrict__ Vtl, int SEQ) {
    __shared__ __half t[2][64][72];
    int sc = blockIdx.x * 64;
    int bh = blockIdx.y;
    int tid = threadIdx.x;
    for (int i = tid; i < 512; i += 256) {
        int r = i >> 3, c = (i & 7) * 8;
        *(uint4*)&t[0][r][c] = *(const uint4*)(Vh + ((size_t)bh * SEQ + sc + r) * 64 + c);
        *(uint4*)&t[1][r][c] = *(const uint4*)(Vl + ((size_t)bh * SEQ + sc + r) * 64 + c);
    }
    __syncthreads();
    for (int i = tid; i < 4096; i += 256) {
        int d = i >> 6, s = i & 63;
        Vth[((size_t)bh * 64 + d) * SEQ + sc + s] = t[0][s][d];
        Vtl[((size_t)bh * 64 + d) * SEQ + sc + s] = t[1][s][d];
    }
}

// ---- tensor-core flash attention, 3xFP16 split, doc-aware tile skipping ----
#define ATS 72
#define AMMA_SMEM (6 * 64 * ATS * 2 + 256)
__global__ __launch_bounds__(128) void attn_mma_k(
        const __half* __restrict__ Qh, const __half* __restrict__ Ql,
        const __half* __restrict__ Kh, const __half* __restrict__ Kl,
        const __half* __restrict__ Vth, const __half* __restrict__ Vtl,
        __half* __restrict__ Oh, __half* __restrict__ Ol,
        const int* __restrict__ doc, int SEQ) {
    extern __shared__ __half hsm[];
    __half* Qsh = hsm;
    __half* Qsl = hsm + 64 * ATS;
    __half* Ksh = hsm + 2 * 64 * ATS;
    __half* Ksl = hsm + 3 * 64 * ATS;
    __half* Vsh = hsm + 4 * 64 * ATS;
    __half* Vsl = hsm + 5 * 64 * ATS;
    int* sdoc = (int*)(hsm + 6 * 64 * ATS);

    int qb = blockIdx.x, bh = blockIdx.y;
    int b = bh >> 3, h = bh & 7;
    int tid = threadIdx.x, lane = tid & 31, warp = tid >> 5;
    int grp = lane >> 2, qid = lane & 3;
    int arow = lane & 15, acg = (lane >> 4) * 8;

    const __half* Qbh = Qh + ((size_t)bh * SEQ + qb * 64) * 64;
    const __half* Qbl = Ql + ((size_t)bh * SEQ + qb * 64) * 64;
    for (int i = tid; i < 512; i += 128) {
        int r = i >> 3, c = (i & 7) * 8;
        *(uint4*)(Qsh + r * ATS + c) = *(const uint4*)(Qbh + r * 64 + c);
        *(uint4*)(Qsl + r * ATS + c) = *(const uint4*)(Qbl + r * 64 + c);
    }
    __syncthreads();

    uint32_t qfh[4][4], qfl[4][4];
#pragma unroll
    for (int ds = 0; ds < 4; ds++) {
        ldsm4(qfh[ds][0], qfh[ds][1], qfh[ds][2], qfh[ds][3],
              sptr(Qsh + (warp * 16 + arow) * ATS + ds * 16 + acg));
        ldsm4(qfl[ds][0], qfl[ds][1], qfl[ds][2], qfl[ds][3],
              sptr(Qsl + (warp * 16 + arow) * ATS + ds * 16 + acg));
    }
    int dq0 = doc[b * SEQ + qb * 64 + warp * 16 + grp];
    int dq1 = doc[b * SEQ + qb * 64 + warp * 16 + grp + 8];

    // doc-aware skip: tile t fully masked iff doc[t*64+63] < doc[qb*64] (sorted doc)
    int d0 = doc[b * SEQ + qb * 64];
    int pred = (lane <= qb) && (doc[b * SEQ + lane * 64 + 63] >= d0);
    uint32_t bm_ = __ballot_sync(0xffffffffu, pred);
    int kt_start = __ffs(bm_) - 1;

    float o[8][4];
#pragma unroll
    for (int j = 0; j < 8; j++)
#pragma unroll
        for (int t = 0; t < 4; t++) o[j][t] = 0.f;
    float m0r = -1e30f, m1r = -1e30f, l0 = 0.f, l1 = 0.f;

    const __half* Kbh = Kh + (size_t)bh * SEQ * 64;
    const __half* Kbl = Kl + (size_t)bh * SEQ * 64;
    const __half* Vbh = Vth + (size_t)bh * 64 * SEQ;
    const __half* Vbl = Vtl + (size_t)bh * 64 * SEQ;

    for (int kt = kt_start; kt <= qb; kt++) {
        int kbase = kt * 64;
        __syncthreads();
        for (int i = tid; i < 512; i += 128) {
            int r = i >> 3, c = (i & 7) * 8;
            *(uint4*)(Ksh + r * ATS + c) = *(const uint4*)(Kbh + (size_t)(kbase + r) * 64 + c);
            *(uint4*)(Ksl + r * ATS + c) = *(const uint4*)(Kbl + (size_t)(kbase + r) * 64 + c);
            *(uint4*)(Vsh + r * ATS + c) = *(const uint4*)(Vbh + (size_t)r * SEQ + kbase + c);
            *(uint4*)(Vsl + r * ATS + c) = *(const uint4*)(Vbl + (size_t)r * SEQ + kbase + c);
        }
        if (tid < 64) sdoc[tid] = doc[b * SEQ + kbase + tid];
        __syncthreads();

        float sc[8][4];
#pragma unroll
        for (int j = 0; j < 8; j++)
#pragma unroll
            for (int t = 0; t < 4; t++) sc[j][t] = 0.f;
#pragma unroll
        for (int ds = 0; ds < 4; ds++) {
            uint32_t kfh[8][2], kfl[8][2];
#pragma unroll
            for (int np = 0; np < 4; np++) {
                uint32_t m0, m1, m2, m3;
                ldsm4(m0, m1, m2, m3, sptr(Ksh + (np * 16 + arow) * ATS + ds * 16 + acg));
                kfh[2 * np][0] = m0; kfh[2 * np][1] = m2;
                kfh[2 * np + 1][0] = m1; kfh[2 * np + 1][1] = m3;
                ldsm4(m0, m1, m2, m3, sptr(Ksl + (np * 16 + arow) * ATS + ds * 16 + acg));
                kfl[2 * np][0] = m0; kfl[2 * np][1] = m2;
                kfl[2 * np + 1][0] = m1; kfl[2 * np + 1][1] = m3;
            }
#pragma unroll
            for (int j = 0; j < 8; j++) {
                mma16816(sc[j], qfl[ds], kfh[j]);
                mma16816(sc[j], qfh[ds], kfl[j]);
                mma16816(sc[j], qfh[ds], kfh[j]);
            }
        }

#pragma unroll
        for (int j = 0; j < 8; j++) {
            int dk0 = sdoc[8 * j + 2 * qid], dk1 = sdoc[8 * j + 2 * qid + 1];
            sc[j][0] = (dk0 == dq0) ? sc[j][0] * 0.125f : -6e30f;
            sc[j][1] = (dk1 == dq0) ? sc[j][1] * 0.125f : -6e30f;
            sc[j][2] = (dk0 == dq1) ? sc[j][2] * 0.125f : -6e30f;
            sc[j][3] = (dk1 == dq1) ? sc[j][3] * 0.125f : -6e30f;
        }

        float tm0 = -1e30f, tm1 = -1e30f;
#pragma unroll
        for (int j = 0; j < 8; j++) {
            tm0 = fmaxf(tm0, fmaxf(sc[j][0], sc[j][1]));
            tm1 = fmaxf(tm1, fmaxf(sc[j][2], sc[j][3]));
        }
#pragma unroll
        for (int off = 1; off < 4; off <<= 1) {
            tm0 = fmaxf(tm0, __shfl_xor_sync(0xffffffffu, tm0, off));
            tm1 = fmaxf(tm1, __shfl_xor_sync(0xffffffffu, tm1, off));
        }
        float mn0 = fmaxf(m0r, tm0), mn1 = fmaxf(m1r, tm1);
        float r0 = __expf(m0r - mn0), r1 = __expf(m1r - mn1);

        uint32_t pfh[8][2], pfl[8][2];
        float ps0 = 0.f, ps1 = 0.f;
#pragma unroll
        for (int j = 0; j < 8; j++) {
            float p0 = __expf(sc[j][0] - mn0), p1 = __expf(sc[j][1] - mn0);
            float p2 = __expf(sc[j][2] - mn1), p3 = __expf(sc[j][3] - mn1);
            ps0 += p0 + p1; ps1 += p2 + p3;
            __half2 hA = __floats2half2_rn(p0, p1);
            __half2 hB = __floats2half2_rn(p2, p3);
            pfh[j][0] = h2u(hA);
            pfh[j][1] = h2u(hB);
            __half2 lA = __floats2half2_rn(p0 - __half2float(__low2half(hA)),
                                           p1 - __half2float(__high2half(hA)));
            __half2 lB = __floats2half2_rn(p2 - __half2float(__low2half(hB)),
                                           p3 - __half2float(__high2half(hB)));
            pfl[j][0] = h2u(lA);
            pfl[j][1] = h2u(lB);
        }
#pragma unroll
        for (int off = 1; off < 4; off <<= 1) {
            ps0 += __shfl_xor_sync(0xffffffffu, ps0, off);
            ps1 += __shfl_xor_sync(0xffffffffu, ps1, off);
        }
        l0 = l0 * r0 + ps0;
        l1 = l1 * r1 + ps1;
        m0r = mn0; m1r = mn1;
#pragma unroll
        for (int j = 0; j < 8; j++) {
            o[j][0] *= r0; o[j][1] *= r0; o[j][2] *= r1; o[j][3] *= r1;
        }

#pragma unroll
        for (int ks = 0; ks < 4; ks++) {
            uint32_t pah[4] = {pfh[2 * ks][0], pfh[2 * ks][1], pfh[2 * ks + 1][0], pfh[2 * ks + 1][1]};
            uint32_t pal[4] = {pfl[2 * ks][0], pfl[2 * ks][1], pfl[2 * ks + 1][0], pfl[2 * ks + 1][1]};
            uint32_t vfh[8][2], vfl[8][2];
#pragma unroll
            for (int np = 0; np < 4; np++) {
                uint32_t m0, m1, m2, m3;
                ldsm4(m0, m1, m2, m3, sptr(Vsh + (np * 16 + arow) * ATS + ks * 16 + acg));
                vfh[2 * np][0] = m0; vfh[2 * np][1] = m2;
                vfh[2 * np + 1][0] = m1; vfh[2 * np + 1][1] = m3;
                ldsm4(m0, m1, m2, m3, sptr(Vsl + (np * 16 + arow) * ATS + ks * 16 + acg));
                vfl[2 * np][0] = m0; vfl[2 * np][1] = m2;
                vfl[2 * np + 1][0] = m1; vfl[2 * np + 1][1] = m3;
            }
#pragma unroll
            for (int j = 0; j < 8; j++) {
                mma16816(o[j], pal, vfh[j]);
                mma16816(o[j], pah, vfl[j]);
                mma16816(o[j], pah, vfh[j]);
            }
        }
    }

    float inv0 = 1.0f / l0, inv1 = 1.0f / l1;
    int row0 = qb * 64 + warp * 16 + grp;
#pragma unroll
    for (int j = 0; j < 8; j++) {
        int col = h * 64 + 8 * j + 2 * qid;
        float v0 = o[j][0] * inv0, v1 = o[j][1] * inv0;
        __half2 hh = __floats2half2_rn(v0, v1);
        __half2 ll = __floats2half2_rn(v0 - __half2float(__low2half(hh)),
                                       v1 - __half2float(__high2half(hh)));
        size_t i0 = (size_t)(b * SEQ + row0) * DMODEL + col;
        *(__half2*)(Oh + i0) = hh;
        *(__half2*)(Ol + i0) = ll;
        float v2 = o[j][2] * inv1, v3 = o[j][3] * inv1;
        hh = __floats2half2_rn(v2, v3);
        ll = __floats2half2_rn(v2 - __half2float(__low2half(hh)),
                               v3 - __half2float(__high2half(hh)));
        size_t i1 = (size_t)(b * SEQ + row0 + 8) * DMODEL + col;
        *(__half2*)(Oh + i1) = hh;
        *(__half2*)(Ol + i1) = ll;
    }
}

// ---- router attention: one block per (seq, head), full 72x72 in smem ----
#define ATR_SMEM ((72 * 65 * 3 + 72 * 73 + 72) * 4)
__global__ __launch_bounds__(128) void attn_r2(
        const __half* __restrict__ Qh, const __half* __restrict__ Ql,
        const __half* __restrict__ Kh, const __half* __restrict__ Kl,
        const __half* __restrict__ Vh, const __half* __restrict__ Vl,
        __half* __restrict__ Oh, __half* __restrict__ Ol) {
    extern __shared__ float rs[];
    float* Qs = rs;
    float* Ks = rs + 72 * 65;
    float* Vs = rs + 2 * 72 * 65;
    float* Ps = rs + 3 * 72 * 65;
    float* den = rs + 3 * 72 * 65 + 72 * 73;

    int bh = blockIdx.x;
    int tid = threadIdx.x;

    for (int i = tid; i < 72 * 64; i += 128) {
        int r = i >> 6, d = i & 63;
        size_t base = ((size_t)bh * SRTR + r) * 64 + d;
        Qs[r * 65 + d] = __half2float(Qh[base]) + __half2float(Ql[base]);
        Ks[r * 65 + d] = __half2float(Kh[base]) + __half2float(Kl[base]);
        Vs[r * 65 + d] = __half2float(Vh[base]) + __half2float(Vl[base]);
    }
    __syncthreads();

    if (tid < 72) {
        int q = tid;
        float m = -1e30f;
        for (int k = 0; k < 72; k++) {
            float s = 0.f;
#pragma unroll 16
            for (int d = 0; d < 64; d++)
                s += Qs[q * 65 + d] * Ks[k * 65 + d];
            s *= 0.125f;
            Ps[q * 73 + k] = s;
            m = fmaxf(m, s);
        }
        float l = 0.f;
        for (int k = 0; k < 72; k++) {
            float e = __expf(Ps[q * 73 + k] - m);
            Ps[q * 73 + k] = e;
            l += e;
        }
        den[q] = 1.0f / l;
    }
    __syncthreads();

    int b = bh >> 3, h = bh & 7;
    for (int i = tid; i < 72 * 64; i += 128) {
        int q = i >> 6, d = i & 63;
        float acc = 0.f;
#pragma unroll 8
        for (int k = 0; k < 72; k++)
            acc += Ps[q * 73 + k] * Vs[k * 65 + d];
        float o = acc * den[q];
        size_t idx = (size_t)(b * SRTR + q) * DMODEL + h * 64 + d;
        __half hh, ll;
        split_h(o, hh, ll);
        Oh[idx] = hh;
        Ol[idx] = ll;
    }
}

__global__ void build_xr_k(const float* __restrict__ x, const float* __restrict__ rt,
                           float* __restrict__ xr) {
    int i = blockIdx.x * blockDim.x + threadIdx.x;
    if (i >= NTOK_RTR * DMODEL) return;
    int blk = i / (SRTR * DMODEL);
    int rem = i % (SRTR * DMODEL);
    int t = rem / DMODEL, dd = rem % DMODEL;
    xr[i] = (t < 64) ? x[(size_t)(blk * 64 + t) * DMODEL + dd]
                     : rt[(size_t)(t - 64) * DMODEL + dd];
}

__global__ void gather_rows_k(const float* __restrict__ xr, __half* __restrict__ rh,
                              __half* __restrict__ rl) {
    int i = blockIdx.x * blockDim.x + threadIdx.x;
    if (i >= 512 * DMODEL) return;
    int row = i / DMODEL, dd = i % DMODEL;
    int blk = row >> 3, r = row & 7;
    __half h, l;
    split_h(xr[((size_t)blk * SRTR + 64 + r) * DMODEL + dd], h, l);
    rh[i] = h;
    rl[i] = l;
}

__global__ void knorm_k(const float* __restrict__ kr, const float* __restrict__ kg,
                        float* __restrict__ knr, float* __restrict__ kng) {
    int tid = threadIdx.x;
    int which = tid >> 9;
    int idx = tid & 511;
    int g = idx >> 4, e = idx & 15;
    const float* src = which ? kg : kr;
    const float* col = src + (size_t)g * 128 * 16 + e;
    float s = 0.f;
    for (int d = 0; d < 128; d++) { float v = col[d * 16]; s += v * v; }
    float n = fmaxf(sqrtf(s), 1e-12f);
    if (which) kng[idx] = n; else knr[idx] = n;
}

__global__ void logits_k(const float* __restrict__ outp,
                         const float* __restrict__ keys_r, const float* __restrict__ keys_g,
                         const float* __restrict__ knr, const float* __restrict__ kng,
                         float* __restrict__ rl, float* __restrict__ gl) {
    __shared__ float vr[128], vg[128], red[128];
    int g = blockIdx.x >> 6, bb = blockIdx.x & 63;
    int b = bb >> 5, l = bb & 31;
    int srcl = (l + 31) & 31;
    int r = g >> 2;
    const float* row = outp + (size_t)((b * 32 + srcl) * 8 + r) * 256;
    int tid = threadIdx.x;
    vr[tid] = row[tid];
    vg[tid] = row[128 + tid];
    float nr2 = bsum128(vr[tid] * vr[tid], red);
    float ng2 = bsum128(vg[tid] * vg[tid], red);
    float inr = 1.0f / fmaxf(sqrtf(nr2), 1e-12f);
    float ing = 1.0f / fmaxf(sqrtf(ng2), 1e-12f);
    if (tid < 16) {
        int e = tid;
        const float* kr = keys_r + (size_t)g * 128 * 16 + e;
        const float* kg = keys_g + (size_t)g * 128 * 16 + e;
        float dr = 0.f, dg = 0.f;
        for (int dd = 0; dd < 128; dd++) {
            dr += vr[dd] * kr[dd * 16];
            dg += vg[dd] * kg[dd * 16];
        }
        rl[(size_t)(g * 64 + bb) * 16 + e] = dr * inr / knr[g * 16 + e];
        gl[(size_t)(g * 64 + bb) * 16 + e] = dg * ing / kng[g * 16 + e];
    }
}

__global__ void topk_k(const float* __restrict__ rl, const float* __restrict__ gl,
                       float* __restrict__ out) {
    int t = blockIdx.x * blockDim.x + threadIdx.x;
    if (t >= 2048) return;
    const float* r = rl + (size_t)t * 16;
    const float* g = gl + (size_t)t * 16;
    int i1 = 0; float v1 = r[0];
    for (int e = 1; e < 16; e++) if (r[e] > v1) { v1 = r[e]; i1 = e; }
    int i2 = -1; float v2 = -1e30f;
    for (int e = 0; e < 16; e++) {
        if (e == i1) continue;
        if (r[e] > v2) { v2 = r[e]; i2 = e; }
    }
    out[(size_t)t * 2 + 0] = v1;
    out[(size_t)t * 2 + 1] = v2;
    out[4096 + (size_t)t * 2 + 0] = g[i1];
    out[4096 + (size_t)t * 2 + 1] = g[i2];
}

// ---------------- host orchestration ----------------
static inline int pgrid(int tiles) { return tiles < NSM_SLOTS ? tiles : NSM_SLOTS; }

static void run_layer(float* cur, size_t qkvo, size_t oo, size_t upo, size_t dno,
                      const float* n1, const float* n2,
                      int ntok, int SEQ, int enc, const int* doc,
                      float* sb, __half* hb_) {
    float*  qkv  = sb + OFF_QKV;
    float*  hbuf = sb + OFF_H;
    __half* xnh = hb_ + HO_XNH; __half* xnl = hb_ + HO_XNL;
    __half* ath = hb_ + HO_ATTH; __half* atl = hb_ + HO_ATTL;
    __half* ach = hb_ + HO_ACTH; __half* acl = hb_ + HO_ACTL;
    __half* wh = hb_ + HO_WH;  __half* wl = hb_ + HO_WL;
    __half* qh_ = hb_ + HO_QH; __half* ql_ = hb_ + HO_QL;
    __half* kh_ = hb_ + HO_KH; __half* kl_ = hb_ + HO_KL;
    __half* vh_ = hb_ + HO_VH; __half* vl_ = hb_ + HO_VL;
    __half* vth_ = hb_ + HO_VTH; __half* vtl_ = hb_ + HO_VTL;
    int bh_total = (ntok / SEQ) * BH;
    int mt = ntok / 128;

    rmsnorm_k<<<ntok, 128>>>(cur, n1, xnh, xnl);
    sgemm_h3<<<pgrid(12 * mt), 256, GEMM_SMEM>>>(xnh, xnl, wh + qkvo, wl + qkvo, qkv,
                                                 nullptr, nullptr, ntok, 1536, 512, 0);
    split_rope_k<<<ntok, 128>>>(qkv, qh_, ql_, kh_, kl_, vh_, vl_, SEQ);
    if (enc) {
        vtrans_k<<<dim3(SEQ / 64, bh_total), 256>>>(vh_, vl_, vth_, vtl_, SEQ);
        attn_mma_k<<<dim3(SEQ / 64, bh_total), 128, AMMA_SMEM>>>(
            qh_, ql_, kh_, kl_, vth_, vtl_, ath, atl, doc, SEQ);
    } else {
        attn_r2<<<bh_total, 128, ATR_SMEM>>>(qh_, ql_, kh_, kl_, vh_, vl_, ath, atl);
    }
    sgemm_h3<<<pgrid(4 * mt), 256, GEMM_SMEM>>>(ath, atl, wh + oo, wl + oo, cur,
                                                nullptr, nullptr, ntok, 512, 512, 1);
    rmsnorm_k<<<ntok, 128>>>(cur, n2, xnh, xnl);
    sgemm_h3<<<pgrid(16 * mt), 256, GEMM_SMEM>>>(xnh, xnl, wh + upo, wl + upo, hbuf,
                                                 ach, acl, ntok, 2048, 512, 2);
    sgemm_h3<<<pgrid(4 * mt), 256, GEMM_SMEM>>>(ach, acl, wh + dno, wl + dno, cur,
                                                nullptr, nullptr, ntok, 512, 1024, 1);
}

extern "C" void kernel_launch(void* const* d_in, const int* in_sizes, int n_in,
                              void* d_out, int out_size) {
    const float* x_in   = (const float*)d_in[0];
    const int*   doc    = (const int*)d_in[1];
    const float* rt     = (const float*)d_in[2];
    const float* out_w  = (const float*)d_in[3];
    const float* keys_r = (const float*)d_in[4];
    const float* keys_g = (const float*)d_in[5];
    const float* e_qkv  = (const float*)d_in[6];
    const float* e_o    = (const float*)d_in[7];
    const float* e_up   = (const float*)d_in[8];
    const float* e_dn   = (const float*)d_in[9];
    const float* e_n1   = (const float*)d_in[10];
    const float* e_n2   = (const float*)d_in[11];
    const float* r_qkv  = (const float*)d_in[12];
    const float* r_o    = (const float*)d_in[13];
    const float* r_up   = (const float*)d_in[14];
    const float* r_dn   = (const float*)d_in[15];
    const float* r_n1   = (const float*)d_in[16];
    const float* r_n2   = (const float*)d_in[17];
    float* out = (float*)d_out;

    static int attr_set = 0;
    if (!attr_set) {
        cudaFuncSetAttribute(attn_mma_k, cudaFuncAttributeMaxDynamicSharedMemorySize, AMMA_SMEM);
        cudaFuncSetAttribute(sgemm_h3, cudaFuncAttributeMaxDynamicSharedMemorySize, GEMM_SMEM);
        cudaFuncSetAttribute(attn_r2, cudaFuncAttributeMaxDynamicSharedMemorySize, ATR_SMEM);
        attr_set = 1;
    }

    float* sb;
    cudaGetSymbolAddress((void**)&sb, g_s);
    __half* hb_;
    cudaGetSymbolAddress((void**)&hb_, g_h);

    float* xbuf = sb + OFF_X;
    float* xr   = sb + OFF_XR;
    float* outp = sb + OFF_OUT;
    float* knr  = sb + OFF_KNR;
    float* kng  = sb + OFF_KNG;
    float* rl   = sb + OFF_RL;
    float* gl   = sb + OFF_GL;
    __half* wh = hb_ + HO_WH;
    __half* wl = hb_ + HO_WL;
    __half* rowsh = hb_ + HO_ROWSH;
    __half* rowsl = hb_ + HO_ROWSL;

    // pre-split all weights (batched over layers via grid.z)
    wsplitT_k<<<dim3(1536 / 32, 512 / 32, 4), dim3(32, 8)>>>(e_qkv, wh + WO_EQ, wl + WO_EQ, 512, 1536, 0);
    wsplitT_k<<<dim3(512 / 32, 512 / 32, 4), dim3(32, 8)>>>(e_o, wh + WO_EO, wl + WO_EO, 512, 512, 0);
    wsplitT_k<<<dim3(2048 / 32, 512 / 32, 4), dim3(32, 8)>>>(e_up, wh + WO_EU, wl + WO_EU, 512, 2048, 1);
    wsplitT_k<<<dim3(512 / 32, 1024 / 32, 4), dim3(32, 8)>>>(e_dn, wh + WO_ED, wl + WO_ED, 1024, 512, 0);
    wsplitT_k<<<dim3(1536 / 32, 512 / 32, 2), dim3(32, 8)>>>(r_qkv, wh + WO_RQ, wl + WO_RQ, 512, 1536, 0);
    wsplitT_k<<<dim3(512 / 32, 512 / 32, 2), dim3(32, 8)>>>(r_o, wh + WO_RO, wl + WO_RO, 512, 512, 0);
    wsplitT_k<<<dim3(2048 / 32, 512 / 32, 2), dim3(32, 8)>>>(r_up, wh + WO_RU, wl + WO_RU, 512, 2048, 1);
    wsplitT_k<<<dim3(512 / 32, 1024 / 32, 2), dim3(32, 8)>>>(r_dn, wh + WO_RD, wl + WO_RD, 1024, 512, 0);
    wsplitT_k<<<dim3(256 / 32, 512 / 32, 1), dim3(32, 8)>>>(out_w, wh + WO_OUT, wl + WO_OUT, 512, 256, 0);

    copy_k<<<(NTOK_ENC * DMODEL + 255) / 256, 256>>>(x_in, xbuf, NTOK_ENC * DMODEL);

    for (int i = 0; i < 4; i++) {
        run_layer(xbuf,
                  WO_EQ + (size_t)i * 786432,
                  WO_EO + (size_t)i * 262144,
                  WO_EU + (size_t)i * 1048576,
                  WO_ED + (size_t)i * 524288,
                  e_n1 + (size_t)i * 512, e_n2 + (size_t)i * 512,
                  NTOK_ENC, SENC, 1, doc, sb, hb_);
    }

    build_xr_k<<<(NTOK_RTR * DMODEL + 255) / 256, 256>>>(xbuf, rt, xr);

    for (int i = 0; i < 2; i++) {
        run_layer(xr,
                  WO_RQ + (size_t)i * 786432,
                  WO_RO + (size_t)i * 262144,
                  WO_RU + (size_t)i * 1048576,
                  WO_RD + (size_t)i * 524288,
                  r_n1 + (size_t)i * 512, r_n2 + (size_t)i * 512,
                  NTOK_RTR, SRTR, 0, nullptr, sb, hb_);
    }

    gather_rows_k<<<(512 * DMODEL + 255) / 256, 256>>>(xr, rowsh, rowsl);
    sgemm_h3<<<pgrid(8), 256, GEMM_SMEM>>>(rowsh, rowsl, wh + WO_OUT, wl + WO_OUT, outp,
                                           nullptr, nullptr, 512, 256, 512, 0);

    knorm_k<<<1, 1024>>>(keys_r, keys_g, knr, kng);
    logits_k<<<32 * 64, 128>>>(outp, keys_r, keys_g, knr, kng, rl, gl);
    topk_k<<<16, 128>>>(rl, gl, out);
}

// round 16
// speedup vs baseline: 1.7153x; 1.0535x over previous
#include <cuda_runtime.h>
#include <cuda_fp16.h>
#include <math.h>
#include <stdint.h>

// Model constants
#define BH      8
#define HDIM    64
#define DMODEL  512
#define SENC    2048
#define SRTR    72
#define NTOK_ENC 4096
#define NTOK_RTR 4608
#define FFH     1024

// ---- fp32 scratch (float offsets) ----
#define OFF_QKV   0ull
#define OFF_H     14155776ull
#define OFF_X     23592960ull
#define OFF_XR    25952256ull
#define OFF_OUT   28311552ull
#define OFF_KNR   28442624ull
#define OFF_KNG   28443136ull
#define OFF_RL    28443648ull
#define OFF_GL    28476416ull
#define SCRATCH_FLOATS 28509184ull
__device__ float g_s[SCRATCH_FLOATS];

// ---- fp16 scratch (half offsets) ----
#define HO_XNH   0ull
#define HO_XNL   2359296ull
#define HO_ATTH  4718592ull
#define HO_ATTL  7077888ull
#define HO_ACTH  9437184ull
#define HO_ACTL  14155776ull
#define HO_ROWSH 18874368ull
#define HO_ROWSL 19136512ull
#define HO_WH    19398656ull
#define HO_WL    35258368ull
#define HO_QH    51118080ull
#define HO_QL    53477376ull
#define HO_KH    55836672ull
#define HO_KL    58195968ull
#define HO_VH    60555264ull
#define HO_VL    62914560ull
#define HO_VTH   65273856ull
#define HO_VTL   67633152ull
#define SCRATCH_HALVES 69992448ull
__device__ __half g_h[SCRATCH_HALVES];

// weight-plane sub-offsets (halves)
#define WO_EQ   0ull
#define WO_EO   3145728ull
#define WO_EU   4194304ull
#define WO_ED   8388608ull
#define WO_RQ   10485760ull
#define WO_RO   12058624ull
#define WO_RU   12582912ull
#define WO_RD   14680064ull
#define WO_OUT  15728640ull

#define NSM_SLOTS 296

// ---------------- helpers ----------------
__device__ __forceinline__ float bsum128(float v, volatile float* red) {
    int tid = threadIdx.x;
    red[tid] = v;
    for (int off = 64; off >= 1; off >>= 1) {
        __syncthreads();
        if (tid < off) red[tid] += red[tid + off];
    }
    __syncthreads();
    float r = red[0];
    __syncthreads();
    return r;
}

__device__ __forceinline__ void split_h(float v, __half& hi, __half& lo) {
    hi = __float2half_rn(v);
    lo = __float2half_rn(v - __half2float(hi));
}

__device__ __forceinline__ void split_h2(float a, float b, __half2& hi2, __half2& lo2) {
    hi2 = __floats2half2_rn(a, b);
    lo2 = __floats2half2_rn(a - __half2float(__low2half(hi2)),
                            b - __half2float(__high2half(hi2)));
}

__device__ __forceinline__ void mma16816(float* c, const uint32_t* a, const uint32_t* b) {
    asm volatile(
        "mma.sync.aligned.m16n8k16.row.col.f32.f16.f16.f32 "
        "{%0,%1,%2,%3}, {%4,%5,%6,%7}, {%8,%9}, {%0,%1,%2,%3};"
        : "+f"(c[0]), "+f"(c[1]), "+f"(c[2]), "+f"(c[3])
        : "r"(a[0]), "r"(a[1]), "r"(a[2]), "r"(a[3]), "r"(b[0]), "r"(b[1]));
}

__device__ __forceinline__ uint32_t sptr(const void* p) {
    return (uint32_t)__cvta_generic_to_shared(p);
}

__device__ __forceinline__ void ldsm4(uint32_t& r0, uint32_t& r1, uint32_t& r2,
                                      uint32_t& r3, uint32_t addr) {
    asm volatile("ldmatrix.sync.aligned.m8n8.x4.shared.b16 {%0,%1,%2,%3}, [%4];"
                 : "=r"(r0), "=r"(r1), "=r"(r2), "=r"(r3) : "r"(addr));
}

__device__ __forceinline__ void cpa16(uint32_t dst, const void* src) {
    asm volatile("cp.async.cg.shared.global [%0], [%1], 16;" :: "r"(dst), "l"(src));
}
__device__ __forceinline__ void cpa_commit() { asm volatile("cp.async.commit_group;"); }
__device__ __forceinline__ void cpa_wait0() { asm volatile("cp.async.wait_group 0;"); }
__device__ __forceinline__ void cpa_wait1() { asm volatile("cp.async.wait_group 1;"); }
__device__ __forceinline__ void cpa_wait2() { asm volatile("cp.async.wait_group 2;"); }

__device__ __forceinline__ uint32_t h2u(__half2 h) { return *(uint32_t*)&h; }

// ---------------- kernels ----------------
__global__ void copy_k(const float* __restrict__ src, float* __restrict__ dst, int n) {
    int i = blockIdx.x * blockDim.x + threadIdx.x;
    if (i < n) dst[i] = src[i];
}

// transpose + split weights; gridDim.z = layer index
__global__ void wsplitT_k(const float* __restrict__ w, __half* __restrict__ hT,
                          __half* __restrict__ lT, int K, int N, int ilv) {
    __shared__ float t[32][33];
    size_t loff = (size_t)blockIdx.z * K * N;
    w += loff; hT += loff; lT += loff;
    int n0 = blockIdx.x * 32, k0 = blockIdx.y * 32;
    int tx = threadIdx.x, ty = threadIdx.y;
    for (int i = ty; i < 32; i += 8) {
        int n = n0 + tx;
        int srcn = ilv ? ((n & 1) ? (N >> 1) + (n >> 1) : (n >> 1)) : n;
        t[i][tx] = w[(size_t)(k0 + i) * N + srcn];
    }
    __syncthreads();
    for (int i = ty; i < 32; i += 8) {
        float v = t[tx][i];
        __half h, l;
        split_h(v, h, l);
        hT[(size_t)(n0 + i) * K + k0 + tx] = h;
        lT[(size_t)(n0 + i) * K + k0 + tx] = l;
    }
}

__global__ void rmsnorm_k(const float* __restrict__ x, const float* __restrict__ w,
                          __half* __restrict__ yh, __half* __restrict__ yl) {
    __shared__ float red[128];
    size_t row = (size_t)blockIdx.x * DMODEL;
    int tid = threadIdx.x;
    float ss = 0.f;
    for (int i = tid; i < DMODEL; i += 128) {
        float v = x[row + i];
        ss += v * v;
    }
    float tot = bsum128(ss, red);
    float scale = rsqrtf(tot / (float)DMODEL + 1e-6f);
    for (int i = tid; i < DMODEL; i += 128) {
        __half h, l;
        split_h(x[row + i] * scale * w[i], h, l);
        yh[row + i] = h;
        yl[row + i] = l;
    }
}

// ---- 3xFP16 split GEMM, 6-stage swizzled pipeline, unroll-2, persistent ----
// Stage = 16KB: A hi/lo + B hi/lo arrays of [128 rows][16 halves] with
// XOR-granule swizzle: byte off = r*32 + ((g ^ ((r>>2)&1))<<4), g = 16B granule.
#define STG_B 16384
#define GEMM_SMEM (6 * STG_B)
#define SWZ(r, g) (((r) << 5) + ((((g) ^ (((r) >> 2) & 1))) << 4))
__global__ __launch_bounds__(256) void sgemm_h3(const __half* __restrict__ Ah,
                                                const __half* __restrict__ Al,
                                                const __half* __restrict__ BTh,
                                                const __half* __restrict__ BTl,
                                                float* __restrict__ C,
                                                __half* __restrict__ Dh,
                                                __half* __restrict__ Dl,
                                                int M, int N, int K, int mode) {
    extern __shared__ __align__(16) char gsm[];
    uint32_t gbase = sptr(gsm);
    int tid = threadIdx.x;
    int lane = tid & 31, warp = tid >> 5;
    int wm = warp >> 2, wn = warp & 3;
    int grp = lane >> 2, qid = lane & 3;
    int lrow = tid >> 1, gsel = tid & 1;       // cp.async: row, 16B granule
    int arow = lane & 15, ga = lane >> 4;      // ldsm: row-in-16, granule
    int nk = K >> 4;
    int ntN = N >> 7;
    int ntiles = (M >> 7) * ntN;

#define SLOT(s) (gbase + (uint32_t)(s) * STG_B)
#define LOADS(s, k0)                                                                  \
    {                                                                                 \
        uint32_t sb_ = SLOT(s);                                                       \
        uint32_t dsw = SWZ(lrow, gsel);                                               \
        size_t so = (size_t)(bm + lrow) * K + (k0) + gsel * 8;                        \
        size_t sb2o = (size_t)(bn + lrow) * K + (k0) + gsel * 8;                      \
        cpa16(sb_ + dsw, Ah + so);                                                    \
        cpa16(sb_ + 4096 + dsw, Al + so);                                             \
        cpa16(sb_ + 8192 + dsw, BTh + sb2o);                                          \
        cpa16(sb_ + 12288 + dsw, BTl + sb2o);                                         \
        cpa_commit();                                                                 \
    }
#define COMPUTE(s)                                                                    \
    {                                                                                 \
        uint32_t sb_ = SLOT(s);                                                       \
        uint32_t ah[4][4], al[4][4], bh[4][2], bl[4][2];                              \
        _Pragma("unroll")                                                             \
        for (int mt = 0; mt < 4; mt++) {                                              \
            int r = wm * 64 + mt * 16 + arow;                                         \
            uint32_t sa = SWZ(r, ga);                                                 \
            ldsm4(ah[mt][0], ah[mt][1], ah[mt][2], ah[mt][3], sb_ + sa);              \
            ldsm4(al[mt][0], al[mt][1], al[mt][2], al[mt][3], sb_ + 4096 + sa);       \
        }                                                                             \
        _Pragma("unroll")                                                             \
        for (int ntp = 0; ntp < 2; ntp++) {                                           \
            int r = wn * 32 + ntp * 16 + arow;                                        \
            uint32_t sa = SWZ(r, ga);                                                 \
            uint32_t m0, m1, m2, m3;                                                  \
            ldsm4(m0, m1, m2, m3, sb_ + 8192 + sa);                                   \
            bh[2 * ntp][0] = m0; bh[2 * ntp][1] = m2;                                 \
            bh[2 * ntp + 1][0] = m1; bh[2 * ntp + 1][1] = m3;                         \
            ldsm4(m0, m1, m2, m3, sb_ + 12288 + sa);                                  \
            bl[2 * ntp][0] = m0; bl[2 * ntp][1] = m2;                                 \
            bl[2 * ntp + 1][0] = m1; bl[2 * ntp + 1][1] = m3;                         \
        }                                                                             \
        _Pragma("unroll")                                                             \
        for (int mt = 0; mt < 4; mt++)                                                \
            _Pragma("unroll")                                                         \
            for (int nt = 0; nt < 4; nt++) {                                          \
                mma16816(acc[mt][nt], al[mt], bh[nt]);                                \
                mma16816(acc[mt][nt], ah[mt], bl[nt]);                                \
                mma16816(acc[mt][nt], ah[mt], bh[nt]);                                \
            }                                                                         \
    }

    for (int t = blockIdx.x; t < ntiles; t += gridDim.x) {
        int bm = (t / ntN) << 7;
        int bn = (t % ntN) << 7;

        float acc[4][4][4];
#pragma unroll
        for (int i = 0; i < 4; i++)
#pragma unroll
            for (int j = 0; j < 4; j++)
#pragma unroll
                for (int u = 0; u < 4; u++) acc[i][j][u] = 0.f;

        __syncthreads();        // all warps done with previous tile's smem
        LOADS(0, 0);
        LOADS(1, 16);
        LOADS(2, 32);
        LOADS(3, 48);           // nk >= 32 always here

        for (int kt = 0; kt < nk; kt += 2) {
            int newer = (kt + 2 < nk) + (kt + 3 < nk);
            if (newer == 2) cpa_wait2();
            else if (newer == 1) cpa_wait1();
            else cpa_wait0();
            __syncthreads();
            // slots (kt+4)%6, (kt+5)%6 were consumed in the PREVIOUS iteration;
            // this sync fences all warps past that compute -> safe to refill.
            if (kt + 4 < nk) LOADS((kt + 4) % 6, (kt + 4) << 4);
            if (kt + 5 < nk) LOADS((kt + 5) % 6, (kt + 5) << 4);
            COMPUTE(kt % 6);
            COMPUTE((kt + 1) % 6);
        }

        if (mode == 2) {
            int half_n = N >> 1;
#pragma unroll
            for (int mt = 0; mt < 4; mt++)
#pragma unroll
                for (int nt = 0; nt < 4; nt++) {
                    int r0 = bm + wm * 64 + mt * 16 + grp;
                    int j = (bn + wn * 32 + nt * 8 + 2 * qid) >> 1;
                    float a0 = acc[mt][nt][0], b0 = acc[mt][nt][1];
                    float a1 = acc[mt][nt][2], b1 = acc[mt][nt][3];
                    float g0 = (a0 / (1.0f + __expf(-a0))) * b0;
                    float g1 = (a1 / (1.0f + __expf(-a1))) * b1;
                    __half h, l;
                    split_h(g0, h, l);
                    Dh[(size_t)r0 * half_n + j] = h;
                    Dl[(size_t)r0 * half_n + j] = l;
                    split_h(g1, h, l);
                    Dh[(size_t)(r0 + 8) * half_n + j] = h;
                    Dl[(size_t)(r0 + 8) * half_n + j] = l;
                }
        } else {
#pragma unroll
            for (int mt = 0; mt < 4; mt++)
#pragma unroll
                for (int nt = 0; nt < 4; nt++) {
                    int r0 = bm + wm * 64 + mt * 16 + grp;
                    int c0 = bn + wn * 32 + nt * 8 + 2 * qid;
                    size_t i00 = (size_t)r0 * N + c0;
                    size_t i10 = (size_t)(r0 + 8) * N + c0;
                    if (mode == 1) {
                        C[i00]     += acc[mt][nt][0];
                        C[i00 + 1] += acc[mt][nt][1];
                        C[i10]     += acc[mt][nt][2];
                        C[i10 + 1] += acc[mt][nt][3];
                    } else {
                        C[i00]     = acc[mt][nt][0];
                        C[i00 + 1] = acc[mt][nt][1];
                        C[i10]     = acc[mt][nt][2];
                        C[i10 + 1] = acc[mt][nt][3];
                    }
                }
        }
    }
#undef LOADS
#undef COMPUTE
#undef SLOT
}

// qkv row -> q/k (RoPE) and v, hi/lo half planes [bh][SEQ][64].
__global__ void split_rope_k(const float* __restrict__ qkv,
                             __half* __restrict__ Qh, __half* __restrict__ Ql,
                             __half* __restrict__ Kh, __half* __restrict__ Kl,
                             __half* __restrict__ Vh, __half* __restrict__ Vl,
                             int SEQ) {
    int tok = blockIdx.x;
    int b = tok / SEQ, s = tok % SEQ;
    const float* row = qkv + (size_t)tok * 1536;
    int tid = threadIdx.x;                 // 0..127
    int h = tid >> 4, p = (tid & 15) * 2;
    float q1a = row[h * 64 + p],      q1b = row[h * 64 + p + 1];
    float q2a = row[h * 64 + p + 32], q2b = row[h * 64 + p + 33];
    float k1a = row[512 + h * 64 + p],      k1b = row[512 + h * 64 + p + 1];
    float k2a = row[512 + h * 64 + p + 32], k2b = row[512 + h * 64 + p + 33];
    float inva = powf(1e-4f, (float)p * (1.0f / 32.0f));
    float invb = powf(1e-4f, (float)(p + 1) * (1.0f / 32.0f));
    float ca = cosf((float)s * inva), sa = sinf((float)s * inva);
    float cb = cosf((float)s * invb), sb2 = sinf((float)s * invb);
    size_t base = ((size_t)(b * BH + h) * SEQ + s) * 64;
    __half2 hi2, lo2;
    split_h2(q1a * ca + q2a * sa, q1b * cb + q2b * sb2, hi2, lo2);
    *(__half2*)(Qh + base + p) = hi2;       *(__half2*)(Ql + base + p) = lo2;
    split_h2(-q1a * sa + q2a * ca, -q1b * sb2 + q2b * cb, hi2, lo2);
    *(__half2*)(Qh + base + p + 32) = hi2;  *(__half2*)(Ql + base + p + 32) = lo2;
    split_h2(k1a * ca + k2a * sa, k1b * cb + k2b * sb2, hi2, lo2);
    *(__half2*)(Kh + base + p) = hi2;       *(__half2*)(Kl + base + p) = lo2;
    split_h2(-k1a * sa + k2a * ca, -k1b * sb2 + k2b * cb, hi2, lo2);
    *(__half2*)(Kh + base + p + 32) = hi2;  *(__half2*)(Kl + base + p + 32) = lo2;
    for (int j = tid; j < 256; j += 128) {
        int e = 2 * j;
        int hd = e >> 6, dd = e & 63;
        float va = row[1024 + e], vb = row[1024 + e + 1];
        split_h2(va, vb, hi2, lo2);
        size_t vi = ((size_t)(b * BH + hd) * SEQ + s) * 64 + dd;
        *(__half2*)(Vh + vi) = hi2;
        *(__half2*)(Vl + vi) = lo2;
    }
}

// V [bh][s][64] -> Vt [bh][64][s]
__global__ void vtrans_k(const __half* __restrict__ Vh, const __half* __restrict__ Vl,
                         __half* __restrict__ Vth, __half* __restrict__ Vtl, int SEQ) {
    __shared__ __half t[2][64][72];
    int sc = blockIdx.x * 64;
    int bh = blockIdx.y;
    int tid = threadIdx.x;
    for (int i = tid; i < 512; i += 256) {
        int r = i >> 3, c = (i & 7) * 8;
        *(uint4*)&t[0][r][c] = *(const uint4*)(Vh + ((size_t)bh * SEQ + sc + r) * 64 + c);
        *(uint4*)&t[1][r][c] = *(const uint4*)(Vl + ((size_t)bh * SEQ + sc + r) * 64 + c);
    }
    __syncthreads();
    for (int i = tid; i < 4096; i += 256) {
        int d = i >> 6, s = i & 63;
        Vth[((size_t)bh * 64 + d) * SEQ + sc + s] = t[0][s][d];
        Vtl[((size_t)bh * 64 + d) * SEQ + sc + s] = t[1][s][d];
    }
}

// ---- tensor-core flash attention, 3xFP16 split, doc-aware tile skipping ----
#define ATS 72
#define AMMA_SMEM (6 * 64 * ATS * 2 + 256)
__global__ __launch_bounds__(128) void attn_mma_k(
        const __half* __restrict__ Qh, const __half* __restrict__ Ql,
        const __half* __restrict__ Kh, const __half* __restrict__ Kl,
        const __half* __restrict__ Vth, const __half* __restrict__ Vtl,
        __half* __restrict__ Oh, __half* __restrict__ Ol,
        const int* __restrict__ doc, int SEQ) {
    extern __shared__ __half hsm[];
    __half* Qsh = hsm;
    __half* Qsl = hsm + 64 * ATS;
    __half* Ksh = hsm + 2 * 64 * ATS;
    __half* Ksl = hsm + 3 * 64 * ATS;
    __half* Vsh = hsm + 4 * 64 * ATS;
    __half* Vsl = hsm + 5 * 64 * ATS;
    int* sdoc = (int*)(hsm + 6 * 64 * ATS);

    int qb = blockIdx.x, bh = blockIdx.y;
    int b = bh >> 3, h = bh & 7;
    int tid = threadIdx.x, lane = tid & 31, warp = tid >> 5;
    int grp = lane >> 2, qid = lane & 3;
    int arow = lane & 15, acg = (lane >> 4) * 8;

    const __half* Qbh = Qh + ((size_t)bh * SEQ + qb * 64) * 64;
    const __half* Qbl = Ql + ((size_t)bh * SEQ + qb * 64) * 64;
    for (int i = tid; i < 512; i += 128) {
        int r = i >> 3, c = (i & 7) * 8;
        *(uint4*)(Qsh + r * ATS + c) = *(const uint4*)(Qbh + r * 64 + c);
        *(uint4*)(Qsl + r * ATS + c) = *(const uint4*)(Qbl + r * 64 + c);
    }
    __syncthreads();

    uint32_t qfh[4][4], qfl[4][4];
#pragma unroll
    for (int ds = 0; ds < 4; ds++) {
        ldsm4(qfh[ds][0], qfh[ds][1], qfh[ds][2], qfh[ds][3],
              sptr(Qsh + (warp * 16 + arow) * ATS + ds * 16 + acg));
        ldsm4(qfl[ds][0], qfl[ds][1], qfl[ds][2], qfl[ds][3],
              sptr(Qsl + (warp * 16 + arow) * ATS + ds * 16 + acg));
    }
    int dq0 = doc[b * SEQ + qb * 64 + warp * 16 + grp];
    int dq1 = doc[b * SEQ + qb * 64 + warp * 16 + grp + 8];

    int d0 = doc[b * SEQ + qb * 64];
    int pred = (lane <= qb) && (doc[b * SEQ + lane * 64 + 63] >= d0);
    uint32_t bm_ = __ballot_sync(0xffffffffu, pred);
    int kt_start = __ffs(bm_) - 1;

    float o[8][4];
#pragma unroll
    for (int j = 0; j < 8; j++)
#pragma unroll
        for (int t = 0; t < 4; t++) o[j][t] = 0.f;
    float m0r = -1e30f, m1r = -1e30f, l0 = 0.f, l1 = 0.f;

    const __half* Kbh = Kh + (size_t)bh * SEQ * 64;
    const __half* Kbl = Kl + (size_t)bh * SEQ * 64;
    const __half* Vbh = Vth + (size_t)bh * 64 * SEQ;
    const __half* Vbl = Vtl + (size_t)bh * 64 * SEQ;

    for (int kt = kt_start; kt <= qb; kt++) {
        int kbase = kt * 64;
        __syncthreads();
        for (int i = tid; i < 512; i += 128) {
            int r = i >> 3, c = (i & 7) * 8;
            *(uint4*)(Ksh + r * ATS + c) = *(const uint4*)(Kbh + (size_t)(kbase + r) * 64 + c);
            *(uint4*)(Ksl + r * ATS + c) = *(const uint4*)(Kbl + (size_t)(kbase + r) * 64 + c);
            *(uint4*)(Vsh + r * ATS + c) = *(const uint4*)(Vbh + (size_t)r * SEQ + kbase + c);
            *(uint4*)(Vsl + r * ATS + c) = *(const uint4*)(Vbl + (size_t)r * SEQ + kbase + c);
        }
        if (tid < 64) sdoc[tid] = doc[b * SEQ + kbase + tid];
        __syncthreads();

        float sc[8][4];
#pragma unroll
        for (int j = 0; j < 8; j++)
#pragma unroll
            for (int t = 0; t < 4; t++) sc[j][t] = 0.f;
#pragma unroll
        for (int ds = 0; ds < 4; ds++) {
            uint32_t kfh[8][2], kfl[8][2];
#pragma unroll
            for (int np = 0; np < 4; np++) {
                uint32_t m0, m1, m2, m3;
                ldsm4(m0, m1, m2, m3, sptr(Ksh + (np * 16 + arow) * ATS + ds * 16 + acg));
                kfh[2 * np][0] = m0; kfh[2 * np][1] = m2;
                kfh[2 * np + 1][0] = m1; kfh[2 * np + 1][1] = m3;
                ldsm4(m0, m1, m2, m3, sptr(Ksl + (np * 16 + arow) * ATS + ds * 16 + acg));
                kfl[2 * np][0] = m0; kfl[2 * np][1] = m2;
                kfl[2 * np + 1][0] = m1; kfl[2 * np + 1][1] = m3;
            }
#pragma unroll
            for (int j = 0; j < 8; j++) {
                mma16816(sc[j], qfl[ds], kfh[j]);
                mma16816(sc[j], qfh[ds], kfl[j]);
                mma16816(sc[j], qfh[ds], kfh[j]);
            }
        }

#pragma unroll
        for (int j = 0; j < 8; j++) {
            int dk0 = sdoc[8 * j + 2 * qid], dk1 = sdoc[8 * j + 2 * qid + 1];
            sc[j][0] = (dk0 == dq0) ? sc[j][0] * 0.125f : -6e30f;
            sc[j][1] = (dk1 == dq0) ? sc[j][1] * 0.125f : -6e30f;
            sc[j][2] = (dk0 == dq1) ? sc[j][2] * 0.125f : -6e30f;
            sc[j][3] = (dk1 == dq1) ? sc[j][3] * 0.125f : -6e30f;
        }

        float tm0 = -1e30f, tm1 = -1e30f;
#pragma unroll
        for (int j = 0; j < 8; j++) {
            tm0 = fmaxf(tm0, fmaxf(sc[j][0], sc[j][1]));
            tm1 = fmaxf(tm1, fmaxf(sc[j][2], sc[j][3]));
        }
#pragma unroll
        for (int off = 1; off < 4; off <<= 1) {
            tm0 = fmaxf(tm0, __shfl_xor_sync(0xffffffffu, tm0, off));
            tm1 = fmaxf(tm1, __shfl_xor_sync(0xffffffffu, tm1, off));
        }
        float mn0 = fmaxf(m0r, tm0), mn1 = fmaxf(m1r, tm1);
        float r0 = __expf(m0r - mn0), r1 = __expf(m1r - mn1);

        uint32_t pfh[8][2], pfl[8][2];
        float ps0 = 0.f, ps1 = 0.f;
#pragma unroll
        for (int j = 0; j < 8; j++) {
            float p0 = __expf(sc[j][0] - mn0), p1 = __expf(sc[j][1] - mn0);
            float p2 = __expf(sc[j][2] - mn1), p3 = __expf(sc[j][3] - mn1);
            ps0 += p0 + p1; ps1 += p2 + p3;
            __half2 hA = __floats2half2_rn(p0, p1);
            __half2 hB = __floats2half2_rn(p2, p3);
            pfh[j][0] = h2u(hA);
            pfh[j][1] = h2u(hB);
            __half2 lA = __floats2half2_rn(p0 - __half2float(__low2half(hA)),
                                           p1 - __half2float(__high2half(hA)));
            __half2 lB = __floats2half2_rn(p2 - __half2float(__low2half(hB)),
                                           p3 - __half2float(__high2half(hB)));
            pfl[j][0] = h2u(lA);
            pfl[j][1] = h2u(lB);
        }
#pragma unroll
        for (int off = 1; off < 4; off <<= 1) {
            ps0 += __shfl_xor_sync(0xffffffffu, ps0, off);
            ps1 += __shfl_xor_sync(0xffffffffu, ps1, off);
        }
        l0 = l0 * r0 + ps0;
        l1 = l1 * r1 + ps1;
        m0r = mn0; m1r = mn1;
#pragma unroll
        for (int j = 0; j < 8; j++) {
            o[j][0] *= r0; o[j][1] *= r0; o[j][2] *= r1; o[j][3] *= r1;
        }

#pragma unroll
        for (int ks = 0; ks < 4; ks++) {
            uint32_t pah[4] = {pfh[2 * ks][0], pfh[2 * ks][1], pfh[2 * ks + 1][0], pfh[2 * ks + 1][1]};
            uint32_t pal[4] = {pfl[2 * ks][0], pfl[2 * ks][1], pfl[2 * ks + 1][0], pfl[2 * ks + 1][1]};
            uint32_t vfh[8][2], vfl[8][2];
#pragma unroll
            for (int np = 0; np < 4; np++) {
                uint32_t m0, m1, m2, m3;
                ldsm4(m0, m1, m2, m3, sptr(Vsh + (np * 16 + arow) * ATS + ks * 16 + acg));
                vfh[2 * np][0] = m0; vfh[2 * np][1] = m2;
                vfh[2 * np + 1][0] = m1; vfh[2 * np + 1][1] = m3;
                ldsm4(m0, m1, m2, m3, sptr(Vsl + (np * 16 + arow) * ATS + ks * 16 + acg));
                vfl[2 * np][0] = m0; vfl[2 * np][1] = m2;
                vfl[2 * np + 1][0] = m1; vfl[2 * np + 1][1] = m3;
            }
#pragma unroll
            for (int j = 0; j < 8; j++) {
                mma16816(o[j], pal, vfh[j]);
                mma16816(o[j], pah, vfl[j]);
                mma16816(o[j], pah, vfh[j]);
            }
        }
    }

    float inv0 = 1.0f / l0, inv1 = 1.0f / l1;
    int row0 = qb * 64 + warp * 16 + grp;
#pragma unroll
    for (int j = 0; j < 8; j++) {
        int col = h * 64 + 8 * j + 2 * qid;
        float v0 = o[j][0] * inv0, v1 = o[j][1] * inv0;
        __half2 hh = __floats2half2_rn(v0, v1);
        __half2 ll = __floats2half2_rn(v0 - __half2float(__low2half(hh)),
                                       v1 - __half2float(__high2half(hh)));
        size_t i0 = (size_t)(b * SEQ + row0) * DMODEL + col;
        *(__half2*)(Oh + i0) = hh;
        *(__half2*)(Ol + i0) = ll;
        float v2 = o[j][2] * inv1, v3 = o[j][3] * inv1;
        hh = __floats2half2_rn(v2, v3);
        ll = __floats2half2_rn(v2 - __half2float(__low2half(hh)),
                               v3 - __half2float(__high2half(hh)));
        size_t i1 = (size_t)(b * SEQ + row0 + 8) * DMODEL + col;
        *(__half2*)(Oh + i1) = hh;
        *(__half2*)(Ol + i1) = ll;
    }
}

// ---- router attention: one block per (seq, head), full 72x72 in smem ----
#define ATR_SMEM ((72 * 65 * 3 + 72 * 73 + 72) * 4)
__global__ __launch_bounds__(128) void attn_r2(
        const __half* __restrict__ Qh, const __half* __restrict__ Ql,
        const __half* __restrict__ Kh, const __half* __restrict__ Kl,
        const __half* __restrict__ Vh, const __half* __restrict__ Vl,
        __half* __restrict__ Oh, __half* __restrict__ Ol) {
    extern __shared__ float rs[];
    float* Qs = rs;
    float* Ks = rs + 72 * 65;
    float* Vs = rs + 2 * 72 * 65;
    float* Ps = rs + 3 * 72 * 65;
    float* den = rs + 3 * 72 * 65 + 72 * 73;

    int bh = blockIdx.x;
    int tid = threadIdx.x;

    for (int i = tid; i < 72 * 64; i += 128) {
        int r = i >> 6, d = i & 63;
        size_t base = ((size_t)bh * SRTR + r) * 64 + d;
        Qs[r * 65 + d] = __half2float(Qh[base]) + __half2float(Ql[base]);
        Ks[r * 65 + d] = __half2float(Kh[base]) + __half2float(Kl[base]);
        Vs[r * 65 + d] = __half2float(Vh[base]) + __half2float(Vl[base]);
    }
    __syncthreads();

    if (tid < 72) {
        int q = tid;
        float m = -1e30f;
        for (int k = 0; k < 72; k++) {
            float s = 0.f;
#pragma unroll 16
            for (int d = 0; d < 64; d++)
                s += Qs[q * 65 + d] * Ks[k * 65 + d];
            s *= 0.125f;
            Ps[q * 73 + k] = s;
            m = fmaxf(m, s);
        }
        float l = 0.f;
        for (int k = 0; k < 72; k++) {
            float e = __expf(Ps[q * 73 + k] - m);
            Ps[q * 73 + k] = e;
            l += e;
        }
        den[q] = 1.0f / l;
    }
    __syncthreads();

    int b = bh >> 3, h = bh & 7;
    for (int i = tid; i < 72 * 64; i += 128) {
        int q = i >> 6, d = i & 63;
        float acc = 0.f;
#pragma unroll 8
        for (int k = 0; k < 72; k++)
            acc += Ps[q * 73 + k] * Vs[k * 65 + d];
        float o = acc * den[q];
        size_t idx = (size_t)(b * SRTR + q) * DMODEL + h * 64 + d;
        __half hh, ll;
        split_h(o, hh, ll);
        Oh[idx] = hh;
        Ol[idx] = ll;
    }
}

__global__ void build_xr_k(const float* __restrict__ x, const float* __restrict__ rt,
                           float* __restrict__ xr) {
    int i = blockIdx.x * blockDim.x + threadIdx.x;
    if (i >= NTOK_RTR * DMODEL) return;
    int blk = i / (SRTR * DMODEL);
    int rem = i % (SRTR * DMODEL);
    int t = rem / DMODEL, dd = rem % DMODEL;
    xr[i] = (t < 64) ? x[(size_t)(blk * 64 + t) * DMODEL + dd]
                     : rt[(size_t)(t - 64) * DMODEL + dd];
}

__global__ void gather_rows_k(const float* __restrict__ xr, __half* __restrict__ rh,
                              __half* __restrict__ rl) {
    int i = blockIdx.x * blockDim.x + threadIdx.x;
    if (i >= 512 * DMODEL) return;
    int row = i / DMODEL, dd = i % DMODEL;
    int blk = row >> 3, r = row & 7;
    __half h, l;
    split_h(xr[((size_t)blk * SRTR + 64 + r) * DMODEL + dd], h, l);
    rh[i] = h;
    rl[i] = l;
}

__global__ void knorm_k(const float* __restrict__ kr, const float* __restrict__ kg,
                        float* __restrict__ knr, float* __restrict__ kng) {
    int tid = threadIdx.x;
    int which = tid >> 9;
    int idx = tid & 511;
    int g = idx >> 4, e = idx & 15;
    const float* src = which ? kg : kr;
    const float* col = src + (size_t)g * 128 * 16 + e;
    float s = 0.f;
    for (int d = 0; d < 128; d++) { float v = col[d * 16]; s += v * v; }
    float n = fmaxf(sqrtf(s), 1e-12f);
    if (which) kng[idx] = n; else knr[idx] = n;
}

__global__ void logits_k(const float* __restrict__ outp,
                         const float* __restrict__ keys_r, const float* __restrict__ keys_g,
                         const float* __restrict__ knr, const float* __restrict__ kng,
                         float* __restrict__ rl, float* __restrict__ gl) {
    __shared__ float vr[128], vg[128], red[128];
    int g = blockIdx.x >> 6, bb = blockIdx.x & 63;
    int b = bb >> 5, l = bb & 31;
    int srcl = (l + 31) & 31;
    int r = g >> 2;
    const float* row = outp + (size_t)((b * 32 + srcl) * 8 + r) * 256;
    int tid = threadIdx.x;
    vr[tid] = row[tid];
    vg[tid] = row[128 + tid];
    float nr2 = bsum128(vr[tid] * vr[tid], red);
    float ng2 = bsum128(vg[tid] * vg[tid], red);
    float inr = 1.0f / fmaxf(sqrtf(nr2), 1e-12f);
    float ing = 1.0f / fmaxf(sqrtf(ng2), 1e-12f);
    if (tid < 16) {
        int e = tid;
        const float* kr = keys_r + (size_t)g * 128 * 16 + e;
        const float* kg = keys_g + (size_t)g * 128 * 16 + e;
        float dr = 0.f, dg = 0.f;
        for (int dd = 0; dd < 128; dd++) {
            dr += vr[dd] * kr[dd * 16];
            dg += vg[dd] * kg[dd * 16];
        }
        rl[(size_t)(g * 64 + bb) * 16 + e] = dr * inr / knr[g * 16 + e];
        gl[(size_t)(g * 64 + bb) * 16 + e] = dg * ing / kng[g * 16 + e];
    }
}

__global__ void topk_k(const float* __restrict__ rl, const float* __restrict__ gl,
                       float* __restrict__ out) {
    int t = blockIdx.x * blockDim.x + threadIdx.x;
    if (t >= 2048) return;
    const float* r = rl + (size_t)t * 16;
    const float* g = gl + (size_t)t * 16;
    int i1 = 0; float v1 = r[0];
    for (int e = 1; e < 16; e++) if (r[e] > v1) { v1 = r[e]; i1 = e; }
    int i2 = -1; float v2 = -1e30f;
    for (int e = 0; e < 16; e++) {
        if (e == i1) continue;
        if (r[e] > v2) { v2 = r[e]; i2 = e; }
    }
    out[(size_t)t * 2 + 0] = v1;
    out[(size_t)t * 2 + 1] = v2;
    out[4096 + (size_t)t * 2 + 0] = g[i1];
    out[4096 + (size_t)t * 2 + 1] = g[i2];
}

// ---------------- host orchestration ----------------
static inline int pgrid(int tiles) { return tiles < NSM_SLOTS ? tiles : NSM_SLOTS; }

static void run_layer(float* cur, size_t qkvo, size_t oo, size_t upo, size_t dno,
                      const float* n1, const float* n2,
                      int ntok, int SEQ, int enc, const int* doc,
                      float* sb, __half* hb_) {
    float*  qkv  = sb + OFF_QKV;
    float*  hbuf = sb + OFF_H;
    __half* xnh = hb_ + HO_XNH; __half* xnl = hb_ + HO_XNL;
    __half* ath = hb_ + HO_ATTH; __half* atl = hb_ + HO_ATTL;
    __half* ach = hb_ + HO_ACTH; __half* acl = hb_ + HO_ACTL;
    __half* wh = hb_ + HO_WH;  __half* wl = hb_ + HO_WL;
    __half* qh_ = hb_ + HO_QH; __half* ql_ = hb_ + HO_QL;
    __half* kh_ = hb_ + HO_KH; __half* kl_ = hb_ + HO_KL;
    __half* vh_ = hb_ + HO_VH; __half* vl_ = hb_ + HO_VL;
    __half* vth_ = hb_ + HO_VTH; __half* vtl_ = hb_ + HO_VTL;
    int bh_total = (ntok / SEQ) * BH;
    int mt = ntok / 128;

    rmsnorm_k<<<ntok, 128>>>(cur, n1, xnh, xnl);
    sgemm_h3<<<pgrid(12 * mt), 256, GEMM_SMEM>>>(xnh, xnl, wh + qkvo, wl + qkvo, qkv,
                                                 nullptr, nullptr, ntok, 1536, 512, 0);
    split_rope_k<<<ntok, 128>>>(qkv, qh_, ql_, kh_, kl_, vh_, vl_, SEQ);
    if (enc) {
        vtrans_k<<<dim3(SEQ / 64, bh_total), 256>>>(vh_, vl_, vth_, vtl_, SEQ);
        attn_mma_k<<<dim3(SEQ / 64, bh_total), 128, AMMA_SMEM>>>(
            qh_, ql_, kh_, kl_, vth_, vtl_, ath, atl, doc, SEQ);
    } else {
        attn_r2<<<bh_total, 128, ATR_SMEM>>>(qh_, ql_, kh_, kl_, vh_, vl_, ath, atl);
    }
    sgemm_h3<<<pgrid(4 * mt), 256, GEMM_SMEM>>>(ath, atl, wh + oo, wl + oo, cur,
                                                nullptr, nullptr, ntok, 512, 512, 1);
    rmsnorm_k<<<ntok, 128>>>(cur, n2, xnh, xnl);
    sgemm_h3<<<pgrid(16 * mt), 256, GEMM_SMEM>>>(xnh, xnl, wh + upo, wl + upo, hbuf,
                                                 ach, acl, ntok, 2048, 512, 2);
    sgemm_h3<<<pgrid(4 * mt), 256, GEMM_SMEM>>>(ach, acl, wh + dno, wl + dno, cur,
                                                nullptr, nullptr, ntok, 512, 1024, 1);
}

extern "C" void kernel_launch(void* const* d_in, const int* in_sizes, int n_in,
                              void* d_out, int out_size) {
    const float* x_in   = (const float*)d_in[0];
    const int*   doc    = (const int*)d_in[1];
    const float* rt     = (const float*)d_in[2];
    const float* out_w  = (const float*)d_in[3];
    const float* keys_r = (const float*)d_in[4];
    const float* keys_g = (const float*)d_in[5];
    const float* e_qkv  = (const float*)d_in[6];
    const float* e_o    = (const float*)d_in[7];
    const float* e_up   = (const float*)d_in[8];
    const float* e_dn   = (const float*)d_in[9];
    const float* e_n1   = (const float*)d_in[10];
    const float* e_n2   = (const float*)d_in[11];
    const float* r_qkv  = (const float*)d_in[12];
    const float* r_o    = (const float*)d_in[13];
    const float* r_up   = (const float*)d_in[14];
    const float* r_dn   = (const float*)d_in[15];
    const float* r_n1   = (const float*)d_in[16];
    const float* r_n2   = (const float*)d_in[17];
    float* out = (float*)d_out;

    static int attr_set = 0;
    if (!attr_set) {
        cudaFuncSetAttribute(attn_mma_k, cudaFuncAttributeMaxDynamicSharedMemorySize, AMMA_SMEM);
        cudaFuncSetAttribute(sgemm_h3, cudaFuncAttributeMaxDynamicSharedMemorySize, GEMM_SMEM);
        cudaFuncSetAttribute(attn_r2, cudaFuncAttributeMaxDynamicSharedMemorySize, ATR_SMEM);
        attr_set = 1;
    }

    float* sb;
    cudaGetSymbolAddress((void**)&sb, g_s);
    __half* hb_;
    cudaGetSymbolAddress((void**)&hb_, g_h);

    float* xbuf = sb + OFF_X;
    float* xr   = sb + OFF_XR;
    float* outp = sb + OFF_OUT;
    float* knr  = sb + OFF_KNR;
    float* kng  = sb + OFF_KNG;
    float* rl   = sb + OFF_RL;
    float* gl   = sb + OFF_GL;
    __half* wh = hb_ + HO_WH;
    __half* wl = hb_ + HO_WL;
    __half* rowsh = hb_ + HO_ROWSH;
    __half* rowsl = hb_ + HO_ROWSL;

    // pre-split all weights (batched over layers via grid.z)
    wsplitT_k<<<dim3(1536 / 32, 512 / 32, 4), dim3(32, 8)>>>(e_qkv, wh + WO_EQ, wl + WO_EQ, 512, 1536, 0);
    wsplitT_k<<<dim3(512 / 32, 512 / 32, 4), dim3(32, 8)>>>(e_o, wh + WO_EO, wl + WO_EO, 512, 512, 0);
    wsplitT_k<<<dim3(2048 / 32, 512 / 32, 4), dim3(32, 8)>>>(e_up, wh + WO_EU, wl + WO_EU, 512, 2048, 1);
    wsplitT_k<<<dim3(512 / 32, 1024 / 32, 4), dim3(32, 8)>>>(e_dn, wh + WO_ED, wl + WO_ED, 1024, 512, 0);
    wsplitT_k<<<dim3(1536 / 32, 512 / 32, 2), dim3(32, 8)>>>(r_qkv, wh + WO_RQ, wl + WO_RQ, 512, 1536, 0);
    wsplitT_k<<<dim3(512 / 32, 512 / 32, 2), dim3(32, 8)>>>(r_o, wh + WO_RO, wl + WO_RO, 512, 512, 0);
    wsplitT_k<<<dim3(2048 / 32, 512 / 32, 2), dim3(32, 8)>>>(r_up, wh + WO_RU, wl + WO_RU, 512, 2048, 1);
    wsplitT_k<<<dim3(512 / 32, 1024 / 32, 2), dim3(32, 8)>>>(r_dn, wh + WO_RD, wl + WO_RD, 1024, 512, 0);
    wsplitT_k<<<dim3(256 / 32, 512 / 32, 1), dim3(32, 8)>>>(out_w, wh + WO_OUT, wl + WO_OUT, 512, 256, 0);

    copy_k<<<(NTOK_ENC * DMODEL + 255) / 256, 256>>>(x_in, xbuf, NTOK_ENC * DMODEL);

    for (int i = 0; i < 4; i++) {
        run_layer(xbuf,
                  WO_EQ + (size_t)i * 786432,
                  WO_EO + (size_t)i * 262144,
                  WO_EU + (size_t)i * 1048576,
                  WO_ED + (size_t)i * 524288,
                  e_n1 + (size_t)i * 512, e_n2 + (size_t)i * 512,
                  NTOK_ENC, SENC, 1, doc, sb, hb_);
    }

    build_xr_k<<<(NTOK_RTR * DMODEL + 255) / 256, 256>>>(xbuf, rt, xr);

    for (int i = 0; i < 2; i++) {
        run_layer(xr,
                  WO_RQ + (size_t)i * 786432,
                  WO_RO + (size_t)i * 262144,
                  WO_RU + (size_t)i * 1048576,
                  WO_RD + (size_t)i * 524288,
                  r_n1 + (size_t)i * 512, r_n2 + (size_t)i * 512,
                  NTOK_RTR, SRTR, 0, nullptr, sb, hb_);
    }

    gather_rows_k<<<(512 * DMODEL + 255) / 256, 256>>>(xr, rowsh, rowsl);
    sgemm_h3<<<pgrid(8), 256, GEMM_SMEM>>>(rowsh, rowsl, wh + WO_OUT, wl + WO_OUT, outp,
                                           nullptr, nullptr, 512, 256, 512, 0);

    knorm_k<<<1, 1024>>>(keys_r, keys_g, knr, kng);
    logits_k<<<32 * 64, 128>>>(outp, keys_r, keys_g, knr, kng, rl, gl);
    topk_k<<<16, 128>>>(rl, gl, out);
}